// round 3
// baseline (speedup 1.0000x reference)
#include <cuda_runtime.h>
#include <cstdint>

#define H        256
#define NS       6
#define G        32      // cells per block
#define NTHREADS 256

// ---------------- device scratch (allocations are forbidden) ----------------
__device__ float g_w2T[H * H];   // g_w2T[j*H + h] = w2[h*H + j]

// ---------------- w2 transpose ----------------
__global__ void k_transpose(const float* __restrict__ w2) {
    __shared__ float t[32][33];
    int j0 = blockIdx.x * 32, h0 = blockIdx.y * 32;
    int tx = threadIdx.x, ty = threadIdx.y;     // (32, 8)
    #pragma unroll
    for (int r = 0; r < 32; r += 8)
        t[ty + r][tx] = w2[(h0 + ty + r) * H + j0 + tx];
    __syncthreads();
    #pragma unroll
    for (int r = 0; r < 32; r += 8)
        g_w2T[(j0 + ty + r) * H + h0 + tx] = t[tx][ty + r];
}

// ---------------- fused kernel ----------------
struct Smem {
    float v1t[H][36];            // v1 transposed [j][c], stride 36 (16B-aligned float4 reads)
    float w3t[H][8];             // w3 transposed [h][i] (cols 6,7 zero), broadcast reads
    float xs[G][8];              // per-cell inputs
    unsigned m1w[G][8];          // m1 bits: word g, bit b <-> j = 32g + b
    unsigned char m2b[G][32];    // m2 bits: byte hb, bit r <-> h = 8*hb + r
};

__global__ void __launch_bounds__(NTHREADS, 2)
k_fused(const float* __restrict__ y,  const float* __restrict__ er,
        const float* __restrict__ Tg, const float* __restrict__ w1,
        const float* __restrict__ w2, const float* __restrict__ w3,
        const float* __restrict__ b1, const float* __restrict__ b2,
        const float* __restrict__ b3, float* __restrict__ out, int ncell)
{
    extern __shared__ char raw[];
    Smem* s = reinterpret_cast<Smem*>(raw);

    const int tid  = threadIdx.x;
    const int lane = tid & 31;
    const int wid  = tid >> 5;
    const int n0   = blockIdx.x * G;

    // ---------------- phase 0: stage ----------------
    float w1r[8];
    #pragma unroll
    for (int q = 0; q < 8; q++) w1r[q] = w1[tid * 8 + q];
    #pragma unroll
    for (int i = 0; i < NS; i++) s->w3t[tid][i] = w3[i * H + tid];
    s->w3t[tid][6] = 0.0f;
    s->w3t[tid][7] = 0.0f;
    {
        int c = tid >> 3, q = tid & 7, n = n0 + c;
        float xv = (q < 6) ? y[n * 6 + q] : (q == 6 ? er[n] : Tg[n]);
        s->xs[c][q] = xv;
    }
    __syncthreads();

    // ---------------- phase 1: z1 / v1 / m1 (thread = neuron j = tid) -------
    {
        float b1v = b1[tid];
        #pragma unroll 4
        for (int c = 0; c < G; c++) {
            float z = b1v;
            #pragma unroll
            for (int q = 0; q < 8; q++) z = fmaf(w1r[q], s->xs[c][q], z);
            s->v1t[tid][c] = fmaxf(z, 0.0f);
            unsigned bal = __ballot_sync(0xffffffffu, z > 0.0f);
            if (lane == 0) s->m1w[c][wid] = bal;
        }
    }
    __syncthreads();

    // ---------------- phase 2: z2 GEMM + ydot + m2 -------------------------
    // lane -> h0 = 8*lane (8 consecutive h), warp -> c0 = 4*wid (4 cells)
    {
        const int h0 = lane * 8, c0 = wid * 4;
        float acc[8][4];
        #pragma unroll
        for (int r = 0; r < 8; r++)
            #pragma unroll
            for (int cc = 0; cc < 4; cc++) acc[r][cc] = 0.0f;

        #pragma unroll 2
        for (int j = 0; j < H; j++) {
            float4 wa = *reinterpret_cast<const float4*>(&g_w2T[j * H + h0]);
            float4 wb = *reinterpret_cast<const float4*>(&g_w2T[j * H + h0 + 4]);
            float4 vv = *reinterpret_cast<const float4*>(&s->v1t[j][c0]);
            float wr[8] = {wa.x, wa.y, wa.z, wa.w, wb.x, wb.y, wb.z, wb.w};
            float vr[4] = {vv.x, vv.y, vv.z, vv.w};
            #pragma unroll
            for (int r = 0; r < 8; r++)
                #pragma unroll
                for (int cc = 0; cc < 4; cc++)
                    acc[r][cc] = fmaf(wr[r], vr[cc], acc[r][cc]);
        }

        unsigned mbyte[4] = {0u, 0u, 0u, 0u};
        float yp[NS][4];
        #pragma unroll
        for (int i = 0; i < NS; i++)
            #pragma unroll
            for (int cc = 0; cc < 4; cc++) yp[i][cc] = 0.0f;

        #pragma unroll
        for (int r = 0; r < 8; r++) {
            float b2v = b2[h0 + r];
            float w3v[NS];
            #pragma unroll
            for (int i = 0; i < NS; i++) w3v[i] = w3[i * H + h0 + r];
            #pragma unroll
            for (int cc = 0; cc < 4; cc++) {
                float z2 = acc[r][cc] + b2v;
                float v2 = fmaxf(z2, 0.0f);
                if (z2 > 0.0f) mbyte[cc] |= (1u << r);
                #pragma unroll
                for (int i = 0; i < NS; i++)
                    yp[i][cc] = fmaf(w3v[i], v2, yp[i][cc]);
            }
        }
        #pragma unroll
        for (int cc = 0; cc < 4; cc++)
            s->m2b[c0 + cc][lane] = (unsigned char)mbyte[cc];

        // warp-reduce ydot partials (sum over all h)
        #pragma unroll
        for (int i = 0; i < NS; i++)
            #pragma unroll
            for (int cc = 0; cc < 4; cc++) {
                float v = yp[i][cc];
                #pragma unroll
                for (int o = 16; o > 0; o >>= 1)
                    v += __shfl_xor_sync(0xffffffffu, v, o);
                yp[i][cc] = v;
            }
        if (lane == 0) {
            #pragma unroll
            for (int i = 0; i < NS; i++) {
                float b3v = b3[i];
                #pragma unroll
                for (int cc = 0; cc < 4; cc++)
                    out[(size_t)(n0 + c0 + cc) * NS + i] = yp[i][cc] + b3v;
            }
        }
    }
    __syncthreads();

    // ---------------- phase 3: Jacobian (warp per cell, 4 cells/warp) ------
    {
        const size_t N = (size_t)ncell;
        float* outDY = out + 6 * N;    // [n][i][q<6]
        float* outDE = out + 42 * N;   // [n][i]
        float* outDT = out + 48 * N;   // [n][i]

        for (int cc = 0; cc < 4; cc++) {
            const int c = wid * 4 + cc;
            const int n = n0 + c;

            unsigned m2w[8];
            #pragma unroll
            for (int g = 0; g < 8; g++)
                m2w[g] = *reinterpret_cast<const unsigned*>(&s->m2b[c][4 * g]);

            // lane owns j = 8*lane + jj, jj in [0,8)
            float B[NS][8];
            #pragma unroll
            for (int i = 0; i < NS; i++)
                #pragma unroll
                for (int jj = 0; jj < 8; jj++) B[i][jj] = 0.0f;

            // warp-uniform sparse loop over active h
            #pragma unroll 1
            for (int g = 0; g < 8; g++) {
                unsigned w = m2w[g];
                while (w) {
                    int b = __ffs(w) - 1;
                    w &= w - 1;
                    int h = 32 * g + b;
                    float4 w3a = *reinterpret_cast<const float4*>(&s->w3t[h][0]);
                    float2 w3b = *reinterpret_cast<const float2*>(&s->w3t[h][4]);
                    float w3v[NS] = {w3a.x, w3a.y, w3a.z, w3a.w, w3b.x, w3b.y};
                    const float* row = w2 + h * H + lane * 8;
                    float4 ra = *reinterpret_cast<const float4*>(row);
                    float4 rb = *reinterpret_cast<const float4*>(row + 4);
                    float rv[8] = {ra.x, ra.y, ra.z, ra.w, rb.x, rb.y, rb.z, rb.w};
                    #pragma unroll
                    for (int i = 0; i < NS; i++)
                        #pragma unroll
                        for (int jj = 0; jj < 8; jj++)
                            B[i][jj] = fmaf(w3v[i], rv[jj], B[i][jj]);
                }
            }

            // fold m1 mask into B
            {
                unsigned mb = (s->m1w[c][lane >> 2] >> (8 * (lane & 3))) & 0xffu;
                #pragma unroll
                for (int jj = 0; jj < 8; jj++) {
                    float m = ((mb >> jj) & 1u) ? 1.0f : 0.0f;
                    #pragma unroll
                    for (int i = 0; i < NS; i++) B[i][jj] *= m;
                }
            }

            // epilogue per output-row i: J[i][q] = sum_j B[i][j] * w1[j][q]
            #pragma unroll 1
            for (int i = 0; i < NS; i++) {
                float Jq[8];
                #pragma unroll
                for (int q = 0; q < 8; q++) Jq[q] = 0.0f;
                #pragma unroll
                for (int jj = 0; jj < 8; jj++) {
                    const float* w1row = w1 + (size_t)(8 * lane + jj) * 8;
                    float4 wa = *reinterpret_cast<const float4*>(w1row);
                    float4 wb = *reinterpret_cast<const float4*>(w1row + 4);
                    float wv[8] = {wa.x, wa.y, wa.z, wa.w, wb.x, wb.y, wb.z, wb.w};
                    float bv = B[i][jj];
                    #pragma unroll
                    for (int q = 0; q < 8; q++)
                        Jq[q] = fmaf(bv, wv[q], Jq[q]);
                }
                #pragma unroll
                for (int q = 0; q < 8; q++) {
                    float v = Jq[q];
                    #pragma unroll
                    for (int o = 16; o > 0; o >>= 1)
                        v += __shfl_xor_sync(0xffffffffu, v, o);
                    Jq[q] = v;
                }
                if (lane == 0) {
                    #pragma unroll
                    for (int q = 0; q < 6; q++)
                        outDY[(size_t)n * 36 + i * 6 + q] = Jq[q];
                    outDE[(size_t)n * 6 + i] = Jq[6];
                    outDT[(size_t)n * 6 + i] = Jq[7];
                }
            }
        }
    }
}

extern "C" void kernel_launch(void* const* d_in, const int* in_sizes, int n_in,
                              void* d_out, int out_size) {
    // metadata order: t, y, erate, T, w1, w2, w3, b1, b2, b3
    const float* y  = (const float*)d_in[1];
    const float* er = (const float*)d_in[2];
    const float* Tg = (const float*)d_in[3];
    const float* w1 = (const float*)d_in[4];
    const float* w2 = (const float*)d_in[5];
    const float* w3 = (const float*)d_in[6];
    const float* b1 = (const float*)d_in[7];
    const float* b2 = (const float*)d_in[8];
    const float* b3 = (const float*)d_in[9];
    float* out = (float*)d_out;
    int ncell = in_sizes[2];             // NT*NB = 65536

    cudaFuncSetAttribute(k_fused, cudaFuncAttributeMaxDynamicSharedMemorySize,
                         (int)sizeof(Smem));

    dim3 tposeGrid(H / 32, H / 32);
    dim3 tposeBlock(32, 8);
    k_transpose<<<tposeGrid, tposeBlock>>>(w2);

    int nblocks = ncell / G;
    k_fused<<<nblocks, NTHREADS, sizeof(Smem)>>>(y, er, Tg, w1, w2, w3,
                                                 b1, b2, b3, out, ncell);
}

// round 4
// speedup vs baseline: 1.0507x; 1.0507x over previous
#include <cuda_runtime.h>
#include <cstdint>

#define H        256
#define NS       6
#define G        32      // cells per block
#define NTHREADS 256

typedef unsigned long long u64;

// ---------------- device scratch (allocations are forbidden) ----------------
__device__ float g_w2T[H * H];   // g_w2T[j*H + h] = w2[h*H + j]

// ---------------- w2 transpose ----------------
__global__ void k_transpose(const float* __restrict__ w2) {
    __shared__ float t[32][33];
    int j0 = blockIdx.x * 32, h0 = blockIdx.y * 32;
    int tx = threadIdx.x, ty = threadIdx.y;     // (32, 8)
    #pragma unroll
    for (int r = 0; r < 32; r += 8)
        t[ty + r][tx] = w2[(h0 + ty + r) * H + j0 + tx];
    __syncthreads();
    #pragma unroll
    for (int r = 0; r < 32; r += 8)
        g_w2T[(j0 + ty + r) * H + h0 + tx] = t[tx][ty + r];
}

// ---------------- f32x2 helpers ----------------
__device__ __forceinline__ u64 pk2(float lo, float hi) {
    u64 r; asm("mov.b64 %0, {%1, %2};" : "=l"(r) : "f"(lo), "f"(hi)); return r;
}
__device__ __forceinline__ void upk2(u64 v, float& lo, float& hi) {
    asm("mov.b64 {%0, %1}, %2;" : "=f"(lo), "=f"(hi) : "l"(v));
}
__device__ __forceinline__ void fma2(u64& d, u64 a, u64 b) {
    asm("fma.rn.f32x2 %0, %1, %2, %0;" : "+l"(d) : "l"(a), "l"(b));
}
// pack 8 nibbles (at bits 0,8,...,56 of x) into 32 bits
__device__ __forceinline__ unsigned pack8(u64 x) {
    x |= x >> 4;  x &= 0x00FF00FF00FF00FFull;
    x |= x >> 8;  x &= 0x0000FFFF0000FFFFull;
    x |= x >> 16;
    return (unsigned)x;
}

// ---------------- shared layout ----------------
struct Smem {
    float    v1t[H][36];     // v1 transposed [j][c], stride 36 (16B-aligned float4)
    float    w3t[H][8];      // w3 transposed [h][i] (cols 6,7 zero)
    u64      w3d[H][6];      // pre-splatted w3 pairs (w3[i][h], w3[i][h])
    float    xs[G][8];       // per-cell inputs
    unsigned m1w[G][8];      // m1 bits: word g, bit b <-> j = 32g + b
    u64      m2c[G][4];      // m2 nibble bytes: byte l: low nib = h 4l..4l+3, high nib = 128+4l..
};

__global__ void __launch_bounds__(NTHREADS, 2)
k_fused(const float* __restrict__ y,  const float* __restrict__ er,
        const float* __restrict__ Tg, const float* __restrict__ w1,
        const float* __restrict__ w2, const float* __restrict__ w3,
        const float* __restrict__ b1, const float* __restrict__ b2,
        const float* __restrict__ b3, float* __restrict__ out, int ncell)
{
    extern __shared__ char raw[];
    Smem* s = reinterpret_cast<Smem*>(raw);

    const int tid  = threadIdx.x;
    const int lane = tid & 31;
    const int wid  = tid >> 5;
    const int n0   = blockIdx.x * G;

    // ---------------- phase 0: stage ----------------
    float w1r[8];
    #pragma unroll
    for (int q = 0; q < 8; q++) w1r[q] = w1[tid * 8 + q];
    #pragma unroll
    for (int i = 0; i < NS; i++) {
        float v = w3[i * H + tid];
        s->w3t[tid][i] = v;
        s->w3d[tid][i] = pk2(v, v);
    }
    s->w3t[tid][6] = 0.0f;
    s->w3t[tid][7] = 0.0f;
    {
        int c = tid >> 3, q = tid & 7, n = n0 + c;
        float xv = (q < 6) ? y[n * 6 + q] : (q == 6 ? er[n] : Tg[n]);
        s->xs[c][q] = xv;
    }
    __syncthreads();

    // ---------------- phase 1: z1 / v1 / m1 (thread = neuron j = tid) -------
    {
        float b1v = b1[tid];
        #pragma unroll 4
        for (int c = 0; c < G; c++) {
            float z = b1v;
            #pragma unroll
            for (int q = 0; q < 8; q++) z = fmaf(w1r[q], s->xs[c][q], z);
            s->v1t[tid][c] = fmaxf(z, 0.0f);
            unsigned bal = __ballot_sync(0xffffffffu, z > 0.0f);
            if (lane == 0) s->m1w[c][wid] = bal;
        }
    }
    __syncthreads();

    // ---------------- phase 2: z2 GEMM + ydot + m2 -------------------------
    // lane owns h in {4l..4l+3} u {128+4l..128+4l+3}; warp owns cells c0..c0+3
    const int c0 = wid * 4;
    {
        u64 acc2[4][4];        // [h-pair r2][cell cc]; r2<2: lo block, r2>=2: hi
        #pragma unroll
        for (int r2 = 0; r2 < 4; r2++)
            #pragma unroll
            for (int cc = 0; cc < 4; cc++) acc2[r2][cc] = 0ull;

        #pragma unroll 2
        for (int j = 0; j < H; j++) {
            const float* wrow = g_w2T + j * H + 4 * lane;
            ulonglong2 wa = *reinterpret_cast<const ulonglong2*>(wrow);        // h pairs (4l,4l+1),(4l+2,4l+3)
            ulonglong2 wb = *reinterpret_cast<const ulonglong2*>(wrow + 128);  // hi block pairs
            u64 wv[4] = {wa.x, wa.y, wb.x, wb.y};
            float4 vv = *reinterpret_cast<const float4*>(&s->v1t[j][c0]);
            u64 vs[4] = {pk2(vv.x, vv.x), pk2(vv.y, vv.y),
                         pk2(vv.z, vv.z), pk2(vv.w, vv.w)};
            #pragma unroll
            for (int r2 = 0; r2 < 4; r2++)
                #pragma unroll
                for (int cc = 0; cc < 4; cc++)
                    fma2(acc2[r2][cc], wv[r2], vs[cc]);
        }

        // bias + relu + m2 nibble bytes + ydot partials
        float4 b2lo = *reinterpret_cast<const float4*>(b2 + 4 * lane);
        float4 b2hi = *reinterpret_cast<const float4*>(b2 + 128 + 4 * lane);
        float b2a[8] = {b2lo.x, b2lo.y, b2lo.z, b2lo.w,
                        b2hi.x, b2hi.y, b2hi.z, b2hi.w};
        unsigned mbyte[4] = {0u, 0u, 0u, 0u};
        float yp[NS][4];
        #pragma unroll
        for (int i = 0; i < NS; i++)
            #pragma unroll
            for (int cc = 0; cc < 4; cc++) yp[i][cc] = 0.0f;

        #pragma unroll
        for (int r = 0; r < 8; r++) {
            int h = (r < 4) ? (4 * lane + r) : (128 + 4 * lane + (r - 4));
            float w3v[NS];
            #pragma unroll
            for (int i = 0; i < NS; i++) w3v[i] = s->w3t[h][i];
            int r2 = r >> 1;
            int odd = r & 1;
            #pragma unroll
            for (int cc = 0; cc < 4; cc++) {
                float lo, hi; upk2(acc2[r2][cc], lo, hi);
                float z = (odd ? hi : lo) + b2a[r];
                float v2 = fmaxf(z, 0.0f);
                if (z > 0.0f) mbyte[cc] |= (1u << r);
                #pragma unroll
                for (int i = 0; i < NS; i++)
                    yp[i][cc] = fmaf(w3v[i], v2, yp[i][cc]);
            }
        }
        #pragma unroll
        for (int cc = 0; cc < 4; cc++)
            reinterpret_cast<unsigned char*>(&s->m2c[c0 + cc][0])[lane] =
                (unsigned char)mbyte[cc];
        __syncwarp();

        // warp-reduce ydot
        #pragma unroll
        for (int i = 0; i < NS; i++)
            #pragma unroll
            for (int cc = 0; cc < 4; cc++) {
                float v = yp[i][cc];
                #pragma unroll
                for (int o = 16; o > 0; o >>= 1)
                    v += __shfl_xor_sync(0xffffffffu, v, o);
                yp[i][cc] = v;
            }
        if (lane == 0) {
            #pragma unroll
            for (int i = 0; i < NS; i++) {
                float b3v = b3[i];
                #pragma unroll
                for (int cc = 0; cc < 4; cc++)
                    out[(size_t)(n0 + c0 + cc) * NS + i] = yp[i][cc] + b3v;
            }
        }
    }
    // no block sync needed: phase 3 consumes only this warp's cells

    // ---------------- phase 3: Jacobian (warp per cell, 4 cells/warp) ------
    {
        const size_t N = (size_t)ncell;
        float* outDY = out + 6 * N;    // [n][i][q<6]
        float* outDE = out + 42 * N;   // [n][i]
        float* outDT = out + 48 * N;   // [n][i]

        for (int cc = 0; cc < 4; cc++) {
            const int c = c0 + cc;
            const int n = n0 + c;

            // assemble m2 words: h = 32g + b
            unsigned m2w[8];
            #pragma unroll
            for (int d = 0; d < 4; d++) {
                u64 ch = s->m2c[c][d];
                m2w[d]     = pack8(ch        & 0x0F0F0F0F0F0F0F0Full);
                m2w[4 + d] = pack8((ch >> 4) & 0x0F0F0F0F0F0F0F0Full);
            }

            // lane owns j in {4l..4l+3} u {128+4l..128+4l+3}, packed in pairs
            u64 B2[NS][4];
            #pragma unroll
            for (int i = 0; i < NS; i++)
                #pragma unroll
                for (int p = 0; p < 4; p++) B2[i][p] = 0ull;

            // warp-uniform sparse loop over active h
            #pragma unroll 1
            for (int g = 0; g < 8; g++) {
                unsigned w = m2w[g];
                while (w) {
                    int b = __ffs(w) - 1;
                    w &= w - 1;
                    int h = 32 * g + b;
                    const u64* wp3 = s->w3d[h];
                    ulonglong2 p0 = *reinterpret_cast<const ulonglong2*>(wp3);
                    ulonglong2 p1 = *reinterpret_cast<const ulonglong2*>(wp3 + 2);
                    ulonglong2 p2 = *reinterpret_cast<const ulonglong2*>(wp3 + 4);
                    u64 a[NS] = {p0.x, p0.y, p1.x, p1.y, p2.x, p2.y};
                    const float* row = w2 + h * H + 4 * lane;
                    ulonglong2 ra = *reinterpret_cast<const ulonglong2*>(row);
                    ulonglong2 rb = *reinterpret_cast<const ulonglong2*>(row + 128);
                    u64 rv[4] = {ra.x, ra.y, rb.x, rb.y};
                    #pragma unroll
                    for (int i = 0; i < NS; i++)
                        #pragma unroll
                        for (int p = 0; p < 4; p++)
                            fma2(B2[i][p], a[i], rv[p]);
                }
            }

            // unpack + fold m1 mask
            unsigned nlo = (s->m1w[c][lane >> 3]     >> (4 * (lane & 7))) & 0xFu;
            unsigned nhi = (s->m1w[c][4 + (lane >> 3)] >> (4 * (lane & 7))) & 0xFu;
            float ml[8];
            #pragma unroll
            for (int jj = 0; jj < 4; jj++) {
                ml[jj]     = ((nlo >> jj) & 1u) ? 1.0f : 0.0f;
                ml[4 + jj] = ((nhi >> jj) & 1u) ? 1.0f : 0.0f;
            }
            float Bm[NS][8];
            #pragma unroll
            for (int i = 0; i < NS; i++) {
                upk2(B2[i][0], Bm[i][0], Bm[i][1]);
                upk2(B2[i][1], Bm[i][2], Bm[i][3]);
                upk2(B2[i][2], Bm[i][4], Bm[i][5]);
                upk2(B2[i][3], Bm[i][6], Bm[i][7]);
                #pragma unroll
                for (int jj = 0; jj < 8; jj++) Bm[i][jj] *= ml[jj];
            }

            // epilogue: J[i][q] = sum_j Bm[i][j] * w1[j][q], f32x2 over q pairs
            #pragma unroll 1
            for (int half = 0; half < 2; half++) {
                u64 Jq2[3][4];
                #pragma unroll
                for (int i3 = 0; i3 < 3; i3++)
                    #pragma unroll
                    for (int q2 = 0; q2 < 4; q2++) Jq2[i3][q2] = 0ull;

                #pragma unroll
                for (int jj = 0; jj < 8; jj++) {
                    int j = (jj < 4) ? (4 * lane + jj) : (128 + 4 * lane + (jj - 4));
                    const float* w1p = w1 + (size_t)j * 8;
                    ulonglong2 ra = *reinterpret_cast<const ulonglong2*>(w1p);
                    ulonglong2 rb = *reinterpret_cast<const ulonglong2*>(w1p + 4);
                    u64 wp[4] = {ra.x, ra.y, rb.x, rb.y};
                    #pragma unroll
                    for (int i3 = 0; i3 < 3; i3++) {
                        float bv = Bm[half * 3 + i3][jj];
                        u64 bv2 = pk2(bv, bv);
                        #pragma unroll
                        for (int q2 = 0; q2 < 4; q2++)
                            fma2(Jq2[i3][q2], bv2, wp[q2]);
                    }
                }

                #pragma unroll
                for (int i3 = 0; i3 < 3; i3++) {
                    int i = half * 3 + i3;
                    float Jq[8];
                    upk2(Jq2[i3][0], Jq[0], Jq[1]);
                    upk2(Jq2[i3][1], Jq[2], Jq[3]);
                    upk2(Jq2[i3][2], Jq[4], Jq[5]);
                    upk2(Jq2[i3][3], Jq[6], Jq[7]);
                    #pragma unroll
                    for (int q = 0; q < 8; q++) {
                        float v = Jq[q];
                        #pragma unroll
                        for (int o = 16; o > 0; o >>= 1)
                            v += __shfl_xor_sync(0xffffffffu, v, o);
                        Jq[q] = v;
                    }
                    if (lane == 0) {
                        #pragma unroll
                        for (int q = 0; q < 6; q++)
                            outDY[(size_t)n * 36 + i * 6 + q] = Jq[q];
                        outDE[(size_t)n * 6 + i] = Jq[6];
                        outDT[(size_t)n * 6 + i] = Jq[7];
                    }
                }
            }
        }
    }
}

extern "C" void kernel_launch(void* const* d_in, const int* in_sizes, int n_in,
                              void* d_out, int out_size) {
    // metadata order: t, y, erate, T, w1, w2, w3, b1, b2, b3
    const float* y  = (const float*)d_in[1];
    const float* er = (const float*)d_in[2];
    const float* Tg = (const float*)d_in[3];
    const float* w1 = (const float*)d_in[4];
    const float* w2 = (const float*)d_in[5];
    const float* w3 = (const float*)d_in[6];
    const float* b1 = (const float*)d_in[7];
    const float* b2 = (const float*)d_in[8];
    const float* b3 = (const float*)d_in[9];
    float* out = (float*)d_out;
    int ncell = in_sizes[2];             // NT*NB = 65536

    cudaFuncSetAttribute(k_fused, cudaFuncAttributeMaxDynamicSharedMemorySize,
                         (int)sizeof(Smem));

    dim3 tposeGrid(H / 32, H / 32);
    dim3 tposeBlock(32, 8);
    k_transpose<<<tposeGrid, tposeBlock>>>(w2);

    int nblocks = ncell / G;
    k_fused<<<nblocks, NTHREADS, sizeof(Smem)>>>(y, er, Tg, w1, w2, w3,
                                                 b1, b2, b3, out, ncell);
}

// round 5
// speedup vs baseline: 1.0876x; 1.0351x over previous
#include <cuda_runtime.h>
#include <cstdint>

#define H        256
#define NS       6
#define G        32      // cells per block
#define NTHREADS 256

typedef unsigned long long u64;

// ---------------- device scratch (allocations are forbidden) ----------------
__device__ float g_w2T[H * H];   // g_w2T[j*H + h] = w2[h*H + j]

// ---------------- w2 transpose ----------------
__global__ void k_transpose(const float* __restrict__ w2) {
    __shared__ float t[32][33];
    int j0 = blockIdx.x * 32, h0 = blockIdx.y * 32;
    int tx = threadIdx.x, ty = threadIdx.y;     // (32, 8)
    #pragma unroll
    for (int r = 0; r < 32; r += 8)
        t[ty + r][tx] = w2[(h0 + ty + r) * H + j0 + tx];
    __syncthreads();
    #pragma unroll
    for (int r = 0; r < 32; r += 8)
        g_w2T[(j0 + ty + r) * H + h0 + tx] = t[tx][ty + r];
}

// ---------------- f32x2 helpers ----------------
__device__ __forceinline__ u64 pk2(float lo, float hi) {
    u64 r; asm("mov.b64 %0, {%1, %2};" : "=l"(r) : "f"(lo), "f"(hi)); return r;
}
__device__ __forceinline__ void upk2(u64 v, float& lo, float& hi) {
    asm("mov.b64 {%0, %1}, %2;" : "=f"(lo), "=f"(hi) : "l"(v));
}
__device__ __forceinline__ void fma2(u64& d, u64 a, u64 b) {
    asm("fma.rn.f32x2 %0, %1, %2, %0;" : "+l"(d) : "l"(a), "l"(b));
}
// pack 8 nibbles (at bits 0,8,...,56 of x) into 32 bits
__device__ __forceinline__ unsigned pack8(u64 x) {
    x |= x >> 4;  x &= 0x00FF00FF00FF00FFull;
    x |= x >> 8;  x &= 0x0000FFFF0000FFFFull;
    x |= x >> 16;
    return (unsigned)x;
}

// ---------------- shared layout ----------------
struct Smem {
    union {
        float v1t[H][36];            // phase 1/2: v1 transposed [j][c]
        struct {                      // phase 3 (v1t dead):
            u64           w1p[4][H];  //   w1 pairs: w1p[q2][j] = (w1[j][2q2], w1[j][2q2+1])
            unsigned char lst[G][H];  //   per-cell active-h list
        } p3;
    } u;
    u64      w3d[H][6];      // pre-splatted w3 pairs (w3[i][h], w3[i][h])
    float4   w3f4[NS][64];   // w3f4[i][l] = w3[i][4l..4l+3]
    float    xs[G][8];       // per-cell inputs
    unsigned m1w[G][8];      // m1 bits: word g, bit b <-> j = 32g + b
    u64      m2c[G][4];      // m2 nibbles: byte l: low nib = h 4l..4l+3, high nib = 128+4l..
};

__global__ void __launch_bounds__(NTHREADS, 2)
k_fused(const float* __restrict__ y,  const float* __restrict__ er,
        const float* __restrict__ Tg, const float* __restrict__ w1,
        const float* __restrict__ w2, const float* __restrict__ w3,
        const float* __restrict__ b1, const float* __restrict__ b2,
        const float* __restrict__ b3, float* __restrict__ out, int ncell)
{
    extern __shared__ char raw[];
    Smem* s = reinterpret_cast<Smem*>(raw);

    const int tid  = threadIdx.x;
    const int lane = tid & 31;
    const int wid  = tid >> 5;
    const int n0   = blockIdx.x * G;

    // ---------------- phase 0: stage ----------------
    float w1r[8];
    #pragma unroll
    for (int q = 0; q < 8; q++) w1r[q] = w1[tid * 8 + q];
    #pragma unroll
    for (int i = 0; i < NS; i++) {
        float v = w3[i * H + tid];
        s->w3d[tid][i] = pk2(v, v);
    }
    #pragma unroll
    for (int idx = tid; idx < NS * 64; idx += NTHREADS) {
        int i = idx >> 6, l = idx & 63;
        s->w3f4[i][l] = *reinterpret_cast<const float4*>(&w3[i * H + 4 * l]);
    }
    {
        int c = tid >> 3, q = tid & 7, n = n0 + c;
        float xv = (q < 6) ? y[n * 6 + q] : (q == 6 ? er[n] : Tg[n]);
        s->xs[c][q] = xv;
    }
    __syncthreads();

    // ---------------- phase 1: z1 / v1 / m1 (thread = neuron j = tid) -------
    {
        float b1v = b1[tid];
        #pragma unroll 4
        for (int c = 0; c < G; c++) {
            float z = b1v;
            #pragma unroll
            for (int q = 0; q < 8; q++) z = fmaf(w1r[q], s->xs[c][q], z);
            s->u.v1t[tid][c] = fmaxf(z, 0.0f);
            unsigned bal = __ballot_sync(0xffffffffu, z > 0.0f);
            if (lane == 0) s->m1w[c][wid] = bal;
        }
    }
    __syncthreads();

    // ---------------- phase 2: z2 GEMM + ydot + m2 -------------------------
    // lane owns h in {4l..4l+3} u {128+4l..128+4l+3}; warp owns cells c0..c0+3
    const int c0 = wid * 4;
    {
        u64 acc2[4][4];        // [h-pair r2][cell cc]
        #pragma unroll
        for (int r2 = 0; r2 < 4; r2++)
            #pragma unroll
            for (int cc = 0; cc < 4; cc++) acc2[r2][cc] = 0ull;

        #pragma unroll 2
        for (int j = 0; j < H; j++) {
            const float* wrow = g_w2T + j * H + 4 * lane;
            ulonglong2 wa = *reinterpret_cast<const ulonglong2*>(wrow);
            ulonglong2 wb = *reinterpret_cast<const ulonglong2*>(wrow + 128);
            u64 wv[4] = {wa.x, wa.y, wb.x, wb.y};
            float4 vv = *reinterpret_cast<const float4*>(&s->u.v1t[j][c0]);
            u64 vs[4] = {pk2(vv.x, vv.x), pk2(vv.y, vv.y),
                         pk2(vv.z, vv.z), pk2(vv.w, vv.w)};
            #pragma unroll
            for (int r2 = 0; r2 < 4; r2++)
                #pragma unroll
                for (int cc = 0; cc < 4; cc++)
                    fma2(acc2[r2][cc], wv[r2], vs[cc]);
        }

        // bias + relu + m2 nibble bytes
        float4 b2lo = *reinterpret_cast<const float4*>(b2 + 4 * lane);
        float4 b2hi = *reinterpret_cast<const float4*>(b2 + 128 + 4 * lane);
        float b2a[8] = {b2lo.x, b2lo.y, b2lo.z, b2lo.w,
                        b2hi.x, b2hi.y, b2hi.z, b2hi.w};
        unsigned mbyte[4] = {0u, 0u, 0u, 0u};
        float v2r[8][4];
        #pragma unroll
        for (int r2 = 0; r2 < 4; r2++)
            #pragma unroll
            for (int cc = 0; cc < 4; cc++) {
                float lo, hi; upk2(acc2[r2][cc], lo, hi);
                float z0 = lo + b2a[2 * r2];
                float z1 = hi + b2a[2 * r2 + 1];
                v2r[2 * r2][cc]     = fmaxf(z0, 0.0f);
                v2r[2 * r2 + 1][cc] = fmaxf(z1, 0.0f);
                if (z0 > 0.0f) mbyte[cc] |= (1u << (2 * r2));
                if (z1 > 0.0f) mbyte[cc] |= (1u << (2 * r2 + 1));
            }
        #pragma unroll
        for (int cc = 0; cc < 4; cc++)
            reinterpret_cast<unsigned char*>(&s->m2c[c0 + cc][0])[lane] =
                (unsigned char)mbyte[cc];

        // ydot partials: conflict-free float4 reads of w3
        float yp[NS][4];
        #pragma unroll
        for (int i = 0; i < NS; i++) {
            float4 wa = s->w3f4[i][lane];        // r = 0..3 (h = 4*lane + r)
            float4 wb = s->w3f4[i][32 + lane];   // r = 4..7 (h = 128 + 4*lane + r)
            float w3r[8] = {wa.x, wa.y, wa.z, wa.w, wb.x, wb.y, wb.z, wb.w};
            float acc0 = 0.f, acc1 = 0.f, acc2f = 0.f, acc3 = 0.f;
            #pragma unroll
            for (int r = 0; r < 8; r++) {
                acc0 = fmaf(w3r[r], v2r[r][0], acc0);
                acc1 = fmaf(w3r[r], v2r[r][1], acc1);
                acc2f = fmaf(w3r[r], v2r[r][2], acc2f);
                acc3 = fmaf(w3r[r], v2r[r][3], acc3);
            }
            yp[i][0] = acc0; yp[i][1] = acc1; yp[i][2] = acc2f; yp[i][3] = acc3;
        }

        #pragma unroll
        for (int i = 0; i < NS; i++)
            #pragma unroll
            for (int cc = 0; cc < 4; cc++) {
                float v = yp[i][cc];
                #pragma unroll
                for (int o = 16; o > 0; o >>= 1)
                    v += __shfl_xor_sync(0xffffffffu, v, o);
                yp[i][cc] = v;
            }
        if (lane == 0) {
            #pragma unroll
            for (int i = 0; i < NS; i++) {
                float b3v = b3[i];
                #pragma unroll
                for (int cc = 0; cc < 4; cc++)
                    out[(size_t)(n0 + c0 + cc) * NS + i] = yp[i][cc] + b3v;
            }
        }
    }
    __syncthreads();     // v1t region is about to be repurposed

    // ---------------- build w1 pair table in union space -------------------
    {
        const float* wr = w1 + tid * 8;
        float4 a = *reinterpret_cast<const float4*>(wr);
        float4 b = *reinterpret_cast<const float4*>(wr + 4);
        s->u.p3.w1p[0][tid] = pk2(a.x, a.y);
        s->u.p3.w1p[1][tid] = pk2(a.z, a.w);
        s->u.p3.w1p[2][tid] = pk2(b.x, b.y);
        s->u.p3.w1p[3][tid] = pk2(b.z, b.w);
    }
    __syncthreads();

    // ---------------- phase 3: Jacobian (warp per cell, 4 cells/warp) ------
    {
        const size_t N = (size_t)ncell;
        float* outDY = out + 6 * N;    // [n][i][q<6]
        float* outDE = out + 42 * N;   // [n][i]
        float* outDT = out + 48 * N;   // [n][i]

        for (int cc = 0; cc < 4; cc++) {
            const int c = c0 + cc;
            const int n = n0 + c;

            // assemble m2 words: h = 32g + b
            unsigned m2w[8];
            #pragma unroll
            for (int d = 0; d < 4; d++) {
                u64 ch = s->m2c[c][d];
                m2w[d]     = pack8(ch        & 0x0F0F0F0F0F0F0F0Full);
                m2w[4 + d] = pack8((ch >> 4) & 0x0F0F0F0F0F0F0F0Full);
            }

            // warp-parallel compaction of active h into a per-cell list
            unsigned char* lc = s->u.p3.lst[c];
            int cnt = 0;
            #pragma unroll
            for (int g = 0; g < 8; g++) {
                unsigned w = m2w[g];
                if ((w >> lane) & 1u)
                    lc[cnt + __popc(w & ((1u << lane) - 1u))] =
                        (unsigned char)(32 * g + lane);
                cnt += __popc(w);
            }
            __syncwarp();

            // lane owns j in {4l..4l+3} u {128+4l..128+4l+3}, packed in pairs
            u64 B2[NS][4];
            #pragma unroll
            for (int i = 0; i < NS; i++)
                #pragma unroll
                for (int p = 0; p < 4; p++) B2[i][p] = 0ull;

            if (cnt > 0) {
                // prefetch iteration 0
                int hcur = lc[0];
                const float* r0 = w2 + hcur * H + 4 * lane;
                ulonglong2 ca = *reinterpret_cast<const ulonglong2*>(r0);
                ulonglong2 cb = *reinterpret_cast<const ulonglong2*>(r0 + 128);
                u64 rcur[4] = {ca.x, ca.y, cb.x, cb.y};

                #pragma unroll 1
                for (int k = 0; k < cnt; k++) {
                    int kn = (k + 1 < cnt) ? (k + 1) : k;
                    int hnxt = lc[kn];
                    const float* rn = w2 + hnxt * H + 4 * lane;
                    ulonglong2 na = *reinterpret_cast<const ulonglong2*>(rn);
                    ulonglong2 nb = *reinterpret_cast<const ulonglong2*>(rn + 128);

                    const u64* wp3 = s->w3d[hcur];
                    ulonglong2 p0 = *reinterpret_cast<const ulonglong2*>(wp3);
                    ulonglong2 p1 = *reinterpret_cast<const ulonglong2*>(wp3 + 2);
                    ulonglong2 p2 = *reinterpret_cast<const ulonglong2*>(wp3 + 4);
                    u64 a[NS] = {p0.x, p0.y, p1.x, p1.y, p2.x, p2.y};

                    #pragma unroll
                    for (int i = 0; i < NS; i++)
                        #pragma unroll
                        for (int p = 0; p < 4; p++)
                            fma2(B2[i][p], a[i], rcur[p]);

                    rcur[0] = na.x; rcur[1] = na.y;
                    rcur[2] = nb.x; rcur[3] = nb.y;
                    hcur = hnxt;
                }
            }

            // unpack + fold m1 mask
            unsigned nlo = (s->m1w[c][lane >> 3]       >> (4 * (lane & 7))) & 0xFu;
            unsigned nhi = (s->m1w[c][4 + (lane >> 3)] >> (4 * (lane & 7))) & 0xFu;
            float ml[8];
            #pragma unroll
            for (int jj = 0; jj < 4; jj++) {
                ml[jj]     = ((nlo >> jj) & 1u) ? 1.0f : 0.0f;
                ml[4 + jj] = ((nhi >> jj) & 1u) ? 1.0f : 0.0f;
            }
            float Bm[NS][8];
            #pragma unroll
            for (int i = 0; i < NS; i++) {
                upk2(B2[i][0], Bm[i][0], Bm[i][1]);
                upk2(B2[i][1], Bm[i][2], Bm[i][3]);
                upk2(B2[i][2], Bm[i][4], Bm[i][5]);
                upk2(B2[i][3], Bm[i][6], Bm[i][7]);
                #pragma unroll
                for (int jj = 0; jj < 8; jj++) Bm[i][jj] *= ml[jj];
            }

            // epilogue: J[i][q] = sum_j Bm[i][j] * w1[j][q], via paired smem w1
            #pragma unroll 1
            for (int half = 0; half < 2; half++) {
                u64 Jq2[3][4];
                #pragma unroll
                for (int i3 = 0; i3 < 3; i3++)
                    #pragma unroll
                    for (int q2 = 0; q2 < 4; q2++) Jq2[i3][q2] = 0ull;

                #pragma unroll
                for (int q2 = 0; q2 < 4; q2++) {
                    const u64* wp = s->u.p3.w1p[q2];
                    ulonglong2 qa = *reinterpret_cast<const ulonglong2*>(&wp[4 * lane]);
                    ulonglong2 qb = *reinterpret_cast<const ulonglong2*>(&wp[4 * lane + 2]);
                    ulonglong2 qc = *reinterpret_cast<const ulonglong2*>(&wp[128 + 4 * lane]);
                    ulonglong2 qd = *reinterpret_cast<const ulonglong2*>(&wp[128 + 4 * lane + 2]);
                    u64 jp[8] = {qa.x, qa.y, qb.x, qb.y, qc.x, qc.y, qd.x, qd.y};
                    #pragma unroll
                    for (int i3 = 0; i3 < 3; i3++) {
                        #pragma unroll
                        for (int jj = 0; jj < 8; jj++) {
                            float bv = Bm[half * 3 + i3][jj];
                            u64 bv2 = pk2(bv, bv);
                            fma2(Jq2[i3][q2], bv2, jp[jj]);
                        }
                    }
                }

                #pragma unroll
                for (int i3 = 0; i3 < 3; i3++) {
                    int i = half * 3 + i3;
                    float Jq[8];
                    upk2(Jq2[i3][0], Jq[0], Jq[1]);
                    upk2(Jq2[i3][1], Jq[2], Jq[3]);
                    upk2(Jq2[i3][2], Jq[4], Jq[5]);
                    upk2(Jq2[i3][3], Jq[6], Jq[7]);
                    #pragma unroll
                    for (int q = 0; q < 8; q++) {
                        float v = Jq[q];
                        #pragma unroll
                        for (int o = 16; o > 0; o >>= 1)
                            v += __shfl_xor_sync(0xffffffffu, v, o);
                        Jq[q] = v;
                    }
                    if (lane == 0) {
                        #pragma unroll
                        for (int q = 0; q < 6; q++)
                            outDY[(size_t)n * 36 + i * 6 + q] = Jq[q];
                        outDE[(size_t)n * 6 + i] = Jq[6];
                        outDT[(size_t)n * 6 + i] = Jq[7];
                    }
                }
            }
        }
    }
}

extern "C" void kernel_launch(void* const* d_in, const int* in_sizes, int n_in,
                              void* d_out, int out_size) {
    // metadata order: t, y, erate, T, w1, w2, w3, b1, b2, b3
    const float* y  = (const float*)d_in[1];
    const float* er = (const float*)d_in[2];
    const float* Tg = (const float*)d_in[3];
    const float* w1 = (const float*)d_in[4];
    const float* w2 = (const float*)d_in[5];
    const float* w3 = (const float*)d_in[6];
    const float* b1 = (const float*)d_in[7];
    const float* b2 = (const float*)d_in[8];
    const float* b3 = (const float*)d_in[9];
    float* out = (float*)d_out;
    int ncell = in_sizes[2];             // NT*NB = 65536

    cudaFuncSetAttribute(k_fused, cudaFuncAttributeMaxDynamicSharedMemorySize,
                         (int)sizeof(Smem));

    dim3 tposeGrid(H / 32, H / 32);
    dim3 tposeBlock(32, 8);
    k_transpose<<<tposeGrid, tposeBlock>>>(w2);

    int nblocks = ncell / G;
    k_fused<<<nblocks, NTHREADS, sizeof(Smem)>>>(y, er, Tg, w1, w2, w3,
                                                 b1, b2, b3, out, ncell);
}

// round 6
// speedup vs baseline: 1.1845x; 1.0891x over previous
#include <cuda_runtime.h>
#include <cstdint>

#define H        256
#define NS       6
#define G        32      // cells per forward block
#define NTA      256
#define NCMAX    65536

typedef unsigned long long u64;

// ---------------- device scratch (allocations are forbidden) ----------------
__device__ float         g_w2T[H * H];        // g_w2T[j*H + h] = w2[h*H + j]
__device__ unsigned char g_m2cb[NCMAX * 32];  // m2 nibble bytes per cell
__device__ unsigned      g_m1w[NCMAX * 8];    // m1 ballot words per cell

// ---------------- w2 transpose ----------------
__global__ void k_transpose(const float* __restrict__ w2) {
    __shared__ float t[32][33];
    int j0 = blockIdx.x * 32, h0 = blockIdx.y * 32;
    int tx = threadIdx.x, ty = threadIdx.y;     // (32, 8)
    #pragma unroll
    for (int r = 0; r < 32; r += 8)
        t[ty + r][tx] = w2[(h0 + ty + r) * H + j0 + tx];
    __syncthreads();
    #pragma unroll
    for (int r = 0; r < 32; r += 8)
        g_w2T[(j0 + ty + r) * H + h0 + tx] = t[tx][ty + r];
}

// ---------------- f32x2 helpers ----------------
__device__ __forceinline__ u64 pk2(float lo, float hi) {
    u64 r; asm("mov.b64 %0, {%1, %2};" : "=l"(r) : "f"(lo), "f"(hi)); return r;
}
__device__ __forceinline__ void upk2(u64 v, float& lo, float& hi) {
    asm("mov.b64 {%0, %1}, %2;" : "=f"(lo), "=f"(hi) : "l"(v));
}
__device__ __forceinline__ void fma2(u64& d, u64 a, u64 b) {
    asm("fma.rn.f32x2 %0, %1, %2, %0;" : "+l"(d) : "l"(a), "l"(b));
}
// pack 8 nibbles (at bits 0,8,...,56 of x) into 32 bits
__device__ __forceinline__ unsigned pack8(u64 x) {
    x |= x >> 4;  x &= 0x00FF00FF00FF00FFull;
    x |= x >> 8;  x &= 0x0000FFFF0000FFFFull;
    x |= x >> 16;
    return (unsigned)x;
}

// ======================= kernel A: forward =======================
struct SmemA {
    float  v1t[H][36];     // v1 transposed [j][c]
    float4 w3f4[NS][64];   // w3f4[i][l] = w3[i][4l..4l+3]
    float  xs[G][8];       // per-cell inputs
};

__global__ void __launch_bounds__(NTA, 2)
k_fwd(const float* __restrict__ y,  const float* __restrict__ er,
      const float* __restrict__ Tg, const float* __restrict__ w1,
      const float* __restrict__ w3, const float* __restrict__ b1,
      const float* __restrict__ b2, const float* __restrict__ b3,
      float* __restrict__ out, int ncell)
{
    extern __shared__ char raw[];
    SmemA* s = reinterpret_cast<SmemA*>(raw);

    const int tid  = threadIdx.x;
    const int lane = tid & 31;
    const int wid  = tid >> 5;
    const int n0   = blockIdx.x * G;

    // ---------------- stage ----------------
    float w1r[8];
    #pragma unroll
    for (int q = 0; q < 8; q++) w1r[q] = w1[tid * 8 + q];
    #pragma unroll
    for (int idx = tid; idx < NS * 64; idx += NTA) {
        int i = idx >> 6, l = idx & 63;
        s->w3f4[i][l] = *reinterpret_cast<const float4*>(&w3[i * H + 4 * l]);
    }
    {
        int c = tid >> 3, q = tid & 7, n = n0 + c;
        float xv = (q < 6) ? y[n * 6 + q] : (q == 6 ? er[n] : Tg[n]);
        s->xs[c][q] = xv;
    }
    __syncthreads();

    // ---------------- phase 1: z1 / v1 / m1 (thread = neuron j = tid) ------
    {
        float b1v = b1[tid];
        #pragma unroll 4
        for (int c = 0; c < G; c++) {
            float z = b1v;
            #pragma unroll
            for (int q = 0; q < 8; q++) z = fmaf(w1r[q], s->xs[c][q], z);
            s->v1t[tid][c] = fmaxf(z, 0.0f);
            unsigned bal = __ballot_sync(0xffffffffu, z > 0.0f);
            if (lane == 0) g_m1w[(size_t)(n0 + c) * 8 + wid] = bal;
        }
    }
    __syncthreads();

    // ---------------- phase 2: z2 GEMM + ydot + m2 -------------------------
    // lane owns h in {4l..4l+3} u {128+4l..128+4l+3}; warp owns cells c0..c0+3
    const int c0 = wid * 4;
    {
        u64 acc2[4][4];
        #pragma unroll
        for (int r2 = 0; r2 < 4; r2++)
            #pragma unroll
            for (int cc = 0; cc < 4; cc++) acc2[r2][cc] = 0ull;

        #pragma unroll 2
        for (int j = 0; j < H; j++) {
            const float* wrow = g_w2T + j * H + 4 * lane;
            ulonglong2 wa = *reinterpret_cast<const ulonglong2*>(wrow);
            ulonglong2 wb = *reinterpret_cast<const ulonglong2*>(wrow + 128);
            u64 wv[4] = {wa.x, wa.y, wb.x, wb.y};
            float4 vv = *reinterpret_cast<const float4*>(&s->v1t[j][c0]);
            u64 vs[4] = {pk2(vv.x, vv.x), pk2(vv.y, vv.y),
                         pk2(vv.z, vv.z), pk2(vv.w, vv.w)};
            #pragma unroll
            for (int r2 = 0; r2 < 4; r2++)
                #pragma unroll
                for (int cc = 0; cc < 4; cc++)
                    fma2(acc2[r2][cc], wv[r2], vs[cc]);
        }

        // bias + relu + m2 bytes
        float4 b2lo = *reinterpret_cast<const float4*>(b2 + 4 * lane);
        float4 b2hi = *reinterpret_cast<const float4*>(b2 + 128 + 4 * lane);
        float b2a[8] = {b2lo.x, b2lo.y, b2lo.z, b2lo.w,
                        b2hi.x, b2hi.y, b2hi.z, b2hi.w};
        unsigned mbyte[4] = {0u, 0u, 0u, 0u};
        float v2r[8][4];
        #pragma unroll
        for (int r2 = 0; r2 < 4; r2++)
            #pragma unroll
            for (int cc = 0; cc < 4; cc++) {
                float lo, hi; upk2(acc2[r2][cc], lo, hi);
                float z0 = lo + b2a[2 * r2];
                float z1 = hi + b2a[2 * r2 + 1];
                v2r[2 * r2][cc]     = fmaxf(z0, 0.0f);
                v2r[2 * r2 + 1][cc] = fmaxf(z1, 0.0f);
                if (z0 > 0.0f) mbyte[cc] |= (1u << (2 * r2));
                if (z1 > 0.0f) mbyte[cc] |= (1u << (2 * r2 + 1));
            }
        #pragma unroll
        for (int cc = 0; cc < 4; cc++)
            g_m2cb[(size_t)(n0 + c0 + cc) * 32 + lane] = (unsigned char)mbyte[cc];

        // ydot partials: conflict-free float4 reads of w3
        float yp[NS][4];
        #pragma unroll
        for (int i = 0; i < NS; i++) {
            float4 wa = s->w3f4[i][lane];
            float4 wb = s->w3f4[i][32 + lane];
            float w3r[8] = {wa.x, wa.y, wa.z, wa.w, wb.x, wb.y, wb.z, wb.w};
            float a0 = 0.f, a1 = 0.f, a2 = 0.f, a3 = 0.f;
            #pragma unroll
            for (int r = 0; r < 8; r++) {
                a0 = fmaf(w3r[r], v2r[r][0], a0);
                a1 = fmaf(w3r[r], v2r[r][1], a1);
                a2 = fmaf(w3r[r], v2r[r][2], a2);
                a3 = fmaf(w3r[r], v2r[r][3], a3);
            }
            yp[i][0] = a0; yp[i][1] = a1; yp[i][2] = a2; yp[i][3] = a3;
        }

        #pragma unroll
        for (int i = 0; i < NS; i++)
            #pragma unroll
            for (int cc = 0; cc < 4; cc++) {
                float v = yp[i][cc];
                #pragma unroll
                for (int o = 16; o > 0; o >>= 1)
                    v += __shfl_xor_sync(0xffffffffu, v, o);
                yp[i][cc] = v;
            }
        if (lane == 0) {
            #pragma unroll
            for (int i = 0; i < NS; i++) {
                float b3v = b3[i];
                #pragma unroll
                for (int cc = 0; cc < 4; cc++)
                    out[(size_t)(n0 + c0 + cc) * NS + i] = yp[i][cc] + b3v;
            }
        }
    }
}

// ======================= kernel B: Jacobian =======================
struct SmemB {
    u64           w3d[H][6];    // pre-splatted w3 pairs (w3[i][h], w3[i][h])  12KB
    u64           w1p[4][H];    // w1p[q2][j] = (w1[j][2q2], w1[j][2q2+1])     8KB
    unsigned char lst[4][H];    // per-warp active-h list                      1KB
};

__global__ void __launch_bounds__(128, 5)
k_jac(const float* __restrict__ w1, const float* __restrict__ w2,
      const float* __restrict__ w3, float* __restrict__ out, int ncell)
{
    extern __shared__ char raw[];
    SmemB* s = reinterpret_cast<SmemB*>(raw);

    const int tid  = threadIdx.x;
    const int lane = tid & 31;
    const int wid  = tid >> 5;       // 0..3

    // ---------------- stage tables (128 threads) ----------------
    #pragma unroll
    for (int rep = 0; rep < 2; rep++) {
        int h = tid + 128 * rep;
        #pragma unroll
        for (int i = 0; i < NS; i++) {
            float v = w3[i * H + h];
            s->w3d[h][i] = pk2(v, v);
        }
        const float* wr = w1 + (size_t)h * 8;
        float4 a = *reinterpret_cast<const float4*>(wr);
        float4 b = *reinterpret_cast<const float4*>(wr + 4);
        s->w1p[0][h] = pk2(a.x, a.y);
        s->w1p[1][h] = pk2(a.z, a.w);
        s->w1p[2][h] = pk2(b.x, b.y);
        s->w1p[3][h] = pk2(b.z, b.w);
    }
    __syncthreads();

    const int n = blockIdx.x * 4 + wid;     // one cell per warp
    const size_t N = (size_t)ncell;
    float* outDY = out + 6 * N;
    float* outDE = out + 42 * N;
    float* outDT = out + 48 * N;

    // ---------------- masks ----------------
    unsigned m2w[8];
    {
        const u64* mp = reinterpret_cast<const u64*>(g_m2cb + (size_t)n * 32);
        #pragma unroll
        for (int d = 0; d < 4; d++) {
            u64 ch = mp[d];
            m2w[d]     = pack8(ch        & 0x0F0F0F0F0F0F0F0Full);
            m2w[4 + d] = pack8((ch >> 4) & 0x0F0F0F0F0F0F0F0Full);
        }
    }
    unsigned nlo = (g_m1w[(size_t)n * 8 + (lane >> 3)]     >> (4 * (lane & 7))) & 0xFu;
    unsigned nhi = (g_m1w[(size_t)n * 8 + 4 + (lane >> 3)] >> (4 * (lane & 7))) & 0xFu;

    // ---------------- compaction of active h ----------------
    unsigned char* lc = s->lst[wid];
    int cnt = 0;
    #pragma unroll
    for (int g = 0; g < 8; g++) {
        unsigned w = m2w[g];
        if ((w >> lane) & 1u)
            lc[cnt + __popc(w & ((1u << lane) - 1u))] =
                (unsigned char)(32 * g + lane);
        cnt += __popc(w);
    }
    __syncwarp();

    // ---------------- sparse contraction: B = (w3 o m2) @ w2 ---------------
    // lane owns j in {4l..4l+3} u {128+4l..128+4l+3}, packed in pairs
    u64 B2[NS][4];
    #pragma unroll
    for (int i = 0; i < NS; i++)
        #pragma unroll
        for (int p = 0; p < 4; p++) B2[i][p] = 0ull;

    if (cnt > 0) {
        int hcur = lc[0];
        const float* r0 = w2 + hcur * H + 4 * lane;
        ulonglong2 ca = *reinterpret_cast<const ulonglong2*>(r0);
        ulonglong2 cb = *reinterpret_cast<const ulonglong2*>(r0 + 128);
        u64 rcur[4] = {ca.x, ca.y, cb.x, cb.y};

        #pragma unroll 1
        for (int k = 0; k < cnt; k++) {
            int kn = (k + 1 < cnt) ? (k + 1) : k;
            int hnxt = lc[kn];
            const float* rn = w2 + hnxt * H + 4 * lane;
            ulonglong2 na = *reinterpret_cast<const ulonglong2*>(rn);
            ulonglong2 nb = *reinterpret_cast<const ulonglong2*>(rn + 128);

            const u64* wp3 = s->w3d[hcur];
            ulonglong2 p0 = *reinterpret_cast<const ulonglong2*>(wp3);
            ulonglong2 p1 = *reinterpret_cast<const ulonglong2*>(wp3 + 2);
            ulonglong2 p2 = *reinterpret_cast<const ulonglong2*>(wp3 + 4);
            u64 a[NS] = {p0.x, p0.y, p1.x, p1.y, p2.x, p2.y};

            #pragma unroll
            for (int i = 0; i < NS; i++)
                #pragma unroll
                for (int p = 0; p < 4; p++)
                    fma2(B2[i][p], a[i], rcur[p]);

            rcur[0] = na.x; rcur[1] = na.y;
            rcur[2] = nb.x; rcur[3] = nb.y;
            hcur = hnxt;
        }
    }

    // ---------------- fold m1, unpack ----------------
    float ml[8];
    #pragma unroll
    for (int jj = 0; jj < 4; jj++) {
        ml[jj]     = ((nlo >> jj) & 1u) ? 1.0f : 0.0f;
        ml[4 + jj] = ((nhi >> jj) & 1u) ? 1.0f : 0.0f;
    }
    float Bm[NS][8];
    #pragma unroll
    for (int i = 0; i < NS; i++) {
        upk2(B2[i][0], Bm[i][0], Bm[i][1]);
        upk2(B2[i][1], Bm[i][2], Bm[i][3]);
        upk2(B2[i][2], Bm[i][4], Bm[i][5]);
        upk2(B2[i][3], Bm[i][6], Bm[i][7]);
        #pragma unroll
        for (int jj = 0; jj < 8; jj++) Bm[i][jj] *= ml[jj];
    }

    // ---------------- epilogue: J[i][q] = sum_j Bm[i][j] * w1[j][q] --------
    // jj outer: one splat per (i, jj), reused across all 4 q-pairs
    #pragma unroll 1
    for (int half = 0; half < 2; half++) {
        u64 Jq2[3][4];
        #pragma unroll
        for (int i3 = 0; i3 < 3; i3++)
            #pragma unroll
            for (int q2 = 0; q2 < 4; q2++) Jq2[i3][q2] = 0ull;

        #pragma unroll
        for (int jj = 0; jj < 8; jj++) {
            int j = (jj < 4) ? (4 * lane + jj) : (128 + 4 * lane + (jj - 4));
            u64 jp0 = s->w1p[0][j];
            u64 jp1 = s->w1p[1][j];
            u64 jp2 = s->w1p[2][j];
            u64 jp3 = s->w1p[3][j];
            #pragma unroll
            for (int i3 = 0; i3 < 3; i3++) {
                float bv = Bm[half * 3 + i3][jj];
                u64 bv2 = pk2(bv, bv);
                fma2(Jq2[i3][0], bv2, jp0);
                fma2(Jq2[i3][1], bv2, jp1);
                fma2(Jq2[i3][2], bv2, jp2);
                fma2(Jq2[i3][3], bv2, jp3);
            }
        }

        #pragma unroll
        for (int i3 = 0; i3 < 3; i3++) {
            int i = half * 3 + i3;
            float Jq[8];
            upk2(Jq2[i3][0], Jq[0], Jq[1]);
            upk2(Jq2[i3][1], Jq[2], Jq[3]);
            upk2(Jq2[i3][2], Jq[4], Jq[5]);
            upk2(Jq2[i3][3], Jq[6], Jq[7]);
            #pragma unroll
            for (int q = 0; q < 8; q++) {
                float v = Jq[q];
                #pragma unroll
                for (int o = 16; o > 0; o >>= 1)
                    v += __shfl_xor_sync(0xffffffffu, v, o);
                Jq[q] = v;
            }
            if (lane == 0) {
                #pragma unroll
                for (int q = 0; q < 6; q++)
                    outDY[(size_t)n * 36 + i * 6 + q] = Jq[q];
                outDE[(size_t)n * 6 + i] = Jq[6];
                outDT[(size_t)n * 6 + i] = Jq[7];
            }
        }
    }
}

extern "C" void kernel_launch(void* const* d_in, const int* in_sizes, int n_in,
                              void* d_out, int out_size) {
    // metadata order: t, y, erate, T, w1, w2, w3, b1, b2, b3
    const float* y  = (const float*)d_in[1];
    const float* er = (const float*)d_in[2];
    const float* Tg = (const float*)d_in[3];
    const float* w1 = (const float*)d_in[4];
    const float* w2 = (const float*)d_in[5];
    const float* w3 = (const float*)d_in[6];
    const float* b1 = (const float*)d_in[7];
    const float* b2 = (const float*)d_in[8];
    const float* b3 = (const float*)d_in[9];
    float* out = (float*)d_out;
    int ncell = in_sizes[2];             // NT*NB = 65536

    cudaFuncSetAttribute(k_fwd, cudaFuncAttributeMaxDynamicSharedMemorySize,
                         (int)sizeof(SmemA));
    cudaFuncSetAttribute(k_jac, cudaFuncAttributeMaxDynamicSharedMemorySize,
                         (int)sizeof(SmemB));

    dim3 tposeGrid(H / 32, H / 32);
    dim3 tposeBlock(32, 8);
    k_transpose<<<tposeGrid, tposeBlock>>>(w2);

    k_fwd<<<ncell / G, NTA, sizeof(SmemA)>>>(y, er, Tg, w1, w3, b1, b2, b3,
                                             out, ncell);
    k_jac<<<ncell / 4, 128, sizeof(SmemB)>>>(w1, w2, w3, out, ncell);
}

// round 8
// speedup vs baseline: 1.2718x; 1.0737x over previous
#include <cuda_runtime.h>
#include <cstdint>

#define H        256
#define NS       6
#define G        32      // cells per forward block
#define NTA      256
#define NCMAX    65536

typedef unsigned long long u64;

// ---------------- device scratch (allocations are forbidden) ----------------
__device__ float         g_w2T[H * H];        // g_w2T[j*H + h] = w2[h*H + j]
__device__ u64           g_w2P[H * 128];      // paired rows for jac (see k_prep)
__device__ unsigned char g_m2cb[NCMAX * 32];  // m2 nibble bytes per cell
__device__ unsigned      g_m1w[NCMAX * 8];    // m1 ballot words per cell

// ---------------- f32x2 helpers ----------------
__device__ __forceinline__ u64 pk2(float lo, float hi) {
    u64 r; asm("mov.b64 %0, {%1, %2};" : "=l"(r) : "f"(lo), "f"(hi)); return r;
}
__device__ __forceinline__ void upk2(u64 v, float& lo, float& hi) {
    asm("mov.b64 {%0, %1}, %2;" : "=f"(lo), "=f"(hi) : "l"(v));
}
__device__ __forceinline__ void fma2(u64& d, u64 a, u64 b) {
    asm("fma.rn.f32x2 %0, %1, %2, %0;" : "+l"(d) : "l"(a), "l"(b));
}
// pack 8 nibbles (at bits 0,8,...,56 of x) into 32 bits
__device__ __forceinline__ unsigned pack8(u64 x) {
    x |= x >> 4;  x &= 0x00FF00FF00FF00FFull;
    x |= x >> 8;  x &= 0x0000FFFF0000FFFFull;
    x |= x >> 16;
    return (unsigned)x;
}

// ======================= prep: transpose w2 + build paired rows =============
// blocks 0..63:   g_w2T[j*H + h] = w2[h*H + j]
// blocks 64..191: g_w2P[((h*2 + p2)*32 + l)*2 + e] = pk2(w2[h][l+64p], w2[h][l+64p+32])
//                 with p = 2*p2 + e  (lane-contiguous ulonglong2 reads in k_jac)
__global__ void k_prep(const float* __restrict__ w2) {
    int bid = blockIdx.x, tid = threadIdx.x;
    if (bid < 64) {
        __shared__ float t[32][33];
        int j0 = (bid & 7) * 32, h0 = (bid >> 3) * 32;
        int tx = tid & 31, ty = tid >> 5;
        #pragma unroll
        for (int r = 0; r < 32; r += 8)
            t[ty + r][tx] = w2[(h0 + ty + r) * H + j0 + tx];
        __syncthreads();
        #pragma unroll
        for (int r = 0; r < 32; r += 8)
            g_w2T[(j0 + ty + r) * H + h0 + tx] = t[tx][ty + r];
    } else {
        int sub = tid >> 7;              // 0..1
        int idx = tid & 127;
        int p   = idx >> 5;              // 0..3
        int l   = idx & 31;
        int h   = (bid - 64) * 2 + sub;
        int p2  = p >> 1, e = p & 1;
        g_w2P[((size_t)(h * 2 + p2) * 32 + l) * 2 + e] =
            pk2(w2[h * H + l + 64 * p], w2[h * H + l + 64 * p + 32]);
    }
}

// ======================= kernel A: forward =======================
struct SmemA {
    u64    v1s[H][34];     // pre-splatted v1 pairs (v,v); pad 34 (16B-aligned)
    float4 w3f4[NS][64];   // w3f4[i][l] = w3[i][4l..4l+3]
    float  xs[G][8];       // per-cell inputs
};

__global__ void __launch_bounds__(NTA, 2)
k_fwd(const float* __restrict__ y,  const float* __restrict__ er,
      const float* __restrict__ Tg, const float* __restrict__ w1,
      const float* __restrict__ w3, const float* __restrict__ b1,
      const float* __restrict__ b2, const float* __restrict__ b3,
      float* __restrict__ out, int ncell)
{
    extern __shared__ char raw[];
    SmemA* s = reinterpret_cast<SmemA*>(raw);

    const int tid  = threadIdx.x;
    const int lane = tid & 31;
    const int wid  = tid >> 5;
    const int n0   = blockIdx.x * G;

    // ---------------- stage ----------------
    float w1r[8];
    #pragma unroll
    for (int q = 0; q < 8; q++) w1r[q] = w1[tid * 8 + q];
    #pragma unroll
    for (int idx = tid; idx < NS * 64; idx += NTA) {
        int i = idx >> 6, l = idx & 63;
        s->w3f4[i][l] = *reinterpret_cast<const float4*>(&w3[i * H + 4 * l]);
    }
    {
        int c = tid >> 3, q = tid & 7, n = n0 + c;
        float xv = (q < 6) ? y[n * 6 + q] : (q == 6 ? er[n] : Tg[n]);
        s->xs[c][q] = xv;
    }
    __syncthreads();

    // ---------------- phase 1: z1 / v1 / m1 (thread = neuron j = tid) ------
    {
        float b1v = b1[tid];
        #pragma unroll 4
        for (int c = 0; c < G; c++) {
            float z = b1v;
            #pragma unroll
            for (int q = 0; q < 8; q++) z = fmaf(w1r[q], s->xs[c][q], z);
            float v = fmaxf(z, 0.0f);
            s->v1s[tid][c] = pk2(v, v);
            unsigned bal = __ballot_sync(0xffffffffu, z > 0.0f);
            if (lane == 0) g_m1w[(size_t)(n0 + c) * 8 + wid] = bal;
        }
    }
    __syncthreads();

    // ---------------- phase 2: z2 GEMM + ydot + m2 -------------------------
    // lane owns h in {4l..4l+3} u {128+4l..128+4l+3}; warp owns cells c0..c0+3
    const int c0 = wid * 4;
    {
        u64 acc2[4][4];
        #pragma unroll
        for (int r2 = 0; r2 < 4; r2++)
            #pragma unroll
            for (int cc = 0; cc < 4; cc++) acc2[r2][cc] = 0ull;

        #pragma unroll 2
        for (int j = 0; j < H; j++) {
            const float* wrow = g_w2T + j * H + 4 * lane;
            ulonglong2 wa = *reinterpret_cast<const ulonglong2*>(wrow);
            ulonglong2 wb = *reinterpret_cast<const ulonglong2*>(wrow + 128);
            u64 wv[4] = {wa.x, wa.y, wb.x, wb.y};
            ulonglong2 va = *reinterpret_cast<const ulonglong2*>(&s->v1s[j][c0]);
            ulonglong2 vb = *reinterpret_cast<const ulonglong2*>(&s->v1s[j][c0 + 2]);
            u64 vs[4] = {va.x, va.y, vb.x, vb.y};
            #pragma unroll
            for (int r2 = 0; r2 < 4; r2++)
                #pragma unroll
                for (int cc = 0; cc < 4; cc++)
                    fma2(acc2[r2][cc], wv[r2], vs[cc]);
        }

        // bias + relu + m2 bytes
        float4 b2lo = *reinterpret_cast<const float4*>(b2 + 4 * lane);
        float4 b2hi = *reinterpret_cast<const float4*>(b2 + 128 + 4 * lane);
        float b2a[8] = {b2lo.x, b2lo.y, b2lo.z, b2lo.w,
                        b2hi.x, b2hi.y, b2hi.z, b2hi.w};
        unsigned mbyte[4] = {0u, 0u, 0u, 0u};
        float v2r[8][4];
        #pragma unroll
        for (int r2 = 0; r2 < 4; r2++)
            #pragma unroll
            for (int cc = 0; cc < 4; cc++) {
                float lo, hi; upk2(acc2[r2][cc], lo, hi);
                float z0 = lo + b2a[2 * r2];
                float z1 = hi + b2a[2 * r2 + 1];
                v2r[2 * r2][cc]     = fmaxf(z0, 0.0f);
                v2r[2 * r2 + 1][cc] = fmaxf(z1, 0.0f);
                if (z0 > 0.0f) mbyte[cc] |= (1u << (2 * r2));
                if (z1 > 0.0f) mbyte[cc] |= (1u << (2 * r2 + 1));
            }
        #pragma unroll
        for (int cc = 0; cc < 4; cc++)
            g_m2cb[(size_t)(n0 + c0 + cc) * 32 + lane] = (unsigned char)mbyte[cc];

        // ydot partials
        float yp[NS][4];
        #pragma unroll
        for (int i = 0; i < NS; i++) {
            float4 wa = s->w3f4[i][lane];
            float4 wb = s->w3f4[i][32 + lane];
            float w3r[8] = {wa.x, wa.y, wa.z, wa.w, wb.x, wb.y, wb.z, wb.w};
            float a0 = 0.f, a1 = 0.f, a2 = 0.f, a3 = 0.f;
            #pragma unroll
            for (int r = 0; r < 8; r++) {
                a0 = fmaf(w3r[r], v2r[r][0], a0);
                a1 = fmaf(w3r[r], v2r[r][1], a1);
                a2 = fmaf(w3r[r], v2r[r][2], a2);
                a3 = fmaf(w3r[r], v2r[r][3], a3);
            }
            yp[i][0] = a0; yp[i][1] = a1; yp[i][2] = a2; yp[i][3] = a3;
        }

        #pragma unroll
        for (int i = 0; i < NS; i++)
            #pragma unroll
            for (int cc = 0; cc < 4; cc++) {
                float v = yp[i][cc];
                #pragma unroll
                for (int o = 16; o > 0; o >>= 1)
                    v += __shfl_xor_sync(0xffffffffu, v, o);
                yp[i][cc] = v;
            }
        if (lane == 0) {
            #pragma unroll
            for (int i = 0; i < NS; i++) {
                float b3v = b3[i];
                #pragma unroll
                for (int cc = 0; cc < 4; cc++)
                    out[(size_t)(n0 + c0 + cc) * NS + i] = yp[i][cc] + b3v;
            }
        }
    }
}

// ======================= kernel B: Jacobian =======================
// Ownership: lane l owns j in {l + 32k : k = 0..7}; pair p: (l+64p, l+64p+32).
struct SmemB {
    u64           w3d[H][6];    // pre-splatted w3 pairs (w3[i][h], w3[i][h])  12KB
    u64           w1p[4][H];    // w1p[q2][j] = (w1[j][2q2], w1[j][2q2+1])     8KB
    unsigned char lst[4][H];    // per-warp active-h list                      1KB
};

__global__ void __launch_bounds__(128, 5)
k_jac(const float* __restrict__ w1, const float* __restrict__ w3,
      float* __restrict__ out, int ncell)
{
    extern __shared__ char raw[];
    SmemB* s = reinterpret_cast<SmemB*>(raw);

    const int tid  = threadIdx.x;
    const int lane = tid & 31;
    const int wid  = tid >> 5;       // 0..3

    // ---------------- stage tables (128 threads) ----------------
    #pragma unroll
    for (int rep = 0; rep < 2; rep++) {
        int h = tid + 128 * rep;
        #pragma unroll
        for (int i = 0; i < NS; i++) {
            float v = w3[i * H + h];
            s->w3d[h][i] = pk2(v, v);
        }
        const float* wr = w1 + (size_t)h * 8;
        float4 a = *reinterpret_cast<const float4*>(wr);
        float4 b = *reinterpret_cast<const float4*>(wr + 4);
        s->w1p[0][h] = pk2(a.x, a.y);
        s->w1p[1][h] = pk2(a.z, a.w);
        s->w1p[2][h] = pk2(b.x, b.y);
        s->w1p[3][h] = pk2(b.z, b.w);
    }
    __syncthreads();

    const int n = blockIdx.x * 4 + wid;     // one cell per warp
    const size_t N = (size_t)ncell;
    float* outDY = out + 6 * N;
    float* outDE = out + 42 * N;
    float* outDT = out + 48 * N;

    // ---------------- masks ----------------
    unsigned m2w[8];
    {
        const u64* mp = reinterpret_cast<const u64*>(g_m2cb + (size_t)n * 32);
        #pragma unroll
        for (int d = 0; d < 4; d++) {
            u64 ch = mp[d];
            m2w[d]     = pack8(ch        & 0x0F0F0F0F0F0F0F0Full);
            m2w[4 + d] = pack8((ch >> 4) & 0x0F0F0F0F0F0F0F0Full);
        }
    }
    unsigned mwv[8];
    {
        const uint4* mp = reinterpret_cast<const uint4*>(g_m1w + (size_t)n * 8);
        uint4 ma = mp[0], mb = mp[1];
        mwv[0] = ma.x; mwv[1] = ma.y; mwv[2] = ma.z; mwv[3] = ma.w;
        mwv[4] = mb.x; mwv[5] = mb.y; mwv[6] = mb.z; mwv[7] = mb.w;
    }

    // ---------------- compaction of active h ----------------
    unsigned char* lc = s->lst[wid];
    int cnt = 0;
    #pragma unroll
    for (int g = 0; g < 8; g++) {
        unsigned w = m2w[g];
        if ((w >> lane) & 1u)
            lc[cnt + __popc(w & ((1u << lane) - 1u))] =
                (unsigned char)(32 * g + lane);
        cnt += __popc(w);
    }
    __syncwarp();

    // ---------------- sparse contraction: B = (w3 o m2) @ w2 ---------------
    u64 B2[NS][4];      // pair p <-> (k = 2p, k = 2p+1), j = lane + 32k
    #pragma unroll
    for (int i = 0; i < NS; i++)
        #pragma unroll
        for (int p = 0; p < 4; p++) B2[i][p] = 0ull;

    if (cnt > 0) {
        int hcur = lc[0];
        const u64* rp0 = g_w2P + (size_t)hcur * 128 + lane * 2;
        ulonglong2 ca = *reinterpret_cast<const ulonglong2*>(rp0);       // p=0,1
        ulonglong2 cb = *reinterpret_cast<const ulonglong2*>(rp0 + 64);  // p=2,3
        u64 rcur[4] = {ca.x, ca.y, cb.x, cb.y};

        #pragma unroll 2
        for (int k = 0; k < cnt; k++) {
            int kn = (k + 1 < cnt) ? (k + 1) : k;
            int hnxt = lc[kn];
            const u64* rp = g_w2P + (size_t)hnxt * 128 + lane * 2;
            ulonglong2 na = *reinterpret_cast<const ulonglong2*>(rp);
            ulonglong2 nb = *reinterpret_cast<const ulonglong2*>(rp + 64);

            const u64* wp3 = s->w3d[hcur];
            ulonglong2 p0 = *reinterpret_cast<const ulonglong2*>(wp3);
            ulonglong2 p1 = *reinterpret_cast<const ulonglong2*>(wp3 + 2);
            ulonglong2 p2 = *reinterpret_cast<const ulonglong2*>(wp3 + 4);
            u64 a[NS] = {p0.x, p0.y, p1.x, p1.y, p2.x, p2.y};

            #pragma unroll
            for (int i = 0; i < NS; i++)
                #pragma unroll
                for (int p = 0; p < 4; p++)
                    fma2(B2[i][p], a[i], rcur[p]);

            rcur[0] = na.x; rcur[1] = na.y;
            rcur[2] = nb.x; rcur[3] = nb.y;
            hcur = hnxt;
        }
    }

    // ---------------- fold m1, unpack ----------------
    float ml[8];
    #pragma unroll
    for (int k = 0; k < 8; k++)
        ml[k] = ((mwv[k] >> lane) & 1u) ? 1.0f : 0.0f;

    float Bm[NS][8];
    #pragma unroll
    for (int i = 0; i < NS; i++) {
        #pragma unroll
        for (int p = 0; p < 4; p++)
            upk2(B2[i][p], Bm[i][2 * p], Bm[i][2 * p + 1]);
        #pragma unroll
        for (int k = 0; k < 8; k++) Bm[i][k] *= ml[k];
    }

    // ---------------- epilogue: J[i][q] = sum_j Bm[i][j] * w1[j][q] --------
    #pragma unroll 1
    for (int half = 0; half < 2; half++) {
        u64 Jq2[3][4];
        #pragma unroll
        for (int i3 = 0; i3 < 3; i3++)
            #pragma unroll
            for (int q2 = 0; q2 < 4; q2++) Jq2[i3][q2] = 0ull;

        #pragma unroll
        for (int k = 0; k < 8; k++) {
            int j = 32 * k + lane;              // conflict-free LDS.64
            u64 jp0 = s->w1p[0][j];
            u64 jp1 = s->w1p[1][j];
            u64 jp2 = s->w1p[2][j];
            u64 jp3 = s->w1p[3][j];
            #pragma unroll
            for (int i3 = 0; i3 < 3; i3++) {
                float bv = Bm[half * 3 + i3][k];
                u64 bv2 = pk2(bv, bv);
                fma2(Jq2[i3][0], bv2, jp0);
                fma2(Jq2[i3][1], bv2, jp1);
                fma2(Jq2[i3][2], bv2, jp2);
                fma2(Jq2[i3][3], bv2, jp3);
            }
        }

        #pragma unroll
        for (int i3 = 0; i3 < 3; i3++) {
            int i = half * 3 + i3;
            float Jq[8];
            upk2(Jq2[i3][0], Jq[0], Jq[1]);
            upk2(Jq2[i3][1], Jq[2], Jq[3]);
            upk2(Jq2[i3][2], Jq[4], Jq[5]);
            upk2(Jq2[i3][3], Jq[6], Jq[7]);
            #pragma unroll
            for (int q = 0; q < 8; q++) {
                float v = Jq[q];
                #pragma unroll
                for (int o = 16; o > 0; o >>= 1)
                    v += __shfl_xor_sync(0xffffffffu, v, o);
                Jq[q] = v;
            }
            if (lane == 0) {
                #pragma unroll
                for (int q = 0; q < 6; q++)
                    outDY[(size_t)n * 36 + i * 6 + q] = Jq[q];
                outDE[(size_t)n * 6 + i] = Jq[6];
                outDT[(size_t)n * 6 + i] = Jq[7];
            }
        }
    }
}

extern "C" void kernel_launch(void* const* d_in, const int* in_sizes, int n_in,
                              void* d_out, int out_size) {
    // metadata order: t, y, erate, T, w1, w2, w3, b1, b2, b3
    const float* y  = (const float*)d_in[1];
    const float* er = (const float*)d_in[2];
    const float* Tg = (const float*)d_in[3];
    const float* w1 = (const float*)d_in[4];
    const float* w2 = (const float*)d_in[5];
    const float* w3 = (const float*)d_in[6];
    const float* b1 = (const float*)d_in[7];
    const float* b2 = (const float*)d_in[8];
    const float* b3 = (const float*)d_in[9];
    float* out = (float*)d_out;
    int ncell = in_sizes[2];             // NT*NB = 65536

    cudaFuncSetAttribute(k_fwd, cudaFuncAttributeMaxDynamicSharedMemorySize,
                         (int)sizeof(SmemA));
    cudaFuncSetAttribute(k_jac, cudaFuncAttributeMaxDynamicSharedMemorySize,
                         (int)sizeof(SmemB));

    k_prep<<<192, 256>>>(w2);
    k_fwd<<<ncell / G, NTA, sizeof(SmemA)>>>(y, er, Tg, w1, w3, b1, b2, b3,
                                             out, ncell);
    k_jac<<<ncell / 4, 128, sizeof(SmemB)>>>(w1, w3, out, ncell);
}

// round 10
// speedup vs baseline: 1.3152x; 1.0341x over previous
#include <cuda_runtime.h>
#include <cuda_bf16.h>
#include <cstdint>

#define H        256
#define NS       6
#define G        32      // cells per forward block
#define NTA      256
#define CPB      16      // cells per jacobian CTA

typedef unsigned long long u64;
typedef unsigned int u32;

// ---------------- device scratch (allocations are forbidden) ----------------
__device__ float         g_w2T[H * H];        // for k_fwd
__device__ u32           g_wB[2 * 256 * 128]; // bf16 pairs: [split][n][k/2]
__device__ unsigned char g_m2cb[65536 * 32];  // m2 nibble bytes per cell
__device__ u32           g_m1w[65536 * 8];    // m1 ballot words per cell

// ---------------- helpers ----------------
__device__ __forceinline__ u64 pk2(float lo, float hi) {
    u64 r; asm("mov.b64 %0, {%1, %2};" : "=l"(r) : "f"(lo), "f"(hi)); return r;
}
__device__ __forceinline__ void upk2(u64 v, float& lo, float& hi) {
    asm("mov.b64 {%0, %1}, %2;" : "=f"(lo), "=f"(hi) : "l"(v));
}
__device__ __forceinline__ void fma2(u64& d, u64 a, u64 b) {
    asm("fma.rn.f32x2 %0, %1, %2, %0;" : "+l"(d) : "l"(a), "l"(b));
}
__device__ __forceinline__ u32 pack8(u64 x) {
    x |= x >> 4;  x &= 0x00FF00FF00FF00FFull;
    x |= x >> 8;  x &= 0x0000FFFF0000FFFFull;
    x |= x >> 16;
    return (u32)x;
}
__device__ __forceinline__ unsigned short bfs(float v, int s) {
    __nv_bfloat16 h0 = __float2bfloat16(v);
    if (s == 0) return __bfloat16_as_ushort(h0);
    float r = v - __bfloat162float(h0);
    return __bfloat16_as_ushort(__float2bfloat16(r));
}
// D += A(bf16) * B(bf16), m16n8k16 row.col, f32 accum
__device__ __forceinline__ void mma16816(float* d, const u32* a, u32 b0, u32 b1) {
    asm volatile(
        "mma.sync.aligned.m16n8k16.row.col.f32.bf16.bf16.f32 "
        "{%0,%1,%2,%3}, {%4,%5,%6,%7}, {%8,%9}, {%0,%1,%2,%3};"
        : "+f"(d[0]), "+f"(d[1]), "+f"(d[2]), "+f"(d[3])
        : "r"(a[0]), "r"(a[1]), "r"(a[2]), "r"(a[3]), "r"(b0), "r"(b1));
}
__device__ __forceinline__ u32 mask2(u32 bits) {
    return ((bits & 1u) ? 0x0000FFFFu : 0u) | ((bits & 2u) ? 0xFFFF0000u : 0u);
}

// ======================= prep: transpose + bf16 W pairs =====================
__global__ void k_prep(const float* __restrict__ w2) {
    int bid = blockIdx.x, tid = threadIdx.x;
    if (bid < 64) {
        __shared__ float t[32][33];
        int j0 = (bid & 7) * 32, h0 = (bid >> 3) * 32;
        int tx = tid & 31, ty = tid >> 5;
        #pragma unroll
        for (int r = 0; r < 32; r += 8)
            t[ty + r][tx] = w2[(h0 + ty + r) * H + j0 + tx];
        __syncthreads();
        #pragma unroll
        for (int r = 0; r < 32; r += 8)
            g_w2T[(j0 + ty + r) * H + h0 + tx] = t[tx][ty + r];
    } else {
        // g_wB[(s*256 + n)*128 + p] = bf16pair(w2[2p][n], w2[2p+1][n]) split s
        int base = (bid - 64) * 1024 + tid * 4;
        #pragma unroll
        for (int e = 0; e < 4; e++) {
            int idx = base + e;
            int s = idx >> 15;
            int rem = idx & 32767;
            int n = rem >> 7, p = rem & 127;
            float va = w2[(size_t)(2 * p) * H + n];
            float vb = w2[(size_t)(2 * p + 1) * H + n];
            g_wB[idx] = (u32)bfs(va, s) | ((u32)bfs(vb, s) << 16);
        }
    }
}

// ======================= kernel A: forward (unchanged, passing) =============
struct SmemA {
    u64    v1s[H][34];
    float4 w3f4[NS][64];
    float  xs[G][8];
};

__global__ void __launch_bounds__(NTA, 2)
k_fwd(const float* __restrict__ y,  const float* __restrict__ er,
      const float* __restrict__ Tg, const float* __restrict__ w1,
      const float* __restrict__ w3, const float* __restrict__ b1,
      const float* __restrict__ b2, const float* __restrict__ b3,
      float* __restrict__ out, int ncell)
{
    extern __shared__ char raw[];
    SmemA* s = reinterpret_cast<SmemA*>(raw);

    const int tid  = threadIdx.x;
    const int lane = tid & 31;
    const int wid  = tid >> 5;
    const int n0   = blockIdx.x * G;

    float w1r[8];
    #pragma unroll
    for (int q = 0; q < 8; q++) w1r[q] = w1[tid * 8 + q];
    #pragma unroll
    for (int idx = tid; idx < NS * 64; idx += NTA) {
        int i = idx >> 6, l = idx & 63;
        s->w3f4[i][l] = *reinterpret_cast<const float4*>(&w3[i * H + 4 * l]);
    }
    {
        int c = tid >> 3, q = tid & 7, n = n0 + c;
        float xv = (q < 6) ? y[n * 6 + q] : (q == 6 ? er[n] : Tg[n]);
        s->xs[c][q] = xv;
    }
    __syncthreads();

    {
        float b1v = b1[tid];
        #pragma unroll 4
        for (int c = 0; c < G; c++) {
            float z = b1v;
            #pragma unroll
            for (int q = 0; q < 8; q++) z = fmaf(w1r[q], s->xs[c][q], z);
            float v = fmaxf(z, 0.0f);
            s->v1s[tid][c] = pk2(v, v);
            unsigned bal = __ballot_sync(0xffffffffu, z > 0.0f);
            if (lane == 0) g_m1w[(size_t)(n0 + c) * 8 + wid] = bal;
        }
    }
    __syncthreads();

    const int c0 = wid * 4;
    {
        u64 acc2[4][4];
        #pragma unroll
        for (int r2 = 0; r2 < 4; r2++)
            #pragma unroll
            for (int cc = 0; cc < 4; cc++) acc2[r2][cc] = 0ull;

        #pragma unroll 2
        for (int j = 0; j < H; j++) {
            const float* wrow = g_w2T + j * H + 4 * lane;
            ulonglong2 wa = *reinterpret_cast<const ulonglong2*>(wrow);
            ulonglong2 wb = *reinterpret_cast<const ulonglong2*>(wrow + 128);
            u64 wv[4] = {wa.x, wa.y, wb.x, wb.y};
            ulonglong2 va = *reinterpret_cast<const ulonglong2*>(&s->v1s[j][c0]);
            ulonglong2 vb = *reinterpret_cast<const ulonglong2*>(&s->v1s[j][c0 + 2]);
            u64 vs[4] = {va.x, va.y, vb.x, vb.y};
            #pragma unroll
            for (int r2 = 0; r2 < 4; r2++)
                #pragma unroll
                for (int cc = 0; cc < 4; cc++)
                    fma2(acc2[r2][cc], wv[r2], vs[cc]);
        }

        float4 b2lo = *reinterpret_cast<const float4*>(b2 + 4 * lane);
        float4 b2hi = *reinterpret_cast<const float4*>(b2 + 128 + 4 * lane);
        float b2a[8] = {b2lo.x, b2lo.y, b2lo.z, b2lo.w,
                        b2hi.x, b2hi.y, b2hi.z, b2hi.w};
        unsigned mbyte[4] = {0u, 0u, 0u, 0u};
        float v2r[8][4];
        #pragma unroll
        for (int r2 = 0; r2 < 4; r2++)
            #pragma unroll
            for (int cc = 0; cc < 4; cc++) {
                float lo, hi; upk2(acc2[r2][cc], lo, hi);
                float z0 = lo + b2a[2 * r2];
                float z1 = hi + b2a[2 * r2 + 1];
                v2r[2 * r2][cc]     = fmaxf(z0, 0.0f);
                v2r[2 * r2 + 1][cc] = fmaxf(z1, 0.0f);
                if (z0 > 0.0f) mbyte[cc] |= (1u << (2 * r2));
                if (z1 > 0.0f) mbyte[cc] |= (1u << (2 * r2 + 1));
            }
        #pragma unroll
        for (int cc = 0; cc < 4; cc++)
            g_m2cb[(size_t)(n0 + c0 + cc) * 32 + lane] = (unsigned char)mbyte[cc];

        float yp[NS][4];
        #pragma unroll
        for (int i = 0; i < NS; i++) {
            float4 wa = s->w3f4[i][lane];
            float4 wb = s->w3f4[i][32 + lane];
            float w3r[8] = {wa.x, wa.y, wa.z, wa.w, wb.x, wb.y, wb.z, wb.w};
            float a0 = 0.f, a1 = 0.f, a2 = 0.f, a3 = 0.f;
            #pragma unroll
            for (int r = 0; r < 8; r++) {
                a0 = fmaf(w3r[r], v2r[r][0], a0);
                a1 = fmaf(w3r[r], v2r[r][1], a1);
                a2 = fmaf(w3r[r], v2r[r][2], a2);
                a3 = fmaf(w3r[r], v2r[r][3], a3);
            }
            yp[i][0] = a0; yp[i][1] = a1; yp[i][2] = a2; yp[i][3] = a3;
        }

        #pragma unroll
        for (int i = 0; i < NS; i++)
            #pragma unroll
            for (int cc = 0; cc < 4; cc++) {
                float v = yp[i][cc];
                #pragma unroll
                for (int o = 16; o > 0; o >>= 1)
                    v += __shfl_xor_sync(0xffffffffu, v, o);
                yp[i][cc] = v;
            }
        if (lane == 0) {
            #pragma unroll
            for (int i = 0; i < NS; i++) {
                float b3v = b3[i];
                #pragma unroll
                for (int cc = 0; cc < 4; cc++)
                    out[(size_t)(n0 + c0 + cc) * NS + i] = yp[i][cc] + b3v;
            }
        }
    }
}

// ======================= kernel B: mma.sync Jacobian ========================
// Per CTA: 16 cells. Warp w owns D rows [16w, 16w+16): cellA=2w (rows g),
// cellB=2w+1 (rows g+8), ii=g (g>=6 are zero pad rows).
struct SmemJ {
    u32 W[2][128][68];      // [split][n-local][k-pair local(64), pad 68]
    u64 w1p[4][256];        // w1 pairs per j
    u32 w3p[2][6][132];     // bf16 pair (w3s[i][2p], w3s[i][2p+1]), pad 132
    u32 m2[16][8];          // m2 bit-words per cell
};

__global__ void __launch_bounds__(256, 2)
k_jacM(const float* __restrict__ w1, const float* __restrict__ w3,
       float* __restrict__ out, int ncell)
{
    extern __shared__ char raw[];
    SmemJ* s = reinterpret_cast<SmemJ*>(raw);

    const int tid  = threadIdx.x;
    const int lane = tid & 31;
    const int wid  = tid >> 5;      // 0..7
    const int g    = lane >> 2;     // 0..7
    const int tg   = lane & 3;
    const int gi   = (g < 6) ? g : 5;
    const int n0   = blockIdx.x * CPB;
    const int cellA = 2 * wid, cellB = 2 * wid + 1;

    // ---------------- stage tables ----------------
    {
        int j = tid;
        const float* wr = w1 + (size_t)j * 8;
        float4 a = *reinterpret_cast<const float4*>(wr);
        float4 b = *reinterpret_cast<const float4*>(wr + 4);
        s->w1p[0][j] = pk2(a.x, a.y);
        s->w1p[1][j] = pk2(a.z, a.w);
        s->w1p[2][j] = pk2(b.x, b.y);
        s->w1p[3][j] = pk2(b.z, b.w);
    }
    for (int idx = tid; idx < 2 * 6 * 128; idx += 256) {
        int sp = idx / 768;
        int r = idx - sp * 768;
        int ii = r >> 7, p = r & 127;
        float va = w3[ii * H + 2 * p], vb = w3[ii * H + 2 * p + 1];
        s->w3p[sp][ii][p] = (u32)bfs(va, sp) | ((u32)bfs(vb, sp) << 16);
    }
    if (tid < CPB) {
        const u64* mp = (const u64*)(g_m2cb + (size_t)(n0 + tid) * 32);
        #pragma unroll
        for (int d = 0; d < 4; d++) {
            u64 ch = mp[d];
            s->m2[tid][d]     = pack8(ch & 0x0F0F0F0F0F0F0F0Full);
            s->m2[tid][4 + d] = pack8((ch >> 4) & 0x0F0F0F0F0F0F0F0Full);
        }
    }
    __syncthreads();

    u64 JA2[4] = {0ull, 0ull, 0ull, 0ull};
    u64 JB2[4] = {0ull, 0ull, 0ull, 0ull};

    #pragma unroll 1
    for (int np = 0; np < 2; np++) {
        float d[16][4];
        #pragma unroll
        for (int t = 0; t < 16; t++)
            #pragma unroll
            for (int c = 0; c < 4; c++) d[t][c] = 0.0f;

        #pragma unroll 1
        for (int kc = 0; kc < 2; kc++) {
            __syncthreads();
            // copy W chunk [2][128 n][64 pairs]
            {
                int sp = tid >> 7, nl = tid & 127;
                const uint4* src = (const uint4*)(g_wB +
                    ((size_t)(sp * 256 + np * 128 + nl) * 128 + kc * 64));
                u32* dst = &s->W[sp][nl][0];
                #pragma unroll
                for (int q = 0; q < 16; q++)
                    *reinterpret_cast<uint4*>(dst + q * 4) = src[q];
            }
            __syncthreads();

            #pragma unroll 1
            for (int kss = 0; kss < 8; kss++) {
                int ksg = kc * 8 + kss;
                int p0g = ksg * 8 + tg;
                u32 wm2A = s->m2[cellA][ksg >> 1];
                u32 wm2B = s->m2[cellB][ksg >> 1];
                int sh0 = ((ksg & 1) << 4) + tg * 2;
                u32 mkA0 = mask2((wm2A >> sh0) & 3u);
                u32 mkB0 = mask2((wm2B >> sh0) & 3u);
                u32 mkA1 = mask2((wm2A >> (sh0 + 8)) & 3u);
                u32 mkB1 = mask2((wm2B >> (sh0 + 8)) & 3u);

                u32 a0[4], a1[4];
                {
                    u32 w300 = (g < 6) ? s->w3p[0][gi][p0g] : 0u;
                    u32 w301 = (g < 6) ? s->w3p[0][gi][p0g + 4] : 0u;
                    u32 w310 = (g < 6) ? s->w3p[1][gi][p0g] : 0u;
                    u32 w311 = (g < 6) ? s->w3p[1][gi][p0g + 4] : 0u;
                    a0[0] = w300 & mkA0; a0[1] = w300 & mkB0;
                    a0[2] = w301 & mkA1; a0[3] = w301 & mkB1;
                    a1[0] = w310 & mkA0; a1[1] = w310 & mkB0;
                    a1[2] = w311 & mkA1; a1[3] = w311 & mkB1;
                }
                int pl0 = kss * 8 + tg;
                #pragma unroll
                for (int t = 0; t < 16; t++) {
                    int nl = t * 8 + g;
                    u32 b00 = s->W[0][nl][pl0], b01 = s->W[0][nl][pl0 + 4];
                    u32 b10 = s->W[1][nl][pl0], b11 = s->W[1][nl][pl0 + 4];
                    mma16816(d[t], a0, b00, b01);   // E0*W0
                    mma16816(d[t], a1, b00, b01);   // E1*W0
                    mma16816(d[t], a0, b10, b11);   // E0*W1
                }
            }
        }

        // ---------------- fold D into J (m1 mask + w1) ----------------
        u32 mA[8], mB[8];
        {
            const uint4* pa = (const uint4*)(g_m1w + (size_t)(n0 + cellA) * 8);
            uint4 x = pa[0], z = pa[1];
            mA[0] = x.x; mA[1] = x.y; mA[2] = x.z; mA[3] = x.w;
            mA[4] = z.x; mA[5] = z.y; mA[6] = z.z; mA[7] = z.w;
            const uint4* pb = (const uint4*)(g_m1w + (size_t)(n0 + cellB) * 8);
            uint4 x2 = pb[0], z2 = pb[1];
            mB[0] = x2.x; mB[1] = x2.y; mB[2] = x2.z; mB[3] = x2.w;
            mB[4] = z2.x; mB[5] = z2.y; mB[6] = z2.z; mB[7] = z2.w;
        }
        #pragma unroll
        for (int t = 0; t < 16; t++) {
            int widx = np * 4 + (t >> 2);
            int sh = ((t & 3) * 8) + tg * 2;
            u32 wa = mA[widx] >> sh;
            u32 wb = mB[widx] >> sh;
            int j0 = np * 128 + t * 8 + tg * 2;

            float vA0 = (wa & 1u) ? d[t][0] : 0.0f;
            float vA1 = (wa & 2u) ? d[t][1] : 0.0f;
            float vB0 = (wb & 1u) ? d[t][2] : 0.0f;
            float vB1 = (wb & 2u) ? d[t][3] : 0.0f;
            u64 pA0 = pk2(vA0, vA0), pA1 = pk2(vA1, vA1);
            u64 pB0 = pk2(vB0, vB0), pB1 = pk2(vB1, vB1);
            #pragma unroll
            for (int q2 = 0; q2 < 4; q2++) {
                u64 wp0 = s->w1p[q2][j0];
                u64 wp1 = s->w1p[q2][j0 + 1];
                fma2(JA2[q2], pA0, wp0);
                fma2(JA2[q2], pA1, wp1);
                fma2(JB2[q2], pB0, wp0);
                fma2(JB2[q2], pB1, wp1);
            }
        }
    }

    // ---------------- reduce across tg lanes and store ----------------
    float JA[8], JB[8];
    #pragma unroll
    for (int q2 = 0; q2 < 4; q2++) {
        upk2(JA2[q2], JA[2 * q2], JA[2 * q2 + 1]);
        upk2(JB2[q2], JB[2 * q2], JB[2 * q2 + 1]);
    }
    #pragma unroll
    for (int o = 1; o <= 2; o <<= 1) {
        #pragma unroll
        for (int q = 0; q < 8; q++) {
            JA[q] += __shfl_xor_sync(0xffffffffu, JA[q], o);
            JB[q] += __shfl_xor_sync(0xffffffffu, JB[q], o);
        }
    }
    if (tg == 0 && g < 6) {
        const size_t N = (size_t)ncell;
        float* outDY = out + 6 * N;
        float* outDE = out + 42 * N;
        float* outDT = out + 48 * N;
        int nA = n0 + cellA, nB = n0 + cellB;
        #pragma unroll
        for (int q = 0; q < 6; q++) {
            outDY[(size_t)nA * 36 + g * 6 + q] = JA[q];
            outDY[(size_t)nB * 36 + g * 6 + q] = JB[q];
        }
        outDE[(size_t)nA * 6 + g] = JA[6];
        outDT[(size_t)nA * 6 + g] = JA[7];
        outDE[(size_t)nB * 6 + g] = JB[6];
        outDT[(size_t)nB * 6 + g] = JB[7];
    }
}

extern "C" void kernel_launch(void* const* d_in, const int* in_sizes, int n_in,
                              void* d_out, int out_size) {
    // metadata order: t, y, erate, T, w1, w2, w3, b1, b2, b3
    const float* y  = (const float*)d_in[1];
    const float* er = (const float*)d_in[2];
    const float* Tg = (const float*)d_in[3];
    const float* w1 = (const float*)d_in[4];
    const float* w2 = (const float*)d_in[5];
    const float* w3 = (const float*)d_in[6];
    const float* b1 = (const float*)d_in[7];
    const float* b2 = (const float*)d_in[8];
    const float* b3 = (const float*)d_in[9];
    float* out = (float*)d_out;
    int ncell = in_sizes[2];             // NT*NB = 65536

    cudaFuncSetAttribute(k_fwd, cudaFuncAttributeMaxDynamicSharedMemorySize,
                         (int)sizeof(SmemA));
    cudaFuncSetAttribute(k_jacM, cudaFuncAttributeMaxDynamicSharedMemorySize,
                         (int)sizeof(SmemJ));

    k_prep<<<128, 256>>>(w2);
    k_fwd<<<ncell / G, NTA, sizeof(SmemA)>>>(y, er, Tg, w1, w3, b1, b2, b3,
                                             out, ncell);
    k_jacM<<<ncell / CPB, 256, sizeof(SmemJ)>>>(w1, w3, out, ncell);
}

// round 11
// speedup vs baseline: 1.4758x; 1.1221x over previous
#include <cuda_runtime.h>
#include <cuda_bf16.h>
#include <cstdint>

#define H        256
#define NS       6
#define G        32      // cells per forward block
#define NTA      256
#define CPB      32      // cells per jacobian CTA (M = 192 rows dense)

typedef unsigned long long u64;
typedef unsigned int u32;

// ---------------- device scratch (allocations are forbidden) ----------------
__device__ float         g_w2T[H * H];        // for k_fwd
__device__ u32           g_wB[2 * 256 * 128]; // bf16 pairs: [split][n][pos] (pair-permuted)
__device__ unsigned char g_m2cb[65536 * 32];  // m2 nibble bytes per cell
__device__ u32           g_m1w[65536 * 8];    // m1 ballot words per cell

// ---------------- helpers ----------------
__device__ __forceinline__ u64 pk2(float lo, float hi) {
    u64 r; asm("mov.b64 %0, {%1, %2};" : "=l"(r) : "f"(lo), "f"(hi)); return r;
}
__device__ __forceinline__ void upk2(u64 v, float& lo, float& hi) {
    asm("mov.b64 {%0, %1}, %2;" : "=f"(lo), "=f"(hi) : "l"(v));
}
__device__ __forceinline__ void fma2(u64& d, u64 a, u64 b) {
    asm("fma.rn.f32x2 %0, %1, %2, %0;" : "+l"(d) : "l"(a), "l"(b));
}
__device__ __forceinline__ u32 pack8(u64 x) {
    x |= x >> 4;  x &= 0x00FF00FF00FF00FFull;
    x |= x >> 8;  x &= 0x0000FFFF0000FFFFull;
    x |= x >> 16;
    return (u32)x;
}
__device__ __forceinline__ unsigned short bfs(float v, int s) {
    __nv_bfloat16 h0 = __float2bfloat16(v);
    if (s == 0) return __bfloat16_as_ushort(h0);
    float r = v - __bfloat162float(h0);
    return __bfloat16_as_ushort(__float2bfloat16(r));
}
__device__ __forceinline__ void mma16816(float* d, const u32* a, u32 b0, u32 b1) {
    asm volatile(
        "mma.sync.aligned.m16n8k16.row.col.f32.bf16.bf16.f32 "
        "{%0,%1,%2,%3}, {%4,%5,%6,%7}, {%8,%9}, {%0,%1,%2,%3};"
        : "+f"(d[0]), "+f"(d[1]), "+f"(d[2]), "+f"(d[3])
        : "r"(a[0]), "r"(a[1]), "r"(a[2]), "r"(a[3]), "r"(b0), "r"(b1));
}
__device__ __forceinline__ u32 mask2(u32 bits) {
    return ((bits & 1u) ? 0x0000FFFFu : 0u) | ((bits & 2u) ? 0xFFFF0000u : 0u);
}

// ======================= prep A: transpose w2 ==============================
__global__ void k_prepT(const float* __restrict__ w2) {
    __shared__ float t[32][33];
    int bid = blockIdx.x, tid = threadIdx.x;
    int j0 = (bid & 7) * 32, h0 = (bid >> 3) * 32;
    int tx = tid & 31, ty = tid >> 5;
    #pragma unroll
    for (int r = 0; r < 32; r += 8)
        t[ty + r][tx] = w2[(h0 + ty + r) * H + j0 + tx];
    __syncthreads();
    #pragma unroll
    for (int r = 0; r < 32; r += 8)
        g_w2T[(j0 + ty + r) * H + h0 + tx] = t[tx][ty + r];
}

// ======================= prep B: bf16 W pairs, pair-permuted ===============
// g_wB[(s*256+n)*128 + pos]; pos within 8-group: (0,4),(1,5),(2,6),(3,7)
// so a u64 read of (pos 2w, 2w+1) yields pairs (kp=w, kp=w+4).
__global__ void k_prepW(const float* __restrict__ w2) {
    int base = blockIdx.x * 1024 + threadIdx.x * 4;
    #pragma unroll
    for (int e4 = 0; e4 < 4; e4++) {
        int idx = base + e4;
        int s = idx >> 15;
        int rem = idx & 32767;
        int n = rem >> 7, pos = rem & 127;
        int group = pos >> 3, within = pos & 7;
        int w8 = (within >> 1) + 4 * (within & 1);
        int kp = group * 8 + w8;
        float va = w2[(size_t)(2 * kp) * H + n];
        float vb = w2[(size_t)(2 * kp + 1) * H + n];
        g_wB[idx] = (u32)bfs(va, s) | ((u32)bfs(vb, s) << 16);
    }
}

// ======================= kernel A: forward (unchanged, passing) =============
struct SmemA {
    u64    v1s[H][34];
    float4 w3f4[NS][64];
    float  xs[G][8];
};

__global__ void __launch_bounds__(NTA, 2)
k_fwd(const float* __restrict__ y,  const float* __restrict__ er,
      const float* __restrict__ Tg, const float* __restrict__ w1,
      const float* __restrict__ w3, const float* __restrict__ b1,
      const float* __restrict__ b2, const float* __restrict__ b3,
      float* __restrict__ out, int ncell)
{
    extern __shared__ char raw[];
    SmemA* s = reinterpret_cast<SmemA*>(raw);

    const int tid  = threadIdx.x;
    const int lane = tid & 31;
    const int wid  = tid >> 5;
    const int n0   = blockIdx.x * G;

    float w1r[8];
    #pragma unroll
    for (int q = 0; q < 8; q++) w1r[q] = w1[tid * 8 + q];
    #pragma unroll
    for (int idx = tid; idx < NS * 64; idx += NTA) {
        int i = idx >> 6, l = idx & 63;
        s->w3f4[i][l] = *reinterpret_cast<const float4*>(&w3[i * H + 4 * l]);
    }
    {
        int c = tid >> 3, q = tid & 7, n = n0 + c;
        float xv = (q < 6) ? y[n * 6 + q] : (q == 6 ? er[n] : Tg[n]);
        s->xs[c][q] = xv;
    }
    __syncthreads();

    {
        float b1v = b1[tid];
        #pragma unroll 4
        for (int c = 0; c < G; c++) {
            float z = b1v;
            #pragma unroll
            for (int q = 0; q < 8; q++) z = fmaf(w1r[q], s->xs[c][q], z);
            float v = fmaxf(z, 0.0f);
            s->v1s[tid][c] = pk2(v, v);
            unsigned bal = __ballot_sync(0xffffffffu, z > 0.0f);
            if (lane == 0) g_m1w[(size_t)(n0 + c) * 8 + wid] = bal;
        }
    }
    __syncthreads();

    const int c0 = wid * 4;
    {
        u64 acc2[4][4];
        #pragma unroll
        for (int r2 = 0; r2 < 4; r2++)
            #pragma unroll
            for (int cc = 0; cc < 4; cc++) acc2[r2][cc] = 0ull;

        #pragma unroll 2
        for (int j = 0; j < H; j++) {
            const float* wrow = g_w2T + j * H + 4 * lane;
            ulonglong2 wa = *reinterpret_cast<const ulonglong2*>(wrow);
            ulonglong2 wb = *reinterpret_cast<const ulonglong2*>(wrow + 128);
            u64 wv[4] = {wa.x, wa.y, wb.x, wb.y};
            ulonglong2 va = *reinterpret_cast<const ulonglong2*>(&s->v1s[j][c0]);
            ulonglong2 vb = *reinterpret_cast<const ulonglong2*>(&s->v1s[j][c0 + 2]);
            u64 vs[4] = {va.x, va.y, vb.x, vb.y};
            #pragma unroll
            for (int r2 = 0; r2 < 4; r2++)
                #pragma unroll
                for (int cc = 0; cc < 4; cc++)
                    fma2(acc2[r2][cc], wv[r2], vs[cc]);
        }

        float4 b2lo = *reinterpret_cast<const float4*>(b2 + 4 * lane);
        float4 b2hi = *reinterpret_cast<const float4*>(b2 + 128 + 4 * lane);
        float b2a[8] = {b2lo.x, b2lo.y, b2lo.z, b2lo.w,
                        b2hi.x, b2hi.y, b2hi.z, b2hi.w};
        unsigned mbyte[4] = {0u, 0u, 0u, 0u};
        float v2r[8][4];
        #pragma unroll
        for (int r2 = 0; r2 < 4; r2++)
            #pragma unroll
            for (int cc = 0; cc < 4; cc++) {
                float lo, hi; upk2(acc2[r2][cc], lo, hi);
                float z0 = lo + b2a[2 * r2];
                float z1 = hi + b2a[2 * r2 + 1];
                v2r[2 * r2][cc]     = fmaxf(z0, 0.0f);
                v2r[2 * r2 + 1][cc] = fmaxf(z1, 0.0f);
                if (z0 > 0.0f) mbyte[cc] |= (1u << (2 * r2));
                if (z1 > 0.0f) mbyte[cc] |= (1u << (2 * r2 + 1));
            }
        #pragma unroll
        for (int cc = 0; cc < 4; cc++)
            g_m2cb[(size_t)(n0 + c0 + cc) * 32 + lane] = (unsigned char)mbyte[cc];

        float yp[NS][4];
        #pragma unroll
        for (int i = 0; i < NS; i++) {
            float4 wa = s->w3f4[i][lane];
            float4 wb = s->w3f4[i][32 + lane];
            float w3r[8] = {wa.x, wa.y, wa.z, wa.w, wb.x, wb.y, wb.z, wb.w};
            float a0 = 0.f, a1 = 0.f, a2 = 0.f, a3 = 0.f;
            #pragma unroll
            for (int r = 0; r < 8; r++) {
                a0 = fmaf(w3r[r], v2r[r][0], a0);
                a1 = fmaf(w3r[r], v2r[r][1], a1);
                a2 = fmaf(w3r[r], v2r[r][2], a2);
                a3 = fmaf(w3r[r], v2r[r][3], a3);
            }
            yp[i][0] = a0; yp[i][1] = a1; yp[i][2] = a2; yp[i][3] = a3;
        }

        #pragma unroll
        for (int i = 0; i < NS; i++)
            #pragma unroll
            for (int cc = 0; cc < 4; cc++) {
                float v = yp[i][cc];
                #pragma unroll
                for (int o = 16; o > 0; o >>= 1)
                    v += __shfl_xor_sync(0xffffffffu, v, o);
                yp[i][cc] = v;
            }
        if (lane == 0) {
            #pragma unroll
            for (int i = 0; i < NS; i++) {
                float b3v = b3[i];
                #pragma unroll
                for (int cc = 0; cc < 4; cc++)
                    out[(size_t)(n0 + c0 + cc) * NS + i] = yp[i][cc] + b3v;
            }
        }
    }
}

// ======================= kernel B: mma.sync Jacobian (M=192 dense) ==========
// 32 cells/CTA, M = 192 rows (cell = row/6, ii = row%6; no pad rows).
// 384 threads = 12 warps; warp = M-tile mt (rows 16mt..16mt+15); np loop inside.
struct SmemJ2 {
    u32 W[2][128][36];      // [split][n-local(np half)][permuted kp-local 32 + pad]
    u64 w1p[4][256];        // w1 pairs per j
    u32 w3p[2][6][132];     // bf16 pair (w3s[i][2p], w3s[i][2p+1]), pad 132
    u32 m2[CPB][8];         // m2 bit-words per cell
};

__global__ void __launch_bounds__(384, 1)
k_jacM(const float* __restrict__ w1, const float* __restrict__ w3,
       float* __restrict__ out, int ncell)
{
    extern __shared__ char raw[];
    SmemJ2* s = reinterpret_cast<SmemJ2*>(raw);

    const int tid  = threadIdx.x;
    const int lane = tid & 31;
    const int wid  = tid >> 5;      // 0..11 = M-tile
    const int g    = lane >> 2;     // 0..7
    const int tg   = lane & 3;
    const int n0   = blockIdx.x * CPB;

    const int r1 = wid * 16 + g, r2 = r1 + 8;
    const int cellA = r1 / 6, iiA = r1 - 6 * cellA;
    const int cellB = r2 / 6, iiB = r2 - 6 * cellB;

    // ---------------- stage tables ----------------
    if (tid < 256) {
        int j = tid;
        const float* wr = w1 + (size_t)j * 8;
        float4 a = *reinterpret_cast<const float4*>(wr);
        float4 b = *reinterpret_cast<const float4*>(wr + 4);
        s->w1p[0][j] = pk2(a.x, a.y);
        s->w1p[1][j] = pk2(a.z, a.w);
        s->w1p[2][j] = pk2(b.x, b.y);
        s->w1p[3][j] = pk2(b.z, b.w);
    }
    for (int idx = tid; idx < 2 * 6 * 128; idx += 384) {
        int sp = idx / 768;
        int r = idx - sp * 768;
        int ii = r >> 7, p = r & 127;
        float va = w3[ii * H + 2 * p], vb = w3[ii * H + 2 * p + 1];
        s->w3p[sp][ii][p] = (u32)bfs(va, sp) | ((u32)bfs(vb, sp) << 16);
    }
    if (tid < CPB) {
        const u64* mp = (const u64*)(g_m2cb + (size_t)(n0 + tid) * 32);
        #pragma unroll
        for (int d = 0; d < 4; d++) {
            u64 ch = mp[d];
            s->m2[tid][d]     = pack8(ch & 0x0F0F0F0F0F0F0F0Full);
            s->m2[tid][4 + d] = pack8((ch >> 4) & 0x0F0F0F0F0F0F0F0Full);
        }
    }
    __syncthreads();

    // hoist m1 masks (per-lane cells)
    u32 mA[8], mB[8];
    {
        const uint4* pa = (const uint4*)(g_m1w + (size_t)(n0 + cellA) * 8);
        uint4 x = pa[0], z = pa[1];
        mA[0] = x.x; mA[1] = x.y; mA[2] = x.z; mA[3] = x.w;
        mA[4] = z.x; mA[5] = z.y; mA[6] = z.z; mA[7] = z.w;
        const uint4* pb = (const uint4*)(g_m1w + (size_t)(n0 + cellB) * 8);
        uint4 x2 = pb[0], z2 = pb[1];
        mB[0] = x2.x; mB[1] = x2.y; mB[2] = x2.z; mB[3] = x2.w;
        mB[4] = z2.x; mB[5] = z2.y; mB[6] = z2.z; mB[7] = z2.w;
    }

    u64 JA2[4] = {0ull, 0ull, 0ull, 0ull};
    u64 JB2[4] = {0ull, 0ull, 0ull, 0ull};

    #pragma unroll 1
    for (int np = 0; np < 2; np++) {
        float d[16][4];
        #pragma unroll
        for (int t = 0; t < 16; t++)
            #pragma unroll
            for (int c = 0; c < 4; c++) d[t][c] = 0.0f;

        #pragma unroll 1
        for (int kc = 0; kc < 4; kc++) {
            __syncthreads();
            // copy W chunk: 2 splits x 128 n x 32 words = 2048 uint4
            for (int i = tid; i < 2048; i += 384) {
                int sp = i >> 10;
                int rem = i & 1023;
                int nl = rem >> 3, q = rem & 7;
                const uint4* src = (const uint4*)(g_wB +
                    ((size_t)(sp * 256 + np * 128 + nl) * 128 + kc * 32 + q * 4));
                *reinterpret_cast<uint4*>(&s->W[sp][nl][q * 4]) = *src;
            }
            __syncthreads();

            #pragma unroll 1
            for (int kss = 0; kss < 4; kss++) {
                int ksg = kc * 4 + kss;        // global k-step (16 wide)
                int p0g = ksg * 8 + tg;        // global k-pair index
                u32 wmA = s->m2[cellA][ksg >> 1];
                u32 wmB = s->m2[cellB][ksg >> 1];
                int sh0 = ((ksg & 1) << 4) + tg * 2;
                u32 mkA0 = mask2((wmA >> sh0) & 3u);
                u32 mkB0 = mask2((wmB >> sh0) & 3u);
                u32 mkA1 = mask2((wmA >> (sh0 + 8)) & 3u);
                u32 mkB1 = mask2((wmB >> (sh0 + 8)) & 3u);

                u32 a0[4], a1[4];
                a0[0] = s->w3p[0][iiA][p0g]     & mkA0;
                a0[1] = s->w3p[0][iiB][p0g]     & mkB0;
                a0[2] = s->w3p[0][iiA][p0g + 4] & mkA1;
                a0[3] = s->w3p[0][iiB][p0g + 4] & mkB1;
                a1[0] = s->w3p[1][iiA][p0g]     & mkA0;
                a1[1] = s->w3p[1][iiB][p0g]     & mkB0;
                a1[2] = s->w3p[1][iiA][p0g + 4] & mkA1;
                a1[3] = s->w3p[1][iiB][p0g + 4] & mkB1;

                #pragma unroll
                for (int t = 0; t < 16; t++) {
                    int nl = t * 8 + g;
                    u64 B0 = *reinterpret_cast<const u64*>(&s->W[0][nl][kss * 8 + 2 * tg]);
                    u64 B1 = *reinterpret_cast<const u64*>(&s->W[1][nl][kss * 8 + 2 * tg]);
                    u32 b00 = (u32)B0, b01 = (u32)(B0 >> 32);
                    u32 b10 = (u32)B1, b11 = (u32)(B1 >> 32);
                    mma16816(d[t], a0, b00, b01);   // E0*W0
                    mma16816(d[t], a1, b00, b01);   // E1*W0
                    mma16816(d[t], a0, b10, b11);   // E0*W1
                }
            }
        }

        // ---------------- fold this np half into J ----------------
        #pragma unroll
        for (int t = 0; t < 16; t++) {
            int widx = np * 4 + (t >> 2);
            int sh = ((t & 3) * 8) + tg * 2;
            u32 wa = mA[widx] >> sh;
            u32 wb = mB[widx] >> sh;
            int j0 = np * 128 + t * 8 + tg * 2;

            float vA0 = (wa & 1u) ? d[t][0] : 0.0f;
            float vA1 = (wa & 2u) ? d[t][1] : 0.0f;
            float vB0 = (wb & 1u) ? d[t][2] : 0.0f;
            float vB1 = (wb & 2u) ? d[t][3] : 0.0f;
            u64 pA0 = pk2(vA0, vA0), pA1 = pk2(vA1, vA1);
            u64 pB0 = pk2(vB0, vB0), pB1 = pk2(vB1, vB1);
            #pragma unroll
            for (int q2 = 0; q2 < 4; q2++) {
                u64 wp0 = s->w1p[q2][j0];
                u64 wp1 = s->w1p[q2][j0 + 1];
                fma2(JA2[q2], pA0, wp0);
                fma2(JA2[q2], pA1, wp1);
                fma2(JB2[q2], pB0, wp0);
                fma2(JB2[q2], pB1, wp1);
            }
        }
    }

    // ---------------- reduce across tg lanes and store ----------------
    float JA[8], JB[8];
    #pragma unroll
    for (int q2 = 0; q2 < 4; q2++) {
        upk2(JA2[q2], JA[2 * q2], JA[2 * q2 + 1]);
        upk2(JB2[q2], JB[2 * q2], JB[2 * q2 + 1]);
    }
    #pragma unroll
    for (int o = 1; o <= 2; o <<= 1) {
        #pragma unroll
        for (int q = 0; q < 8; q++) {
            JA[q] += __shfl_xor_sync(0xffffffffu, JA[q], o);
            JB[q] += __shfl_xor_sync(0xffffffffu, JB[q], o);
        }
    }
    if (tg == 0) {
        const size_t N = (size_t)ncell;
        float* outDY = out + 6 * N;
        float* outDE = out + 42 * N;
        float* outDT = out + 48 * N;
        int nA = n0 + cellA, nB = n0 + cellB;
        #pragma unroll
        for (int q = 0; q < 6; q++) {
            outDY[(size_t)nA * 36 + iiA * 6 + q] = JA[q];
            outDY[(size_t)nB * 36 + iiB * 6 + q] = JB[q];
        }
        outDE[(size_t)nA * 6 + iiA] = JA[6];
        outDT[(size_t)nA * 6 + iiA] = JA[7];
        outDE[(size_t)nB * 6 + iiB] = JB[6];
        outDT[(size_t)nB * 6 + iiB] = JB[7];
    }
}

extern "C" void kernel_launch(void* const* d_in, const int* in_sizes, int n_in,
                              void* d_out, int out_size) {
    // metadata order: t, y, erate, T, w1, w2, w3, b1, b2, b3
    const float* y  = (const float*)d_in[1];
    const float* er = (const float*)d_in[2];
    const float* Tg = (const float*)d_in[3];
    const float* w1 = (const float*)d_in[4];
    const float* w2 = (const float*)d_in[5];
    const float* w3 = (const float*)d_in[6];
    const float* b1 = (const float*)d_in[7];
    const float* b2 = (const float*)d_in[8];
    const float* b3 = (const float*)d_in[9];
    float* out = (float*)d_out;
    int ncell = in_sizes[2];             // NT*NB = 65536

    cudaFuncSetAttribute(k_fwd, cudaFuncAttributeMaxDynamicSharedMemorySize,
                         (int)sizeof(SmemA));
    cudaFuncSetAttribute(k_jacM, cudaFuncAttributeMaxDynamicSharedMemorySize,
                         (int)sizeof(SmemJ2));

    k_prepT<<<64, 256>>>(w2);
    k_prepW<<<64, 256>>>(w2);
    k_fwd<<<ncell / G, NTA, sizeof(SmemA)>>>(y, er, Tg, w1, w3, b1, b2, b3,
                                             out, ncell);
    k_jacM<<<ncell / CPB, 384, sizeof(SmemJ2)>>>(w1, w3, out, ncell);
}

// round 13
// speedup vs baseline: 1.6737x; 1.1341x over previous
#include <cuda_runtime.h>
#include <cuda_bf16.h>
#include <cstdint>

#define H        256
#define NS       6
#define G        32      // cells per forward block
#define NTA      256
#define CPB      32      // cells per jacobian CTA (M = 192 rows dense)

typedef unsigned long long u64;
typedef unsigned int u32;

// ---------------- device scratch (allocations are forbidden) ----------------
__device__ float         g_w2T[H * H];        // for k_fwd
__device__ u32           g_wB[2 * 256 * 128]; // bf16 pairs: [split][n][pos] (pair-permuted)
__device__ unsigned char g_m2cb[65536 * 32];  // m2 nibble bytes per cell
__device__ u32           g_m1w[65536 * 8];    // m1 ballot words per cell

// ---------------- helpers ----------------
__device__ __forceinline__ u64 pk2(float lo, float hi) {
    u64 r; asm("mov.b64 %0, {%1, %2};" : "=l"(r) : "f"(lo), "f"(hi)); return r;
}
__device__ __forceinline__ void upk2(u64 v, float& lo, float& hi) {
    asm("mov.b64 {%0, %1}, %2;" : "=f"(lo), "=f"(hi) : "l"(v));
}
__device__ __forceinline__ void fma2(u64& d, u64 a, u64 b) {
    asm("fma.rn.f32x2 %0, %1, %2, %0;" : "+l"(d) : "l"(a), "l"(b));
}
__device__ __forceinline__ u32 pack8(u64 x) {
    x |= x >> 4;  x &= 0x00FF00FF00FF00FFull;
    x |= x >> 8;  x &= 0x0000FFFF0000FFFFull;
    x |= x >> 16;
    return (u32)x;
}
__device__ __forceinline__ unsigned short bfs(float v, int s) {
    __nv_bfloat16 h0 = __float2bfloat16(v);
    if (s == 0) return __bfloat16_as_ushort(h0);
    float r = v - __bfloat162float(h0);
    return __bfloat16_as_ushort(__float2bfloat16(r));
}
__device__ __forceinline__ void mma16816(float* d, const u32* a, u32 b0, u32 b1) {
    asm volatile(
        "mma.sync.aligned.m16n8k16.row.col.f32.bf16.bf16.f32 "
        "{%0,%1,%2,%3}, {%4,%5,%6,%7}, {%8,%9}, {%0,%1,%2,%3};"
        : "+f"(d[0]), "+f"(d[1]), "+f"(d[2]), "+f"(d[3])
        : "r"(a[0]), "r"(a[1]), "r"(a[2]), "r"(a[3]), "r"(b0), "r"(b1));
}
__device__ __forceinline__ u32 mask2(u32 bits) {
    return ((bits & 1u) ? 0x0000FFFFu : 0u) | ((bits & 2u) ? 0xFFFF0000u : 0u);
}

// ======================= prep A: transpose w2 ==============================
__global__ void k_prepT(const float* __restrict__ w2) {
    __shared__ float t[32][33];
    int bid = blockIdx.x, tid = threadIdx.x;
    int j0 = (bid & 7) * 32, h0 = (bid >> 3) * 32;
    int tx = tid & 31, ty = tid >> 5;
    #pragma unroll
    for (int r = 0; r < 32; r += 8)
        t[ty + r][tx] = w2[(h0 + ty + r) * H + j0 + tx];
    __syncthreads();
    #pragma unroll
    for (int r = 0; r < 32; r += 8)
        g_w2T[(j0 + ty + r) * H + h0 + tx] = t[tx][ty + r];
}

// ======================= prep B: bf16 W pairs, pair-permuted ===============
// g_wB[(s*256+n)*128 + pos]; pos within 8-group: (0,4),(1,5),(2,6),(3,7)
// so a u64 read of (pos 2w, 2w+1) yields pairs (kp=w, kp=w+4).
__global__ void k_prepW(const float* __restrict__ w2) {
    int base = blockIdx.x * 1024 + threadIdx.x * 4;
    #pragma unroll
    for (int e4 = 0; e4 < 4; e4++) {
        int idx = base + e4;
        int s = idx >> 15;
        int rem = idx & 32767;
        int n = rem >> 7, pos = rem & 127;
        int group = pos >> 3, within = pos & 7;
        int w8 = (within >> 1) + 4 * (within & 1);
        int kp = group * 8 + w8;
        float va = w2[(size_t)(2 * kp) * H + n];
        float vb = w2[(size_t)(2 * kp + 1) * H + n];
        g_wB[idx] = (u32)bfs(va, s) | ((u32)bfs(vb, s) << 16);
    }
}

// ======================= kernel A: forward (unchanged, passing) =============
struct SmemA {
    u64    v1s[H][34];
    float4 w3f4[NS][64];
    float  xs[G][8];
};

__global__ void __launch_bounds__(NTA, 2)
k_fwd(const float* __restrict__ y,  const float* __restrict__ er,
      const float* __restrict__ Tg, const float* __restrict__ w1,
      const float* __restrict__ w3, const float* __restrict__ b1,
      const float* __restrict__ b2, const float* __restrict__ b3,
      float* __restrict__ out, int ncell)
{
    extern __shared__ char raw[];
    SmemA* s = reinterpret_cast<SmemA*>(raw);

    const int tid  = threadIdx.x;
    const int lane = tid & 31;
    const int wid  = tid >> 5;
    const int n0   = blockIdx.x * G;

    float w1r[8];
    #pragma unroll
    for (int q = 0; q < 8; q++) w1r[q] = w1[tid * 8 + q];
    #pragma unroll
    for (int idx = tid; idx < NS * 64; idx += NTA) {
        int i = idx >> 6, l = idx & 63;
        s->w3f4[i][l] = *reinterpret_cast<const float4*>(&w3[i * H + 4 * l]);
    }
    {
        int c = tid >> 3, q = tid & 7, n = n0 + c;
        float xv = (q < 6) ? y[n * 6 + q] : (q == 6 ? er[n] : Tg[n]);
        s->xs[c][q] = xv;
    }
    __syncthreads();

    {
        float b1v = b1[tid];
        #pragma unroll 4
        for (int c = 0; c < G; c++) {
            float z = b1v;
            #pragma unroll
            for (int q = 0; q < 8; q++) z = fmaf(w1r[q], s->xs[c][q], z);
            float v = fmaxf(z, 0.0f);
            s->v1s[tid][c] = pk2(v, v);
            unsigned bal = __ballot_sync(0xffffffffu, z > 0.0f);
            if (lane == 0) g_m1w[(size_t)(n0 + c) * 8 + wid] = bal;
        }
    }
    __syncthreads();

    const int c0 = wid * 4;
    {
        u64 acc2[4][4];
        #pragma unroll
        for (int r2 = 0; r2 < 4; r2++)
            #pragma unroll
            for (int cc = 0; cc < 4; cc++) acc2[r2][cc] = 0ull;

        #pragma unroll 2
        for (int j = 0; j < H; j++) {
            const float* wrow = g_w2T + j * H + 4 * lane;
            ulonglong2 wa = *reinterpret_cast<const ulonglong2*>(wrow);
            ulonglong2 wb = *reinterpret_cast<const ulonglong2*>(wrow + 128);
            u64 wv[4] = {wa.x, wa.y, wb.x, wb.y};
            ulonglong2 va = *reinterpret_cast<const ulonglong2*>(&s->v1s[j][c0]);
            ulonglong2 vb = *reinterpret_cast<const ulonglong2*>(&s->v1s[j][c0 + 2]);
            u64 vs[4] = {va.x, va.y, vb.x, vb.y};
            #pragma unroll
            for (int r2 = 0; r2 < 4; r2++)
                #pragma unroll
                for (int cc = 0; cc < 4; cc++)
                    fma2(acc2[r2][cc], wv[r2], vs[cc]);
        }

        float4 b2lo = *reinterpret_cast<const float4*>(b2 + 4 * lane);
        float4 b2hi = *reinterpret_cast<const float4*>(b2 + 128 + 4 * lane);
        float b2a[8] = {b2lo.x, b2lo.y, b2lo.z, b2lo.w,
                        b2hi.x, b2hi.y, b2hi.z, b2hi.w};
        unsigned mbyte[4] = {0u, 0u, 0u, 0u};
        float v2r[8][4];
        #pragma unroll
        for (int r2 = 0; r2 < 4; r2++)
            #pragma unroll
            for (int cc = 0; cc < 4; cc++) {
                float lo, hi; upk2(acc2[r2][cc], lo, hi);
                float z0 = lo + b2a[2 * r2];
                float z1 = hi + b2a[2 * r2 + 1];
                v2r[2 * r2][cc]     = fmaxf(z0, 0.0f);
                v2r[2 * r2 + 1][cc] = fmaxf(z1, 0.0f);
                if (z0 > 0.0f) mbyte[cc] |= (1u << (2 * r2));
                if (z1 > 0.0f) mbyte[cc] |= (1u << (2 * r2 + 1));
            }
        #pragma unroll
        for (int cc = 0; cc < 4; cc++)
            g_m2cb[(size_t)(n0 + c0 + cc) * 32 + lane] = (unsigned char)mbyte[cc];

        float yp[NS][4];
        #pragma unroll
        for (int i = 0; i < NS; i++) {
            float4 wa = s->w3f4[i][lane];
            float4 wb = s->w3f4[i][32 + lane];
            float w3r[8] = {wa.x, wa.y, wa.z, wa.w, wb.x, wb.y, wb.z, wb.w};
            float a0 = 0.f, a1 = 0.f, a2 = 0.f, a3 = 0.f;
            #pragma unroll
            for (int r = 0; r < 8; r++) {
                a0 = fmaf(w3r[r], v2r[r][0], a0);
                a1 = fmaf(w3r[r], v2r[r][1], a1);
                a2 = fmaf(w3r[r], v2r[r][2], a2);
                a3 = fmaf(w3r[r], v2r[r][3], a3);
            }
            yp[i][0] = a0; yp[i][1] = a1; yp[i][2] = a2; yp[i][3] = a3;
        }

        #pragma unroll
        for (int i = 0; i < NS; i++)
            #pragma unroll
            for (int cc = 0; cc < 4; cc++) {
                float v = yp[i][cc];
                #pragma unroll
                for (int o = 16; o > 0; o >>= 1)
                    v += __shfl_xor_sync(0xffffffffu, v, o);
                yp[i][cc] = v;
            }
        if (lane == 0) {
            #pragma unroll
            for (int i = 0; i < NS; i++) {
                float b3v = b3[i];
                #pragma unroll
                for (int cc = 0; cc < 4; cc++)
                    out[(size_t)(n0 + c0 + cc) * NS + i] = yp[i][cc] + b3v;
            }
        }
    }
}

// ======================= kernel B: mma.sync Jacobian (M=192 dense) ==========
// 32 cells/CTA, M = 192 rows (cell = row/6, ii = row%6; no pad rows).
// 384 threads = 12 warps; warp = M-tile mt (rows 16mt..16mt+15); np loop inside.
// W row stride 40 words (== 8 mod 32): B-load bank = 8g+2tg -> conflict-free.
struct SmemJ2 {
    u32 W[2][128][40];      // [split][n-local(np half)][permuted kp-local 32 + pad 8]
    u64 w1p[4][256];        // w1 pairs per j
    u32 w3p[2][6][132];     // bf16 pair (w3s[i][2p], w3s[i][2p+1]), pad 132
    u32 m2[CPB][8];         // m2 bit-words per cell
};

__global__ void __launch_bounds__(384, 1)
k_jacM(const float* __restrict__ w1, const float* __restrict__ w3,
       float* __restrict__ out, int ncell)
{
    extern __shared__ char raw[];
    SmemJ2* s = reinterpret_cast<SmemJ2*>(raw);

    const int tid  = threadIdx.x;
    const int lane = tid & 31;
    const int wid  = tid >> 5;      // 0..11 = M-tile
    const int g    = lane >> 2;     // 0..7
    const int tg   = lane & 3;
    const int n0   = blockIdx.x * CPB;

    const int r1 = wid * 16 + g, r2 = r1 + 8;
    const int cellA = r1 / 6, iiA = r1 - 6 * cellA;
    const int cellB = r2 / 6, iiB = r2 - 6 * cellB;

    // ---------------- stage tables ----------------
    if (tid < 256) {
        int j = tid;
        const float* wr = w1 + (size_t)j * 8;
        float4 a = *reinterpret_cast<const float4*>(wr);
        float4 b = *reinterpret_cast<const float4*>(wr + 4);
        s->w1p[0][j] = pk2(a.x, a.y);
        s->w1p[1][j] = pk2(a.z, a.w);
        s->w1p[2][j] = pk2(b.x, b.y);
        s->w1p[3][j] = pk2(b.z, b.w);
    }
    for (int idx = tid; idx < 2 * 6 * 128; idx += 384) {
        int sp = idx / 768;
        int r = idx - sp * 768;
        int ii = r >> 7, p = r & 127;
        float va = w3[ii * H + 2 * p], vb = w3[ii * H + 2 * p + 1];
        s->w3p[sp][ii][p] = (u32)bfs(va, sp) | ((u32)bfs(vb, sp) << 16);
    }
    if (tid < CPB) {
        const u64* mp = (const u64*)(g_m2cb + (size_t)(n0 + tid) * 32);
        #pragma unroll
        for (int d = 0; d < 4; d++) {
            u64 ch = mp[d];
            s->m2[tid][d]     = pack8(ch & 0x0F0F0F0F0F0F0F0Full);
            s->m2[tid][4 + d] = pack8((ch >> 4) & 0x0F0F0F0F0F0F0F0Full);
        }
    }
    __syncthreads();

    // hoist m1 masks (per-lane cells)
    u32 mA[8], mB[8];
    {
        const uint4* pa = (const uint4*)(g_m1w + (size_t)(n0 + cellA) * 8);
        uint4 x = pa[0], z = pa[1];
        mA[0] = x.x; mA[1] = x.y; mA[2] = x.z; mA[3] = x.w;
        mA[4] = z.x; mA[5] = z.y; mA[6] = z.z; mA[7] = z.w;
        const uint4* pb = (const uint4*)(g_m1w + (size_t)(n0 + cellB) * 8);
        uint4 x2 = pb[0], z2 = pb[1];
        mB[0] = x2.x; mB[1] = x2.y; mB[2] = x2.z; mB[3] = x2.w;
        mB[4] = z2.x; mB[5] = z2.y; mB[6] = z2.z; mB[7] = z2.w;
    }

    u64 JA2[4] = {0ull, 0ull, 0ull, 0ull};
    u64 JB2[4] = {0ull, 0ull, 0ull, 0ull};

    #pragma unroll 1
    for (int np = 0; np < 2; np++) {
        float d[16][4];
        #pragma unroll
        for (int t = 0; t < 16; t++)
            #pragma unroll
            for (int c = 0; c < 4; c++) d[t][c] = 0.0f;

        #pragma unroll 1
        for (int kc = 0; kc < 4; kc++) {
            __syncthreads();
            // copy W chunk: 2 splits x 128 n x 32 words = 2048 uint4
            for (int i = tid; i < 2048; i += 384) {
                int sp = i >> 10;
                int rem = i & 1023;
                int nl = rem >> 3, q = rem & 7;
                const uint4* src = (const uint4*)(g_wB +
                    ((size_t)(sp * 256 + np * 128 + nl) * 128 + kc * 32 + q * 4));
                *reinterpret_cast<uint4*>(&s->W[sp][nl][q * 4]) = *src;
            }
            __syncthreads();

            #pragma unroll 1
            for (int kss = 0; kss < 4; kss++) {
                int ksg = kc * 4 + kss;        // global k-step (16 wide)
                int p0g = ksg * 8 + tg;        // global k-pair index
                u32 wmA = s->m2[cellA][ksg >> 1];
                u32 wmB = s->m2[cellB][ksg >> 1];
                int sh0 = ((ksg & 1) << 4) + tg * 2;
                u32 mkA0 = mask2((wmA >> sh0) & 3u);
                u32 mkB0 = mask2((wmB >> sh0) & 3u);
                u32 mkA1 = mask2((wmA >> (sh0 + 8)) & 3u);
                u32 mkB1 = mask2((wmB >> (sh0 + 8)) & 3u);

                u32 a0[4], a1[4];
                a0[0] = s->w3p[0][iiA][p0g]     & mkA0;
                a0[1] = s->w3p[0][iiB][p0g]     & mkB0;
                a0[2] = s->w3p[0][iiA][p0g + 4] & mkA1;
                a0[3] = s->w3p[0][iiB][p0g + 4] & mkB1;
                a1[0] = s->w3p[1][iiA][p0g]     & mkA0;
                a1[1] = s->w3p[1][iiB][p0g]     & mkB0;
                a1[2] = s->w3p[1][iiA][p0g + 4] & mkA1;
                a1[3] = s->w3p[1][iiB][p0g + 4] & mkB1;

                // manually double-buffered B loads across the t loop
                const int bcol = kss * 8 + 2 * tg;
                u64 B0n = *reinterpret_cast<const u64*>(&s->W[0][g][bcol]);
                u64 B1n = *reinterpret_cast<const u64*>(&s->W[1][g][bcol]);
                #pragma unroll
                for (int t = 0; t < 16; t++) {
                    u64 B0 = B0n, B1 = B1n;
                    if (t < 15) {
                        int nl = (t + 1) * 8 + g;
                        B0n = *reinterpret_cast<const u64*>(&s->W[0][nl][bcol]);
                        B1n = *reinterpret_cast<const u64*>(&s->W[1][nl][bcol]);
                    }
                    u32 b00 = (u32)B0, b01 = (u32)(B0 >> 32);
                    u32 b10 = (u32)B1, b11 = (u32)(B1 >> 32);
                    mma16816(d[t], a0, b00, b01);   // E0*W0
                    mma16816(d[t], a1, b00, b01);   // E1*W0
                    mma16816(d[t], a0, b10, b11);   // E0*W1
                }
            }
        }

        // ---------------- fold this np half into J ----------------
        #pragma unroll
        for (int t = 0; t < 16; t++) {
            int widx = np * 4 + (t >> 2);
            int sh = ((t & 3) * 8) + tg * 2;
            u32 wa = mA[widx] >> sh;
            u32 wb = mB[widx] >> sh;
            int j0 = np * 128 + t * 8 + tg * 2;

            float vA0 = (wa & 1u) ? d[t][0] : 0.0f;
            float vA1 = (wa & 2u) ? d[t][1] : 0.0f;
            float vB0 = (wb & 1u) ? d[t][2] : 0.0f;
            float vB1 = (wb & 2u) ? d[t][3] : 0.0f;
            u64 pA0 = pk2(vA0, vA0), pA1 = pk2(vA1, vA1);
            u64 pB0 = pk2(vB0, vB0), pB1 = pk2(vB1, vB1);
            #pragma unroll
            for (int q2 = 0; q2 < 4; q2++) {
                u64 wp0 = s->w1p[q2][j0];
                u64 wp1 = s->w1p[q2][j0 + 1];
                fma2(JA2[q2], pA0, wp0);
                fma2(JA2[q2], pA1, wp1);
                fma2(JB2[q2], pB0, wp0);
                fma2(JB2[q2], pB1, wp1);
            }
        }
    }

    // ---------------- reduce across tg lanes and store ----------------
    float JA[8], JB[8];
    #pragma unroll
    for (int q2 = 0; q2 < 4; q2++) {
        upk2(JA2[q2], JA[2 * q2], JA[2 * q2 + 1]);
        upk2(JB2[q2], JB[2 * q2], JB[2 * q2 + 1]);
    }
    #pragma unroll
    for (int o = 1; o <= 2; o <<= 1) {
        #pragma unroll
        for (int q = 0; q < 8; q++) {
            JA[q] += __shfl_xor_sync(0xffffffffu, JA[q], o);
            JB[q] += __shfl_xor_sync(0xffffffffu, JB[q], o);
        }
    }
    if (tg == 0) {
        const size_t N = (size_t)ncell;
        float* outDY = out + 6 * N;
        float* outDE = out + 42 * N;
        float* outDT = out + 48 * N;
        int nA = n0 + cellA, nB = n0 + cellB;
        #pragma unroll
        for (int q = 0; q < 6; q++) {
            outDY[(size_t)nA * 36 + iiA * 6 + q] = JA[q];
            outDY[(size_t)nB * 36 + iiB * 6 + q] = JB[q];
        }
        outDE[(size_t)nA * 6 + iiA] = JA[6];
        outDT[(size_t)nA * 6 + iiA] = JA[7];
        outDE[(size_t)nB * 6 + iiB] = JB[6];
        outDT[(size_t)nB * 6 + iiB] = JB[7];
    }
}

extern "C" void kernel_launch(void* const* d_in, const int* in_sizes, int n_in,
                              void* d_out, int out_size) {
    // metadata order: t, y, erate, T, w1, w2, w3, b1, b2, b3
    const float* y  = (const float*)d_in[1];
    const float* er = (const float*)d_in[2];
    const float* Tg = (const float*)d_in[3];
    const float* w1 = (const float*)d_in[4];
    const float* w2 = (const float*)d_in[5];
    const float* w3 = (const float*)d_in[6];
    const float* b1 = (const float*)d_in[7];
    const float* b2 = (const float*)d_in[8];
    const float* b3 = (const float*)d_in[9];
    float* out = (float*)d_out;
    int ncell = in_sizes[2];             // NT*NB = 65536

    cudaFuncSetAttribute(k_fwd, cudaFuncAttributeMaxDynamicSharedMemorySize,
                         (int)sizeof(SmemA));
    cudaFuncSetAttribute(k_jacM, cudaFuncAttributeMaxDynamicSharedMemorySize,
                         (int)sizeof(SmemJ2));

    k_prepT<<<64, 256>>>(w2);
    k_prepW<<<64, 256>>>(w2);
    k_fwd<<<ncell / G, NTA, sizeof(SmemA)>>>(y, er, Tg, w1, w3, b1, b2, b3,
                                             out, ncell);
    k_jacM<<<ncell / CPB, 384, sizeof(SmemJ2)>>>(w1, w3, out, ncell);
}

// round 14
// speedup vs baseline: 1.9389x; 1.1584x over previous
#include <cuda_runtime.h>
#include <cuda_bf16.h>
#include <cstdint>

#define H        256
#define NS       6
#define G        32      // cells per forward block
#define NTA      256
#define CPB      32      // cells per jacobian CTA (M = 192 rows dense)

typedef unsigned long long u64;
typedef unsigned int u32;

// ---------------- device scratch (allocations are forbidden) ----------------
__device__ float         g_w2T[H * H];        // for k_fwd
__device__ u32           g_wB[2 * 256 * 128]; // bf16 pairs: [split][n][pos] (pair-permuted)
__device__ unsigned char g_m2cb[65536 * 32];  // m2 nibble bytes per cell
__device__ u32           g_m1w[65536 * 8];    // m1 ballot words per cell

// ---------------- helpers ----------------
__device__ __forceinline__ u64 pk2(float lo, float hi) {
    u64 r; asm("mov.b64 %0, {%1, %2};" : "=l"(r) : "f"(lo), "f"(hi)); return r;
}
__device__ __forceinline__ void upk2(u64 v, float& lo, float& hi) {
    asm("mov.b64 {%0, %1}, %2;" : "=f"(lo), "=f"(hi) : "l"(v));
}
__device__ __forceinline__ void fma2(u64& d, u64 a, u64 b) {
    asm("fma.rn.f32x2 %0, %1, %2, %0;" : "+l"(d) : "l"(a), "l"(b));
}
__device__ __forceinline__ u32 pack8(u64 x) {
    x |= x >> 4;  x &= 0x00FF00FF00FF00FFull;
    x |= x >> 8;  x &= 0x0000FFFF0000FFFFull;
    x |= x >> 16;
    return (u32)x;
}
__device__ __forceinline__ unsigned short bfs(float v, int s) {
    __nv_bfloat16 h0 = __float2bfloat16(v);
    if (s == 0) return __bfloat16_as_ushort(h0);
    float r = v - __bfloat162float(h0);
    return __bfloat16_as_ushort(__float2bfloat16(r));
}
__device__ __forceinline__ void mma16816(float* d, const u32* a, u32 b0, u32 b1) {
    asm volatile(
        "mma.sync.aligned.m16n8k16.row.col.f32.bf16.bf16.f32 "
        "{%0,%1,%2,%3}, {%4,%5,%6,%7}, {%8,%9}, {%0,%1,%2,%3};"
        : "+f"(d[0]), "+f"(d[1]), "+f"(d[2]), "+f"(d[3])
        : "r"(a[0]), "r"(a[1]), "r"(a[2]), "r"(a[3]), "r"(b0), "r"(b1));
}
__device__ __forceinline__ u32 mask2(u32 bits) {
    return ((bits & 1u) ? 0x0000FFFFu : 0u) | ((bits & 2u) ? 0xFFFF0000u : 0u);
}
__device__ __forceinline__ u32 smem_u32(const void* p) {
    u32 a;
    asm("{ .reg .u64 t; cvta.to.shared.u64 t, %1; cvt.u32.u64 %0, t; }"
        : "=r"(a) : "l"(p));
    return a;
}
__device__ __forceinline__ void cp16(u32 dst, const void* src) {
    asm volatile("cp.async.cg.shared.global [%0], [%1], 16;"
                 :: "r"(dst), "l"(src) : "memory");
}
#define CP_COMMIT() asm volatile("cp.async.commit_group;" ::: "memory")
#define CP_WAIT0()  asm volatile("cp.async.wait_group 0;" ::: "memory")

// ======================= prep A: transpose w2 ==============================
__global__ void k_prepT(const float* __restrict__ w2) {
    __shared__ float t[32][33];
    int bid = blockIdx.x, tid = threadIdx.x;
    int j0 = (bid & 7) * 32, h0 = (bid >> 3) * 32;
    int tx = tid & 31, ty = tid >> 5;
    #pragma unroll
    for (int r = 0; r < 32; r += 8)
        t[ty + r][tx] = w2[(h0 + ty + r) * H + j0 + tx];
    __syncthreads();
    #pragma unroll
    for (int r = 0; r < 32; r += 8)
        g_w2T[(j0 + ty + r) * H + h0 + tx] = t[tx][ty + r];
}

// ======================= prep B: bf16 W pairs, pair-permuted ===============
// g_wB[(s*256+n)*128 + pos]; pos within 8-group: (0,4),(1,5),(2,6),(3,7)
// so a u64 read of (pos 2w, 2w+1) yields pairs (kp=w, kp=w+4).
__global__ void k_prepW(const float* __restrict__ w2) {
    int base = blockIdx.x * 1024 + threadIdx.x * 4;
    #pragma unroll
    for (int e4 = 0; e4 < 4; e4++) {
        int idx = base + e4;
        int s = idx >> 15;
        int rem = idx & 32767;
        int n = rem >> 7, pos = rem & 127;
        int group = pos >> 3, within = pos & 7;
        int w8 = (within >> 1) + 4 * (within & 1);
        int kp = group * 8 + w8;
        float va = w2[(size_t)(2 * kp) * H + n];
        float vb = w2[(size_t)(2 * kp + 1) * H + n];
        g_wB[idx] = (u32)bfs(va, s) | ((u32)bfs(vb, s) << 16);
    }
}

// ======================= kernel A: forward (unchanged, passing) =============
struct SmemA {
    u64    v1s[H][34];
    float4 w3f4[NS][64];
    float  xs[G][8];
};

__global__ void __launch_bounds__(NTA, 2)
k_fwd(const float* __restrict__ y,  const float* __restrict__ er,
      const float* __restrict__ Tg, const float* __restrict__ w1,
      const float* __restrict__ w3, const float* __restrict__ b1,
      const float* __restrict__ b2, const float* __restrict__ b3,
      float* __restrict__ out, int ncell)
{
    extern __shared__ char raw[];
    SmemA* s = reinterpret_cast<SmemA*>(raw);

    const int tid  = threadIdx.x;
    const int lane = tid & 31;
    const int wid  = tid >> 5;
    const int n0   = blockIdx.x * G;

    float w1r[8];
    #pragma unroll
    for (int q = 0; q < 8; q++) w1r[q] = w1[tid * 8 + q];
    #pragma unroll
    for (int idx = tid; idx < NS * 64; idx += NTA) {
        int i = idx >> 6, l = idx & 63;
        s->w3f4[i][l] = *reinterpret_cast<const float4*>(&w3[i * H + 4 * l]);
    }
    {
        int c = tid >> 3, q = tid & 7, n = n0 + c;
        float xv = (q < 6) ? y[n * 6 + q] : (q == 6 ? er[n] : Tg[n]);
        s->xs[c][q] = xv;
    }
    __syncthreads();

    {
        float b1v = b1[tid];
        #pragma unroll 4
        for (int c = 0; c < G; c++) {
            float z = b1v;
            #pragma unroll
            for (int q = 0; q < 8; q++) z = fmaf(w1r[q], s->xs[c][q], z);
            float v = fmaxf(z, 0.0f);
            s->v1s[tid][c] = pk2(v, v);
            unsigned bal = __ballot_sync(0xffffffffu, z > 0.0f);
            if (lane == 0) g_m1w[(size_t)(n0 + c) * 8 + wid] = bal;
        }
    }
    __syncthreads();

    const int c0 = wid * 4;
    {
        u64 acc2[4][4];
        #pragma unroll
        for (int r2 = 0; r2 < 4; r2++)
            #pragma unroll
            for (int cc = 0; cc < 4; cc++) acc2[r2][cc] = 0ull;

        #pragma unroll 2
        for (int j = 0; j < H; j++) {
            const float* wrow = g_w2T + j * H + 4 * lane;
            ulonglong2 wa = *reinterpret_cast<const ulonglong2*>(wrow);
            ulonglong2 wb = *reinterpret_cast<const ulonglong2*>(wrow + 128);
            u64 wv[4] = {wa.x, wa.y, wb.x, wb.y};
            ulonglong2 va = *reinterpret_cast<const ulonglong2*>(&s->v1s[j][c0]);
            ulonglong2 vb = *reinterpret_cast<const ulonglong2*>(&s->v1s[j][c0 + 2]);
            u64 vs[4] = {va.x, va.y, vb.x, vb.y};
            #pragma unroll
            for (int r2 = 0; r2 < 4; r2++)
                #pragma unroll
                for (int cc = 0; cc < 4; cc++)
                    fma2(acc2[r2][cc], wv[r2], vs[cc]);
        }

        float4 b2lo = *reinterpret_cast<const float4*>(b2 + 4 * lane);
        float4 b2hi = *reinterpret_cast<const float4*>(b2 + 128 + 4 * lane);
        float b2a[8] = {b2lo.x, b2lo.y, b2lo.z, b2lo.w,
                        b2hi.x, b2hi.y, b2hi.z, b2hi.w};
        unsigned mbyte[4] = {0u, 0u, 0u, 0u};
        float v2r[8][4];
        #pragma unroll
        for (int r2 = 0; r2 < 4; r2++)
            #pragma unroll
            for (int cc = 0; cc < 4; cc++) {
                float lo, hi; upk2(acc2[r2][cc], lo, hi);
                float z0 = lo + b2a[2 * r2];
                float z1 = hi + b2a[2 * r2 + 1];
                v2r[2 * r2][cc]     = fmaxf(z0, 0.0f);
                v2r[2 * r2 + 1][cc] = fmaxf(z1, 0.0f);
                if (z0 > 0.0f) mbyte[cc] |= (1u << (2 * r2));
                if (z1 > 0.0f) mbyte[cc] |= (1u << (2 * r2 + 1));
            }
        #pragma unroll
        for (int cc = 0; cc < 4; cc++)
            g_m2cb[(size_t)(n0 + c0 + cc) * 32 + lane] = (unsigned char)mbyte[cc];

        float yp[NS][4];
        #pragma unroll
        for (int i = 0; i < NS; i++) {
            float4 wa = s->w3f4[i][lane];
            float4 wb = s->w3f4[i][32 + lane];
            float w3r[8] = {wa.x, wa.y, wa.z, wa.w, wb.x, wb.y, wb.z, wb.w};
            float a0 = 0.f, a1 = 0.f, a2 = 0.f, a3 = 0.f;
            #pragma unroll
            for (int r = 0; r < 8; r++) {
                a0 = fmaf(w3r[r], v2r[r][0], a0);
                a1 = fmaf(w3r[r], v2r[r][1], a1);
                a2 = fmaf(w3r[r], v2r[r][2], a2);
                a3 = fmaf(w3r[r], v2r[r][3], a3);
            }
            yp[i][0] = a0; yp[i][1] = a1; yp[i][2] = a2; yp[i][3] = a3;
        }

        #pragma unroll
        for (int i = 0; i < NS; i++)
            #pragma unroll
            for (int cc = 0; cc < 4; cc++) {
                float v = yp[i][cc];
                #pragma unroll
                for (int o = 16; o > 0; o >>= 1)
                    v += __shfl_xor_sync(0xffffffffu, v, o);
                yp[i][cc] = v;
            }
        if (lane == 0) {
            #pragma unroll
            for (int i = 0; i < NS; i++) {
                float b3v = b3[i];
                #pragma unroll
                for (int cc = 0; cc < 4; cc++)
                    out[(size_t)(n0 + c0 + cc) * NS + i] = yp[i][cc] + b3v;
            }
        }
    }
}

// ======================= kernel B: mma.sync Jacobian (M=192 dense) ==========
// 32 cells/CTA, M = 192 rows (cell = row/6, ii = row%6; no pad rows).
// 384 threads = 12 warps; warp = M-tile (rows 16mt..16mt+15).
// W double-buffered via cp.async; row stride 40 (==8 mod 32) conflict-free.
struct SmemJ2 {
    u32 W[2][2][128][40];   // [buf][split][n-local][permuted kp-local 32 + pad 8]
    u64 w1p[4][256];
    u32 w3p[2][6][132];
    u32 m2[CPB][8];
};

__global__ void __launch_bounds__(384, 1)
k_jacM(const float* __restrict__ w1, const float* __restrict__ w3,
       float* __restrict__ out, int ncell)
{
    extern __shared__ char raw[];
    SmemJ2* s = reinterpret_cast<SmemJ2*>(raw);
    const u32 sWb = smem_u32(&s->W[0][0][0][0]);

    const int tid  = threadIdx.x;
    const int lane = tid & 31;
    const int wid  = tid >> 5;      // 0..11 = M-tile
    const int g    = lane >> 2;     // 0..7
    const int tg   = lane & 3;
    const int n0   = blockIdx.x * CPB;

    const int r1 = wid * 16 + g, r2 = r1 + 8;
    const int cellA = r1 / 6, iiA = r1 - 6 * cellA;
    const int cellB = r2 / 6, iiB = r2 - 6 * cellB;

    // copy chunk (np,kc) into buffer b via cp.async
    auto copyW = [&](int np, int kc, int b) {
        for (int i = tid; i < 2048; i += 384) {
            int sp = i >> 10;
            int rem = i & 1023;
            int nl = rem >> 3, q = rem & 7;
            const void* src = (const void*)(g_wB +
                ((size_t)(sp * 256 + np * 128 + nl) * 128 + kc * 32 + q * 4));
            u32 dst = sWb + (u32)((((b * 2 + sp) * 128 + nl) * 40 + q * 4) * 4);
            cp16(dst, src);
        }
        CP_COMMIT();
    };

    // ---------------- stage tables ----------------
    if (tid < 256) {
        int j = tid;
        const float* wr = w1 + (size_t)j * 8;
        float4 a = *reinterpret_cast<const float4*>(wr);
        float4 b = *reinterpret_cast<const float4*>(wr + 4);
        s->w1p[0][j] = pk2(a.x, a.y);
        s->w1p[1][j] = pk2(a.z, a.w);
        s->w1p[2][j] = pk2(b.x, b.y);
        s->w1p[3][j] = pk2(b.z, b.w);
    }
    for (int idx = tid; idx < 2 * 6 * 128; idx += 384) {
        int sp = idx / 768;
        int r = idx - sp * 768;
        int ii = r >> 7, p = r & 127;
        float va = w3[ii * H + 2 * p], vb = w3[ii * H + 2 * p + 1];
        s->w3p[sp][ii][p] = (u32)bfs(va, sp) | ((u32)bfs(vb, sp) << 16);
    }
    if (tid < CPB) {
        const u64* mp = (const u64*)(g_m2cb + (size_t)(n0 + tid) * 32);
        #pragma unroll
        for (int d = 0; d < 4; d++) {
            u64 ch = mp[d];
            s->m2[tid][d]     = pack8(ch & 0x0F0F0F0F0F0F0F0Full);
            s->m2[tid][4 + d] = pack8((ch >> 4) & 0x0F0F0F0F0F0F0F0Full);
        }
    }
    copyW(0, 0, 0);     // prefetch first chunk

    // hoist m1 masks (per-lane cells)
    u32 mA[8], mB[8];
    {
        const uint4* pa = (const uint4*)(g_m1w + (size_t)(n0 + cellA) * 8);
        uint4 x = pa[0], z = pa[1];
        mA[0] = x.x; mA[1] = x.y; mA[2] = x.z; mA[3] = x.w;
        mA[4] = z.x; mA[5] = z.y; mA[6] = z.z; mA[7] = z.w;
        const uint4* pb = (const uint4*)(g_m1w + (size_t)(n0 + cellB) * 8);
        uint4 x2 = pb[0], z2 = pb[1];
        mB[0] = x2.x; mB[1] = x2.y; mB[2] = x2.z; mB[3] = x2.w;
        mB[4] = z2.x; mB[5] = z2.y; mB[6] = z2.z; mB[7] = z2.w;
    }

    u64 JA2[4] = {0ull, 0ull, 0ull, 0ull};
    u64 JB2[4] = {0ull, 0ull, 0ull, 0ull};

    #pragma unroll 1
    for (int np = 0; np < 2; np++) {
        float d[16][4];
        #pragma unroll
        for (int t = 0; t < 16; t++)
            #pragma unroll
            for (int c = 0; c < 4; c++) d[t][c] = 0.0f;

        #pragma unroll 1
        for (int kc = 0; kc < 4; kc++) {
            const int idx = np * 4 + kc;
            const int buf = idx & 1;
            CP_WAIT0();
            __syncthreads();     // chunk ready + all warps done with prior buf
            if (idx < 7) {
                int nidx = idx + 1;
                copyW(nidx >> 2, nidx & 3, nidx & 1);
            }

            #pragma unroll 1
            for (int kss = 0; kss < 4; kss++) {
                int ksg = kc * 4 + kss;        // global k-step (16 wide)
                int p0g = ksg * 8 + tg;        // global k-pair index
                u32 wmA = s->m2[cellA][ksg >> 1];
                u32 wmB = s->m2[cellB][ksg >> 1];
                int sh0 = ((ksg & 1) << 4) + tg * 2;
                u32 mkA0 = mask2((wmA >> sh0) & 3u);
                u32 mkB0 = mask2((wmB >> sh0) & 3u);
                u32 mkA1 = mask2((wmA >> (sh0 + 8)) & 3u);
                u32 mkB1 = mask2((wmB >> (sh0 + 8)) & 3u);

                u32 a0[4], a1[4];
                a0[0] = s->w3p[0][iiA][p0g]     & mkA0;
                a0[1] = s->w3p[0][iiB][p0g]     & mkB0;
                a0[2] = s->w3p[0][iiA][p0g + 4] & mkA1;
                a0[3] = s->w3p[0][iiB][p0g + 4] & mkB1;
                a1[0] = s->w3p[1][iiA][p0g]     & mkA0;
                a1[1] = s->w3p[1][iiB][p0g]     & mkB0;
                a1[2] = s->w3p[1][iiA][p0g + 4] & mkA1;
                a1[3] = s->w3p[1][iiB][p0g + 4] & mkB1;

                const int bcol = kss * 8 + 2 * tg;
                u64 Br[16];
                // split 0: load all 16 B pairs, then prod0 + prod1 (no RAW chains)
                #pragma unroll
                for (int t = 0; t < 16; t++)
                    Br[t] = *reinterpret_cast<const u64*>(&s->W[buf][0][t * 8 + g][bcol]);
                #pragma unroll
                for (int t = 0; t < 16; t++)
                    mma16816(d[t], a0, (u32)Br[t], (u32)(Br[t] >> 32));
                #pragma unroll
                for (int t = 0; t < 16; t++)
                    mma16816(d[t], a1, (u32)Br[t], (u32)(Br[t] >> 32));
                // split 1: reload, prod2
                #pragma unroll
                for (int t = 0; t < 16; t++)
                    Br[t] = *reinterpret_cast<const u64*>(&s->W[buf][1][t * 8 + g][bcol]);
                #pragma unroll
                for (int t = 0; t < 16; t++)
                    mma16816(d[t], a0, (u32)Br[t], (u32)(Br[t] >> 32));
            }
        }

        // ---------------- fold this np half into J ----------------
        #pragma unroll
        for (int t = 0; t < 16; t++) {
            int widx = np * 4 + (t >> 2);
            int sh = ((t & 3) * 8) + tg * 2;
            u32 wa = mA[widx] >> sh;
            u32 wb = mB[widx] >> sh;
            int j0 = np * 128 + t * 8 + tg * 2;

            float vA0 = (wa & 1u) ? d[t][0] : 0.0f;
            float vA1 = (wa & 2u) ? d[t][1] : 0.0f;
            float vB0 = (wb & 1u) ? d[t][2] : 0.0f;
            float vB1 = (wb & 2u) ? d[t][3] : 0.0f;
            u64 pA0 = pk2(vA0, vA0), pA1 = pk2(vA1, vA1);
            u64 pB0 = pk2(vB0, vB0), pB1 = pk2(vB1, vB1);
            #pragma unroll
            for (int q2 = 0; q2 < 4; q2++) {
                u64 wp0 = s->w1p[q2][j0];
                u64 wp1 = s->w1p[q2][j0 + 1];
                fma2(JA2[q2], pA0, wp0);
                fma2(JA2[q2], pA1, wp1);
                fma2(JB2[q2], pB0, wp0);
                fma2(JB2[q2], pB1, wp1);
            }
        }
    }

    // ---------------- reduce across tg lanes and store ----------------
    float JA[8], JB[8];
    #pragma unroll
    for (int q2 = 0; q2 < 4; q2++) {
        upk2(JA2[q2], JA[2 * q2], JA[2 * q2 + 1]);
        upk2(JB2[q2], JB[2 * q2], JB[2 * q2 + 1]);
    }
    #pragma unroll
    for (int o = 1; o <= 2; o <<= 1) {
        #pragma unroll
        for (int q = 0; q < 8; q++) {
            JA[q] += __shfl_xor_sync(0xffffffffu, JA[q], o);
            JB[q] += __shfl_xor_sync(0xffffffffu, JB[q], o);
        }
    }
    if (tg == 0) {
        const size_t N = (size_t)ncell;
        float* outDY = out + 6 * N;
        float* outDE = out + 42 * N;
        float* outDT = out + 48 * N;
        int nA = n0 + cellA, nB = n0 + cellB;
        #pragma unroll
        for (int q = 0; q < 6; q++) {
            outDY[(size_t)nA * 36 + iiA * 6 + q] = JA[q];
            outDY[(size_t)nB * 36 + iiB * 6 + q] = JB[q];
        }
        outDE[(size_t)nA * 6 + iiA] = JA[6];
        outDT[(size_t)nA * 6 + iiA] = JA[7];
        outDE[(size_t)nB * 6 + iiB] = JB[6];
        outDT[(size_t)nB * 6 + iiB] = JB[7];
    }
}

extern "C" void kernel_launch(void* const* d_in, const int* in_sizes, int n_in,
                              void* d_out, int out_size) {
    // metadata order: t, y, erate, T, w1, w2, w3, b1, b2, b3
    const float* y  = (const float*)d_in[1];
    const float* er = (const float*)d_in[2];
    const float* Tg = (const float*)d_in[3];
    const float* w1 = (const float*)d_in[4];
    const float* w2 = (const float*)d_in[5];
    const float* w3 = (const float*)d_in[6];
    const float* b1 = (const float*)d_in[7];
    const float* b2 = (const float*)d_in[8];
    const float* b3 = (const float*)d_in[9];
    float* out = (float*)d_out;
    int ncell = in_sizes[2];             // NT*NB = 65536

    cudaFuncSetAttribute(k_fwd, cudaFuncAttributeMaxDynamicSharedMemorySize,
                         (int)sizeof(SmemA));
    cudaFuncSetAttribute(k_jacM, cudaFuncAttributeMaxDynamicSharedMemorySize,
                         (int)sizeof(SmemJ2));

    k_prepT<<<64, 256>>>(w2);
    k_prepW<<<64, 256>>>(w2);
    k_fwd<<<ncell / G, NTA, sizeof(SmemA)>>>(y, er, Tg, w1, w3, b1, b2, b3,
                                             out, ncell);
    k_jacM<<<ncell / CPB, 384, sizeof(SmemJ2)>>>(w1, w3, out, ncell);
}

// round 15
// speedup vs baseline: 2.1295x; 1.0983x over previous
#include <cuda_runtime.h>
#include <cuda_bf16.h>
#include <cstdint>

#define H        256
#define NS       6
#define G        32      // cells per forward block
#define CPB      32      // cells per jacobian CTA (M = 192 rows dense)
#define TAU      1e-3f

typedef unsigned long long u64;
typedef unsigned int u32;

// ---------------- device scratch (allocations are forbidden) ----------------
__device__ u32 g_wB[2 * 256 * 128];  // jac B: bf16 pairs [split][n][pos] (pair-permuted)
__device__ u32 g_wA[65536];          // fwd A: w2 bf16 pairs [sp][grp][pos][row]
__device__ u32 g_m2w[65536 * 8];     // m2 words per cell: bit b of word g <-> h=32g+b
__device__ u32 g_m1w[65536 * 8];     // m1 ballot words per cell

// ---------------- helpers ----------------
__device__ __forceinline__ u64 pk2(float lo, float hi) {
    u64 r; asm("mov.b64 %0, {%1, %2};" : "=l"(r) : "f"(lo), "f"(hi)); return r;
}
__device__ __forceinline__ void upk2(u64 v, float& lo, float& hi) {
    asm("mov.b64 {%0, %1}, %2;" : "=f"(lo), "=f"(hi) : "l"(v));
}
__device__ __forceinline__ void fma2(u64& d, u64 a, u64 b) {
    asm("fma.rn.f32x2 %0, %1, %2, %0;" : "+l"(d) : "l"(a), "l"(b));
}
__device__ __forceinline__ unsigned short bfs(float v, int s) {
    __nv_bfloat16 h0 = __float2bfloat16(v);
    if (s == 0) return __bfloat16_as_ushort(h0);
    float r = v - __bfloat162float(h0);
    return __bfloat16_as_ushort(__float2bfloat16(r));
}
__device__ __forceinline__ void mma16816(float* d, const u32* a, u32 b0, u32 b1) {
    asm volatile(
        "mma.sync.aligned.m16n8k16.row.col.f32.bf16.bf16.f32 "
        "{%0,%1,%2,%3}, {%4,%5,%6,%7}, {%8,%9}, {%0,%1,%2,%3};"
        : "+f"(d[0]), "+f"(d[1]), "+f"(d[2]), "+f"(d[3])
        : "r"(a[0]), "r"(a[1]), "r"(a[2]), "r"(a[3]), "r"(b0), "r"(b1));
}
__device__ __forceinline__ u32 mask2(u32 bits) {
    return ((bits & 1u) ? 0x0000FFFFu : 0u) | ((bits & 2u) ? 0xFFFF0000u : 0u);
}
__device__ __forceinline__ u32 smem_u32(const void* p) {
    u32 a;
    asm("{ .reg .u64 t; cvta.to.shared.u64 t, %1; cvt.u32.u64 %0, t; }"
        : "=r"(a) : "l"(p));
    return a;
}
__device__ __forceinline__ void cp16(u32 dst, const void* src) {
    asm volatile("cp.async.cg.shared.global [%0], [%1], 16;"
                 :: "r"(dst), "l"(src) : "memory");
}
#define CP_COMMIT() asm volatile("cp.async.commit_group;" ::: "memory")
#define CP_WAIT0()  asm volatile("cp.async.wait_group 0;" ::: "memory")

// ======================= prep B (jac W tiles, unchanged) ===================
// g_wB[(s*256+n)*128 + pos]; u64 at pos 2w yields pairs (kp=w, kp=w+4).
__global__ void k_prepW(const float* __restrict__ w2) {
    int base = blockIdx.x * 1024 + threadIdx.x * 4;
    #pragma unroll
    for (int e4 = 0; e4 < 4; e4++) {
        int idx = base + e4;
        int s = idx >> 15;
        int rem = idx & 32767;
        int n = rem >> 7, pos = rem & 127;
        int group = pos >> 3, within = pos & 7;
        int w8 = (within >> 1) + 4 * (within & 1);
        int kp = group * 8 + w8;
        float va = w2[(size_t)(2 * kp) * H + n];
        float vb = w2[(size_t)(2 * kp + 1) * H + n];
        g_wB[idx] = (u32)bfs(va, s) | ((u32)bfs(vb, s) << 16);
    }
}

// ======================= prep A (fwd w2 row-major pairs) ===================
// g_wA[((sp*32+grp)*128 + pos)*8 + row]; h = grp*8+row; pair-permuted pos.
__global__ void k_prepA(const float* __restrict__ w2) {
    int base = blockIdx.x * 1024 + threadIdx.x * 4;
    #pragma unroll
    for (int e4 = 0; e4 < 4; e4++) {
        int idx = base + e4;
        int row = idx & 7;
        int pos = (idx >> 3) & 127;
        int grp = (idx >> 10) & 31;
        int sp  = idx >> 15;
        int h = grp * 8 + row;
        int within = pos & 7;
        int w8 = (within >> 1) + 4 * (within & 1);
        int kp = (pos >> 3) * 8 + w8;
        float va = w2[(size_t)h * H + 2 * kp];
        float vb = w2[(size_t)h * H + 2 * kp + 1];
        g_wA[idx] = (u32)bfs(va, sp) | ((u32)bfs(vb, sp) << 16);
    }
}

// ======================= kernel A: tensor-core forward ======================
struct SmemF {
    u32    Abuf[2][2][32][16][8];  // [buf][sp][grp][posL][row]   64 KB
    float  v1f[H][33];             // fp32 v1 (fix-up + packing)  33.8 KB
    u32    v1p[2][G][136];         // B pairs [sp][c][pos]        34.8 KB
    float  v2s[G][260];            // relu(z2) staged             33.3 KB
    float4 w3f4[NS][64];           //                              6 KB
    unsigned char m2s[G][H];       // mask bytes [c][h]            8 KB
    float  xs[G][8];
    float  b2s[H];
    int    cnt;
    u32    flags[256];
};

__global__ void __launch_bounds__(256, 1)
k_fwdM(const float* __restrict__ y,  const float* __restrict__ er,
       const float* __restrict__ Tg, const float* __restrict__ w1,
       const float* __restrict__ w2, const float* __restrict__ w3,
       const float* __restrict__ b1, const float* __restrict__ b2,
       const float* __restrict__ b3, float* __restrict__ out, int ncell)
{
    extern __shared__ char raw[];
    SmemF* s = reinterpret_cast<SmemF*>(raw);
    const u32 sAb = smem_u32(&s->Abuf[0][0][0][0][0]);

    const int tid  = threadIdx.x;
    const int lane = tid & 31;
    const int wid  = tid >> 5;      // 0..7
    const int g    = lane >> 2;     // 0..7
    const int tg   = lane & 3;
    const int n0   = blockIdx.x * G;

    auto copyA = [&](int kc, int b) {
        for (int i = tid; i < 2048; i += 256) {
            int seg  = i & 1;
            int posL = (i >> 1) & 15;
            int grp  = (i >> 5) & 31;
            int sp   = i >> 10;
            const void* src = (const void*)(g_wA +
                ((size_t)((sp * 32 + grp) * 128 + kc * 16 + posL)) * 8 + seg * 4);
            u32 dst = sAb + (u32)((((((b * 2 + sp) * 32 + grp) * 16 + posL) * 8)
                                   + seg * 4) * 4);
            cp16(dst, src);
        }
        CP_COMMIT();
    };

    copyA(0, 0);    // prefetch A chunk 0 immediately (overlaps phase 1)

    // ---------------- stage ----------------
    float w1r[8];
    #pragma unroll
    for (int q = 0; q < 8; q++) w1r[q] = w1[tid * 8 + q];
    #pragma unroll
    for (int idx = tid; idx < NS * 64; idx += 256) {
        int i = idx >> 6, l = idx & 63;
        s->w3f4[i][l] = *reinterpret_cast<const float4*>(&w3[i * H + 4 * l]);
    }
    s->b2s[tid] = b2[tid];
    {
        int c = tid >> 3, q = tid & 7, n = n0 + c;
        float xv = (q < 6) ? y[n * 6 + q] : (q == 6 ? er[n] : Tg[n]);
        s->xs[c][q] = xv;
    }
    if (tid == 0) s->cnt = 0;
    __syncthreads();

    // ---------------- phase 1: z1 / v1 / m1 (thread = neuron j = tid) ------
    {
        float b1v = b1[tid];
        #pragma unroll 4
        for (int c = 0; c < G; c++) {
            float z = b1v;
            #pragma unroll
            for (int q = 0; q < 8; q++) z = fmaf(w1r[q], s->xs[c][q], z);
            s->v1f[tid][c] = fmaxf(z, 0.0f);
            unsigned bal = __ballot_sync(0xffffffffu, z > 0.0f);
            if (lane == 0) g_m1w[(size_t)(n0 + c) * 8 + wid] = bal;
        }
    }
    __syncthreads();

    // ---------------- build v1 bf16-split pairs ----------------
    // v1p[sp][c][pos] = pair(v1[2kp][c], v1[2kp+1][c]), permuted pos
    #pragma unroll
    for (int it = 0; it < 32; it++) {
        int idx = tid + 256 * it;
        int sp = idx >> 12;
        int rem = idx & 4095;
        int c = rem >> 7, pos = rem & 127;
        int within = pos & 7;
        int w8 = (within >> 1) + 4 * (within & 1);
        int kp = (pos >> 3) * 8 + w8;
        float va = s->v1f[2 * kp][c];
        float vb = s->v1f[2 * kp + 1][c];
        s->v1p[sp][c][pos] = (u32)bfs(va, sp) | ((u32)bfs(vb, sp) << 16);
    }
    // (no sync needed yet; the kc=0 barrier below covers visibility)

    // ---------------- MMA mainloop: D[h][c] = w2 @ v1 ----------------------
    // warp owns M-tiles mtA=wid (h 16wid..), mtB=wid+8 (h 128+16wid..)
    float d[2][4][4];
    #pragma unroll
    for (int m = 0; m < 2; m++)
        #pragma unroll
        for (int nt = 0; nt < 4; nt++)
            #pragma unroll
            for (int e = 0; e < 4; e++) d[m][nt][e] = 0.0f;

    const int gA = wid * 2;        // grp of mtA rows 0..7
    const int gB = gA + 16;        // grp of mtB rows 0..7

    #pragma unroll 1
    for (int kc = 0; kc < 8; kc++) {
        CP_WAIT0();
        __syncthreads();
        if (kc < 7) copyA(kc + 1, (kc + 1) & 1);
        const int buf = kc & 1;

        #pragma unroll
        for (int ks = 0; ks < 2; ks++) {
            const int kssG = kc * 2 + ks;
            const int p0 = ks * 8 + 2 * tg, p1 = p0 + 1;

            u32 aA0[4], aA1[4], aB0[4], aB1[4];
            aA0[0] = s->Abuf[buf][0][gA][p0][g];
            aA0[1] = s->Abuf[buf][0][gA + 1][p0][g];
            aA0[2] = s->Abuf[buf][0][gA][p1][g];
            aA0[3] = s->Abuf[buf][0][gA + 1][p1][g];
            aA1[0] = s->Abuf[buf][1][gA][p0][g];
            aA1[1] = s->Abuf[buf][1][gA + 1][p0][g];
            aA1[2] = s->Abuf[buf][1][gA][p1][g];
            aA1[3] = s->Abuf[buf][1][gA + 1][p1][g];
            aB0[0] = s->Abuf[buf][0][gB][p0][g];
            aB0[1] = s->Abuf[buf][0][gB + 1][p0][g];
            aB0[2] = s->Abuf[buf][0][gB][p1][g];
            aB0[3] = s->Abuf[buf][0][gB + 1][p1][g];
            aB1[0] = s->Abuf[buf][1][gB][p0][g];
            aB1[1] = s->Abuf[buf][1][gB + 1][p0][g];
            aB1[2] = s->Abuf[buf][1][gB][p1][g];
            aB1[3] = s->Abuf[buf][1][gB + 1][p1][g];

            u64 B0[4], B1[4];
            #pragma unroll
            for (int nt = 0; nt < 4; nt++) {
                B0[nt] = *reinterpret_cast<const u64*>(
                             &s->v1p[0][nt * 8 + g][kssG * 8 + 2 * tg]);
                B1[nt] = *reinterpret_cast<const u64*>(
                             &s->v1p[1][nt * 8 + g][kssG * 8 + 2 * tg]);
            }
            // product-major (RAW spacing 8)
            #pragma unroll
            for (int nt = 0; nt < 4; nt++) {
                mma16816(d[0][nt], aA0, (u32)B0[nt], (u32)(B0[nt] >> 32));
                mma16816(d[1][nt], aB0, (u32)B0[nt], (u32)(B0[nt] >> 32));
            }
            #pragma unroll
            for (int nt = 0; nt < 4; nt++) {
                mma16816(d[0][nt], aA1, (u32)B0[nt], (u32)(B0[nt] >> 32));
                mma16816(d[1][nt], aB1, (u32)B0[nt], (u32)(B0[nt] >> 32));
            }
            #pragma unroll
            for (int nt = 0; nt < 4; nt++) {
                mma16816(d[0][nt], aA0, (u32)B1[nt], (u32)(B1[nt] >> 32));
                mma16816(d[1][nt], aB0, (u32)B1[nt], (u32)(B1[nt] >> 32));
            }
        }
    }
    __syncthreads();

    // ---------------- epilogue: z2 / relu / mask bytes / flags -------------
    #pragma unroll
    for (int m = 0; m < 2; m++) {
        int hb = ((m == 0) ? wid : wid + 8) * 16;
        #pragma unroll
        for (int nt = 0; nt < 4; nt++) {
            int cbase = nt * 8 + 2 * tg;
            #pragma unroll
            for (int e = 0; e < 4; e++) {
                int h = hb + g + ((e >= 2) ? 8 : 0);
                int c = cbase + (e & 1);
                float z = d[m][nt][e] + s->b2s[h];
                s->m2s[c][h] = (z > 0.0f) ? 1 : 0;
                s->v2s[c][h] = fmaxf(z, 0.0f);
                if (fabsf(z) < TAU) {
                    int fi = atomicAdd(&s->cnt, 1);
                    if (fi < 256) s->flags[fi] = ((u32)c << 16) | (u32)h;
                }
            }
        }
    }
    __syncthreads();

    // ---------------- fix-up: exact fp32 recompute for borderline z2 -------
    {
        int nfix = s->cnt;
        if (nfix > 256) nfix = 256;
        for (int fi = wid; fi < nfix; fi += 8) {
            u32 f = s->flags[fi];
            int c = (int)(f >> 16), h = (int)(f & 0xFFFFu);
            const float* wr = w2 + (size_t)h * H + lane * 8;
            float4 wa = *reinterpret_cast<const float4*>(wr);
            float4 wb = *reinterpret_cast<const float4*>(wr + 4);
            float wv[8] = {wa.x, wa.y, wa.z, wa.w, wb.x, wb.y, wb.z, wb.w};
            float acc = 0.0f;
            #pragma unroll
            for (int e = 0; e < 8; e++)
                acc = fmaf(wv[e], s->v1f[lane * 8 + e][c], acc);
            #pragma unroll
            for (int o = 16; o > 0; o >>= 1)
                acc += __shfl_xor_sync(0xffffffffu, acc, o);
            if (lane == 0) {
                float z = acc + s->b2s[h];
                s->m2s[c][h] = (z > 0.0f) ? 1 : 0;
                s->v2s[c][h] = fmaxf(z, 0.0f);
            }
        }
    }
    __syncthreads();

    // ---------------- pack m2 words ----------------
    {
        int c = tid >> 3, gw = tid & 7;
        u32 wm = 0;
        #pragma unroll
        for (int q = 0; q < 8; q++) {
            u32 x = *reinterpret_cast<const u32*>(&s->m2s[c][gw * 32 + q * 4]);
            wm |= (((x & 0x01010101u) * 0x01020408u) >> 24 & 0xFu) << (q * 4);
        }
        g_m2w[(size_t)(n0 + c) * 8 + gw] = wm;
    }

    // ---------------- ydot ----------------
    {
        const int c0 = wid * 4;
        float v2r[8][4];
        #pragma unroll
        for (int r = 0; r < 8; r++) {
            int h = (r < 4) ? (4 * lane + r) : (128 + 4 * lane + (r - 4));
            #pragma unroll
            for (int cc = 0; cc < 4; cc++)
                v2r[r][cc] = s->v2s[c0 + cc][h];
        }
        float yp[NS][4];
        #pragma unroll
        for (int i = 0; i < NS; i++) {
            float4 wa = s->w3f4[i][lane];
            float4 wb = s->w3f4[i][32 + lane];
            float w3r[8] = {wa.x, wa.y, wa.z, wa.w, wb.x, wb.y, wb.z, wb.w};
            float a0 = 0.f, a1 = 0.f, a2 = 0.f, a3 = 0.f;
            #pragma unroll
            for (int r = 0; r < 8; r++) {
                a0 = fmaf(w3r[r], v2r[r][0], a0);
                a1 = fmaf(w3r[r], v2r[r][1], a1);
                a2 = fmaf(w3r[r], v2r[r][2], a2);
                a3 = fmaf(w3r[r], v2r[r][3], a3);
            }
            yp[i][0] = a0; yp[i][1] = a1; yp[i][2] = a2; yp[i][3] = a3;
        }
        #pragma unroll
        for (int i = 0; i < NS; i++)
            #pragma unroll
            for (int cc = 0; cc < 4; cc++) {
                float v = yp[i][cc];
                #pragma unroll
                for (int o = 16; o > 0; o >>= 1)
                    v += __shfl_xor_sync(0xffffffffu, v, o);
                yp[i][cc] = v;
            }
        if (lane == 0) {
            #pragma unroll
            for (int i = 0; i < NS; i++) {
                float b3v = b3[i];
                #pragma unroll
                for (int cc = 0; cc < 4; cc++)
                    out[(size_t)(n0 + c0 + cc) * NS + i] = yp[i][cc] + b3v;
            }
        }
    }
}

// ======================= kernel B: mma.sync Jacobian (unchanged math) =======
struct SmemJ2 {
    u32 W[2][2][128][40];
    u64 w1p[4][256];
    u32 w3p[2][6][132];
    u32 m2[CPB][8];
};

__global__ void __launch_bounds__(384, 1)
k_jacM(const float* __restrict__ w1, const float* __restrict__ w3,
       float* __restrict__ out, int ncell)
{
    extern __shared__ char raw[];
    SmemJ2* s = reinterpret_cast<SmemJ2*>(raw);
    const u32 sWb = smem_u32(&s->W[0][0][0][0]);

    const int tid  = threadIdx.x;
    const int lane = tid & 31;
    const int wid  = tid >> 5;
    const int g    = lane >> 2;
    const int tg   = lane & 3;
    const int n0   = blockIdx.x * CPB;

    const int r1 = wid * 16 + g, r2 = r1 + 8;
    const int cellA = r1 / 6, iiA = r1 - 6 * cellA;
    const int cellB = r2 / 6, iiB = r2 - 6 * cellB;

    auto copyW = [&](int np, int kc, int b) {
        for (int i = tid; i < 2048; i += 384) {
            int sp = i >> 10;
            int rem = i & 1023;
            int nl = rem >> 3, q = rem & 7;
            const void* src = (const void*)(g_wB +
                ((size_t)(sp * 256 + np * 128 + nl) * 128 + kc * 32 + q * 4));
            u32 dst = sWb + (u32)((((b * 2 + sp) * 128 + nl) * 40 + q * 4) * 4);
            cp16(dst, src);
        }
        CP_COMMIT();
    };

    if (tid < 256) {
        int j = tid;
        const float* wr = w1 + (size_t)j * 8;
        float4 a = *reinterpret_cast<const float4*>(wr);
        float4 b = *reinterpret_cast<const float4*>(wr + 4);
        s->w1p[0][j] = pk2(a.x, a.y);
        s->w1p[1][j] = pk2(a.z, a.w);
        s->w1p[2][j] = pk2(b.x, b.y);
        s->w1p[3][j] = pk2(b.z, b.w);
    }
    for (int idx = tid; idx < 2 * 6 * 128; idx += 384) {
        int sp = idx / 768;
        int r = idx - sp * 768;
        int ii = r >> 7, p = r & 127;
        float va = w3[ii * H + 2 * p], vb = w3[ii * H + 2 * p + 1];
        s->w3p[sp][ii][p] = (u32)bfs(va, sp) | ((u32)bfs(vb, sp) << 16);
    }
    if (tid < CPB) {
        const uint4* mp = (const uint4*)(g_m2w + (size_t)(n0 + tid) * 8);
        uint4 a = mp[0], b = mp[1];
        s->m2[tid][0] = a.x; s->m2[tid][1] = a.y;
        s->m2[tid][2] = a.z; s->m2[tid][3] = a.w;
        s->m2[tid][4] = b.x; s->m2[tid][5] = b.y;
        s->m2[tid][6] = b.z; s->m2[tid][7] = b.w;
    }
    copyW(0, 0, 0);

    u32 mA[8], mB[8];
    {
        const uint4* pa = (const uint4*)(g_m1w + (size_t)(n0 + cellA) * 8);
        uint4 x = pa[0], z = pa[1];
        mA[0] = x.x; mA[1] = x.y; mA[2] = x.z; mA[3] = x.w;
        mA[4] = z.x; mA[5] = z.y; mA[6] = z.z; mA[7] = z.w;
        const uint4* pb = (const uint4*)(g_m1w + (size_t)(n0 + cellB) * 8);
        uint4 x2 = pb[0], z2 = pb[1];
        mB[0] = x2.x; mB[1] = x2.y; mB[2] = x2.z; mB[3] = x2.w;
        mB[4] = z2.x; mB[5] = z2.y; mB[6] = z2.z; mB[7] = z2.w;
    }

    u64 JA2[4] = {0ull, 0ull, 0ull, 0ull};
    u64 JB2[4] = {0ull, 0ull, 0ull, 0ull};

    #pragma unroll 1
    for (int np = 0; np < 2; np++) {
        float d[16][4];
        #pragma unroll
        for (int t = 0; t < 16; t++)
            #pragma unroll
            for (int c = 0; c < 4; c++) d[t][c] = 0.0f;

        #pragma unroll 1
        for (int kc = 0; kc < 4; kc++) {
            const int idx = np * 4 + kc;
            const int buf = idx & 1;
            CP_WAIT0();
            __syncthreads();
            if (idx < 7) {
                int nidx = idx + 1;
                copyW(nidx >> 2, nidx & 3, nidx & 1);
            }

            #pragma unroll 1
            for (int kss = 0; kss < 4; kss++) {
                int ksg = kc * 4 + kss;
                int p0g = ksg * 8 + tg;
                u32 wmA = s->m2[cellA][ksg >> 1];
                u32 wmB = s->m2[cellB][ksg >> 1];
                int sh0 = ((ksg & 1) << 4) + tg * 2;
                u32 mkA0 = mask2((wmA >> sh0) & 3u);
                u32 mkB0 = mask2((wmB >> sh0) & 3u);
                u32 mkA1 = mask2((wmA >> (sh0 + 8)) & 3u);
                u32 mkB1 = mask2((wmB >> (sh0 + 8)) & 3u);

                u32 a0[4], a1[4];
                a0[0] = s->w3p[0][iiA][p0g]     & mkA0;
                a0[1] = s->w3p[0][iiB][p0g]     & mkB0;
                a0[2] = s->w3p[0][iiA][p0g + 4] & mkA1;
                a0[3] = s->w3p[0][iiB][p0g + 4] & mkB1;
                a1[0] = s->w3p[1][iiA][p0g]     & mkA0;
                a1[1] = s->w3p[1][iiB][p0g]     & mkB0;
                a1[2] = s->w3p[1][iiA][p0g + 4] & mkA1;
                a1[3] = s->w3p[1][iiB][p0g + 4] & mkB1;

                const int bcol = kss * 8 + 2 * tg;
                u64 Br[16];
                #pragma unroll
                for (int t = 0; t < 16; t++)
                    Br[t] = *reinterpret_cast<const u64*>(&s->W[buf][0][t * 8 + g][bcol]);
                #pragma unroll
                for (int t = 0; t < 16; t++)
                    mma16816(d[t], a0, (u32)Br[t], (u32)(Br[t] >> 32));
                #pragma unroll
                for (int t = 0; t < 16; t++)
                    mma16816(d[t], a1, (u32)Br[t], (u32)(Br[t] >> 32));
                #pragma unroll
                for (int t = 0; t < 16; t++)
                    Br[t] = *reinterpret_cast<const u64*>(&s->W[buf][1][t * 8 + g][bcol]);
                #pragma unroll
                for (int t = 0; t < 16; t++)
                    mma16816(d[t], a0, (u32)Br[t], (u32)(Br[t] >> 32));
            }
        }

        #pragma unroll
        for (int t = 0; t < 16; t++) {
            int widx = np * 4 + (t >> 2);
            int sh = ((t & 3) * 8) + tg * 2;
            u32 wa = mA[widx] >> sh;
            u32 wb = mB[widx] >> sh;
            int j0 = np * 128 + t * 8 + tg * 2;

            float vA0 = (wa & 1u) ? d[t][0] : 0.0f;
            float vA1 = (wa & 2u) ? d[t][1] : 0.0f;
            float vB0 = (wb & 1u) ? d[t][2] : 0.0f;
            float vB1 = (wb & 2u) ? d[t][3] : 0.0f;
            u64 pA0 = pk2(vA0, vA0), pA1 = pk2(vA1, vA1);
            u64 pB0 = pk2(vB0, vB0), pB1 = pk2(vB1, vB1);
            #pragma unroll
            for (int q2 = 0; q2 < 4; q2++) {
                u64 wp0 = s->w1p[q2][j0];
                u64 wp1 = s->w1p[q2][j0 + 1];
                fma2(JA2[q2], pA0, wp0);
                fma2(JA2[q2], pA1, wp1);
                fma2(JB2[q2], pB0, wp0);
                fma2(JB2[q2], pB1, wp1);
            }
        }
    }

    float JA[8], JB[8];
    #pragma unroll
    for (int q2 = 0; q2 < 4; q2++) {
        upk2(JA2[q2], JA[2 * q2], JA[2 * q2 + 1]);
        upk2(JB2[q2], JB[2 * q2], JB[2 * q2 + 1]);
    }
    #pragma unroll
    for (int o = 1; o <= 2; o <<= 1) {
        #pragma unroll
        for (int q = 0; q < 8; q++) {
            JA[q] += __shfl_xor_sync(0xffffffffu, JA[q], o);
            JB[q] += __shfl_xor_sync(0xffffffffu, JB[q], o);
        }
    }
    if (tg == 0) {
        const size_t N = (size_t)ncell;
        float* outDY = out + 6 * N;
        float* outDE = out + 42 * N;
        float* outDT = out + 48 * N;
        int nA = n0 + cellA, nB = n0 + cellB;
        #pragma unroll
        for (int q = 0; q < 6; q++) {
            outDY[(size_t)nA * 36 + iiA * 6 + q] = JA[q];
            outDY[(size_t)nB * 36 + iiB * 6 + q] = JB[q];
        }
        outDE[(size_t)nA * 6 + iiA] = JA[6];
        outDT[(size_t)nA * 6 + iiA] = JA[7];
        outDE[(size_t)nB * 6 + iiB] = JB[6];
        outDT[(size_t)nB * 6 + iiB] = JB[7];
    }
}

extern "C" void kernel_launch(void* const* d_in, const int* in_sizes, int n_in,
                              void* d_out, int out_size) {
    // metadata order: t, y, erate, T, w1, w2, w3, b1, b2, b3
    const float* y  = (const float*)d_in[1];
    const float* er = (const float*)d_in[2];
    const float* Tg = (const float*)d_in[3];
    const float* w1 = (const float*)d_in[4];
    const float* w2 = (const float*)d_in[5];
    const float* w3 = (const float*)d_in[6];
    const float* b1 = (const float*)d_in[7];
    const float* b2 = (const float*)d_in[8];
    const float* b3 = (const float*)d_in[9];
    float* out = (float*)d_out;
    int ncell = in_sizes[2];             // NT*NB = 65536

    cudaFuncSetAttribute(k_fwdM, cudaFuncAttributeMaxDynamicSharedMemorySize,
                         (int)sizeof(SmemF));
    cudaFuncSetAttribute(k_jacM, cudaFuncAttributeMaxDynamicSharedMemorySize,
                         (int)sizeof(SmemJ2));

    k_prepW<<<64, 256>>>(w2);
    k_prepA<<<64, 256>>>(w2);
    k_fwdM<<<ncell / G, 256, sizeof(SmemF)>>>(y, er, Tg, w1, w2, w3,
                                              b1, b2, b3, out, ncell);
    k_jacM<<<ncell / CPB, 384, sizeof(SmemJ2)>>>(w1, w3, out, ncell);
}

// round 16
// speedup vs baseline: 2.1576x; 1.0132x over previous
#include <cuda_runtime.h>
#include <cuda_bf16.h>
#include <cstdint>

#define H        256
#define NS       6
#define G        32      // cells per forward block
#define CPBJ     64      // cells per jacobian CTA (M = 384 rows dense)
#define TAU      1e-3f

typedef unsigned long long u64;
typedef unsigned int u32;

// ---------------- device scratch (allocations are forbidden) ----------------
__device__ u32 g_wB[2 * 256 * 128];  // jac B: bf16 pairs [split][n][pos] (pair-permuted)
__device__ u32 g_wA[65536];          // fwd A: w2 bf16 pairs [sp][grp][pos][row]
__device__ u32 g_m2w[65536 * 8];     // m2 words per cell: bit b of word g <-> h=32g+b
__device__ u32 g_m1w[65536 * 8];     // m1 ballot words per cell

// ---------------- helpers ----------------
__device__ __forceinline__ u64 pk2(float lo, float hi) {
    u64 r; asm("mov.b64 %0, {%1, %2};" : "=l"(r) : "f"(lo), "f"(hi)); return r;
}
__device__ __forceinline__ void upk2(u64 v, float& lo, float& hi) {
    asm("mov.b64 {%0, %1}, %2;" : "=f"(lo), "=f"(hi) : "l"(v));
}
__device__ __forceinline__ void fma2(u64& d, u64 a, u64 b) {
    asm("fma.rn.f32x2 %0, %1, %2, %0;" : "+l"(d) : "l"(a), "l"(b));
}
__device__ __forceinline__ unsigned short bfs(float v, int s) {
    __nv_bfloat16 h0 = __float2bfloat16(v);
    if (s == 0) return __bfloat16_as_ushort(h0);
    float r = v - __bfloat162float(h0);
    return __bfloat16_as_ushort(__float2bfloat16(r));
}
__device__ __forceinline__ void mma16816(float* d, const u32* a, u32 b0, u32 b1) {
    asm volatile(
        "mma.sync.aligned.m16n8k16.row.col.f32.bf16.bf16.f32 "
        "{%0,%1,%2,%3}, {%4,%5,%6,%7}, {%8,%9}, {%0,%1,%2,%3};"
        : "+f"(d[0]), "+f"(d[1]), "+f"(d[2]), "+f"(d[3])
        : "r"(a[0]), "r"(a[1]), "r"(a[2]), "r"(a[3]), "r"(b0), "r"(b1));
}
__device__ __forceinline__ u32 mask2(u32 bits) {
    return ((bits & 1u) ? 0x0000FFFFu : 0u) | ((bits & 2u) ? 0xFFFF0000u : 0u);
}
__device__ __forceinline__ u32 smem_u32(const void* p) {
    u32 a;
    asm("{ .reg .u64 t; cvta.to.shared.u64 t, %1; cvt.u32.u64 %0, t; }"
        : "=r"(a) : "l"(p));
    return a;
}
__device__ __forceinline__ void cp16(u32 dst, const void* src) {
    asm volatile("cp.async.cg.shared.global [%0], [%1], 16;"
                 :: "r"(dst), "l"(src) : "memory");
}
#define CP_COMMIT() asm volatile("cp.async.commit_group;" ::: "memory")
#define CP_WAIT0()  asm volatile("cp.async.wait_group 0;" ::: "memory")

// ======================= prep B (jac W tiles) ==============================
// g_wB[(s*256+n)*128 + pos]; u64 at pos 2w yields pairs (kp=w, kp=w+4).
__global__ void k_prepW(const float* __restrict__ w2) {
    int base = blockIdx.x * 1024 + threadIdx.x * 4;
    #pragma unroll
    for (int e4 = 0; e4 < 4; e4++) {
        int idx = base + e4;
        int s = idx >> 15;
        int rem = idx & 32767;
        int n = rem >> 7, pos = rem & 127;
        int group = pos >> 3, within = pos & 7;
        int w8 = (within >> 1) + 4 * (within & 1);
        int kp = group * 8 + w8;
        float va = w2[(size_t)(2 * kp) * H + n];
        float vb = w2[(size_t)(2 * kp + 1) * H + n];
        g_wB[idx] = (u32)bfs(va, s) | ((u32)bfs(vb, s) << 16);
    }
}

// ======================= prep A (fwd w2 row-major pairs) ===================
__global__ void k_prepA(const float* __restrict__ w2) {
    int base = blockIdx.x * 1024 + threadIdx.x * 4;
    #pragma unroll
    for (int e4 = 0; e4 < 4; e4++) {
        int idx = base + e4;
        int row = idx & 7;
        int pos = (idx >> 3) & 127;
        int grp = (idx >> 10) & 31;
        int sp  = idx >> 15;
        int h = grp * 8 + row;
        int within = pos & 7;
        int w8 = (within >> 1) + 4 * (within & 1);
        int kp = (pos >> 3) * 8 + w8;
        float va = w2[(size_t)h * H + 2 * kp];
        float vb = w2[(size_t)h * H + 2 * kp + 1];
        g_wA[idx] = (u32)bfs(va, sp) | ((u32)bfs(vb, sp) << 16);
    }
}

// ======================= kernel A: tensor-core forward (R15, passing) =======
struct SmemF {
    u32    Abuf[2][2][32][16][8];
    float  v1f[H][33];
    u32    v1p[2][G][136];
    float  v2s[G][260];
    float4 w3f4[NS][64];
    unsigned char m2s[G][H];
    float  xs[G][8];
    float  b2s[H];
    int    cnt;
    u32    flags[256];
};

__global__ void __launch_bounds__(256, 1)
k_fwdM(const float* __restrict__ y,  const float* __restrict__ er,
       const float* __restrict__ Tg, const float* __restrict__ w1,
       const float* __restrict__ w2, const float* __restrict__ w3,
       const float* __restrict__ b1, const float* __restrict__ b2,
       const float* __restrict__ b3, float* __restrict__ out, int ncell)
{
    extern __shared__ char raw[];
    SmemF* s = reinterpret_cast<SmemF*>(raw);
    const u32 sAb = smem_u32(&s->Abuf[0][0][0][0][0]);

    const int tid  = threadIdx.x;
    const int lane = tid & 31;
    const int wid  = tid >> 5;
    const int g    = lane >> 2;
    const int tg   = lane & 3;
    const int n0   = blockIdx.x * G;

    auto copyA = [&](int kc, int b) {
        for (int i = tid; i < 2048; i += 256) {
            int seg  = i & 1;
            int posL = (i >> 1) & 15;
            int grp  = (i >> 5) & 31;
            int sp   = i >> 10;
            const void* src = (const void*)(g_wA +
                ((size_t)((sp * 32 + grp) * 128 + kc * 16 + posL)) * 8 + seg * 4);
            u32 dst = sAb + (u32)((((((b * 2 + sp) * 32 + grp) * 16 + posL) * 8)
                                   + seg * 4) * 4);
            cp16(dst, src);
        }
        CP_COMMIT();
    };

    copyA(0, 0);

    float w1r[8];
    #pragma unroll
    for (int q = 0; q < 8; q++) w1r[q] = w1[tid * 8 + q];
    #pragma unroll
    for (int idx = tid; idx < NS * 64; idx += 256) {
        int i = idx >> 6, l = idx & 63;
        s->w3f4[i][l] = *reinterpret_cast<const float4*>(&w3[i * H + 4 * l]);
    }
    s->b2s[tid] = b2[tid];
    {
        int c = tid >> 3, q = tid & 7, n = n0 + c;
        float xv = (q < 6) ? y[n * 6 + q] : (q == 6 ? er[n] : Tg[n]);
        s->xs[c][q] = xv;
    }
    if (tid == 0) s->cnt = 0;
    __syncthreads();

    {
        float b1v = b1[tid];
        #pragma unroll 4
        for (int c = 0; c < G; c++) {
            float z = b1v;
            #pragma unroll
            for (int q = 0; q < 8; q++) z = fmaf(w1r[q], s->xs[c][q], z);
            s->v1f[tid][c] = fmaxf(z, 0.0f);
            unsigned bal = __ballot_sync(0xffffffffu, z > 0.0f);
            if (lane == 0) g_m1w[(size_t)(n0 + c) * 8 + wid] = bal;
        }
    }
    __syncthreads();

    #pragma unroll
    for (int it = 0; it < 32; it++) {
        int idx = tid + 256 * it;
        int sp = idx >> 12;
        int rem = idx & 4095;
        int c = rem >> 7, pos = rem & 127;
        int within = pos & 7;
        int w8 = (within >> 1) + 4 * (within & 1);
        int kp = (pos >> 3) * 8 + w8;
        float va = s->v1f[2 * kp][c];
        float vb = s->v1f[2 * kp + 1][c];
        s->v1p[sp][c][pos] = (u32)bfs(va, sp) | ((u32)bfs(vb, sp) << 16);
    }

    float d[2][4][4];
    #pragma unroll
    for (int m = 0; m < 2; m++)
        #pragma unroll
        for (int nt = 0; nt < 4; nt++)
            #pragma unroll
            for (int e = 0; e < 4; e++) d[m][nt][e] = 0.0f;

    const int gA = wid * 2;
    const int gB = gA + 16;

    #pragma unroll 1
    for (int kc = 0; kc < 8; kc++) {
        CP_WAIT0();
        __syncthreads();
        if (kc < 7) copyA(kc + 1, (kc + 1) & 1);
        const int buf = kc & 1;

        #pragma unroll
        for (int ks = 0; ks < 2; ks++) {
            const int kssG = kc * 2 + ks;
            const int p0 = ks * 8 + 2 * tg, p1 = p0 + 1;

            u32 aA0[4], aA1[4], aB0[4], aB1[4];
            aA0[0] = s->Abuf[buf][0][gA][p0][g];
            aA0[1] = s->Abuf[buf][0][gA + 1][p0][g];
            aA0[2] = s->Abuf[buf][0][gA][p1][g];
            aA0[3] = s->Abuf[buf][0][gA + 1][p1][g];
            aA1[0] = s->Abuf[buf][1][gA][p0][g];
            aA1[1] = s->Abuf[buf][1][gA + 1][p0][g];
            aA1[2] = s->Abuf[buf][1][gA][p1][g];
            aA1[3] = s->Abuf[buf][1][gA + 1][p1][g];
            aB0[0] = s->Abuf[buf][0][gB][p0][g];
            aB0[1] = s->Abuf[buf][0][gB + 1][p0][g];
            aB0[2] = s->Abuf[buf][0][gB][p1][g];
            aB0[3] = s->Abuf[buf][0][gB + 1][p1][g];
            aB1[0] = s->Abuf[buf][1][gB][p0][g];
            aB1[1] = s->Abuf[buf][1][gB + 1][p0][g];
            aB1[2] = s->Abuf[buf][1][gB][p1][g];
            aB1[3] = s->Abuf[buf][1][gB + 1][p1][g];

            u64 B0[4], B1[4];
            #pragma unroll
            for (int nt = 0; nt < 4; nt++) {
                B0[nt] = *reinterpret_cast<const u64*>(
                             &s->v1p[0][nt * 8 + g][kssG * 8 + 2 * tg]);
                B1[nt] = *reinterpret_cast<const u64*>(
                             &s->v1p[1][nt * 8 + g][kssG * 8 + 2 * tg]);
            }
            #pragma unroll
            for (int nt = 0; nt < 4; nt++) {
                mma16816(d[0][nt], aA0, (u32)B0[nt], (u32)(B0[nt] >> 32));
                mma16816(d[1][nt], aB0, (u32)B0[nt], (u32)(B0[nt] >> 32));
            }
            #pragma unroll
            for (int nt = 0; nt < 4; nt++) {
                mma16816(d[0][nt], aA1, (u32)B0[nt], (u32)(B0[nt] >> 32));
                mma16816(d[1][nt], aB1, (u32)B0[nt], (u32)(B0[nt] >> 32));
            }
            #pragma unroll
            for (int nt = 0; nt < 4; nt++) {
                mma16816(d[0][nt], aA0, (u32)B1[nt], (u32)(B1[nt] >> 32));
                mma16816(d[1][nt], aB0, (u32)B1[nt], (u32)(B1[nt] >> 32));
            }
        }
    }
    __syncthreads();

    #pragma unroll
    for (int m = 0; m < 2; m++) {
        int hb = ((m == 0) ? wid : wid + 8) * 16;
        #pragma unroll
        for (int nt = 0; nt < 4; nt++) {
            int cbase = nt * 8 + 2 * tg;
            #pragma unroll
            for (int e = 0; e < 4; e++) {
                int h = hb + g + ((e >= 2) ? 8 : 0);
                int c = cbase + (e & 1);
                float z = d[m][nt][e] + s->b2s[h];
                s->m2s[c][h] = (z > 0.0f) ? 1 : 0;
                s->v2s[c][h] = fmaxf(z, 0.0f);
                if (fabsf(z) < TAU) {
                    int fi = atomicAdd(&s->cnt, 1);
                    if (fi < 256) s->flags[fi] = ((u32)c << 16) | (u32)h;
                }
            }
        }
    }
    __syncthreads();

    {
        int nfix = s->cnt;
        if (nfix > 256) nfix = 256;
        for (int fi = wid; fi < nfix; fi += 8) {
            u32 f = s->flags[fi];
            int c = (int)(f >> 16), h = (int)(f & 0xFFFFu);
            const float* wr = w2 + (size_t)h * H + lane * 8;
            float4 wa = *reinterpret_cast<const float4*>(wr);
            float4 wb = *reinterpret_cast<const float4*>(wr + 4);
            float wv[8] = {wa.x, wa.y, wa.z, wa.w, wb.x, wb.y, wb.z, wb.w};
            float acc = 0.0f;
            #pragma unroll
            for (int e = 0; e < 8; e++)
                acc = fmaf(wv[e], s->v1f[lane * 8 + e][c], acc);
            #pragma unroll
            for (int o = 16; o > 0; o >>= 1)
                acc += __shfl_xor_sync(0xffffffffu, acc, o);
            if (lane == 0) {
                float z = acc + s->b2s[h];
                s->m2s[c][h] = (z > 0.0f) ? 1 : 0;
                s->v2s[c][h] = fmaxf(z, 0.0f);
            }
        }
    }
    __syncthreads();

    {
        int c = tid >> 3, gw = tid & 7;
        u32 wm = 0;
        #pragma unroll
        for (int q = 0; q < 8; q++) {
            u32 x = *reinterpret_cast<const u32*>(&s->m2s[c][gw * 32 + q * 4]);
            wm |= (((x & 0x01010101u) * 0x01020408u) >> 24 & 0xFu) << (q * 4);
        }
        g_m2w[(size_t)(n0 + c) * 8 + gw] = wm;
    }

    {
        const int c0 = wid * 4;
        float v2r[8][4];
        #pragma unroll
        for (int r = 0; r < 8; r++) {
            int h = (r < 4) ? (4 * lane + r) : (128 + 4 * lane + (r - 4));
            #pragma unroll
            for (int cc = 0; cc < 4; cc++)
                v2r[r][cc] = s->v2s[c0 + cc][h];
        }
        float yp[NS][4];
        #pragma unroll
        for (int i = 0; i < NS; i++) {
            float4 wa = s->w3f4[i][lane];
            float4 wb = s->w3f4[i][32 + lane];
            float w3r[8] = {wa.x, wa.y, wa.z, wa.w, wb.x, wb.y, wb.z, wb.w};
            float a0 = 0.f, a1 = 0.f, a2 = 0.f, a3 = 0.f;
            #pragma unroll
            for (int r = 0; r < 8; r++) {
                a0 = fmaf(w3r[r], v2r[r][0], a0);
                a1 = fmaf(w3r[r], v2r[r][1], a1);
                a2 = fmaf(w3r[r], v2r[r][2], a2);
                a3 = fmaf(w3r[r], v2r[r][3], a3);
            }
            yp[i][0] = a0; yp[i][1] = a1; yp[i][2] = a2; yp[i][3] = a3;
        }
        #pragma unroll
        for (int i = 0; i < NS; i++)
            #pragma unroll
            for (int cc = 0; cc < 4; cc++) {
                float v = yp[i][cc];
                #pragma unroll
                for (int o = 16; o > 0; o >>= 1)
                    v += __shfl_xor_sync(0xffffffffu, v, o);
                yp[i][cc] = v;
            }
        if (lane == 0) {
            #pragma unroll
            for (int i = 0; i < NS; i++) {
                float b3v = b3[i];
                #pragma unroll
                for (int cc = 0; cc < 4; cc++)
                    out[(size_t)(n0 + c0 + cc) * NS + i] = yp[i][cc] + b3v;
            }
        }
    }
}

// ======================= kernel B: jac, 64 cells, 2 M-tiles/warp ============
// M = 384 rows (24 M-tiles; warp owns mt pairs (wid, wid+12)); N in 4 quarters
// of 64. W chunk layout XOR-swizzled: word (nl, pos) at [nl][pos^((nl&3)<<3)].
struct SmemJ3 {
    u32 W[2][2][64][32];   // [buf][sp][nl][pos-swizzled]   32 KB
    u64 w1p[4][256];       // 8 KB
    u32 w3p[2][6][132];    // ~6.2 KB
    u32 m2s[CPBJ][8];      // 2 KB
    u32 m1s[CPBJ][8];      // 2 KB
};

__global__ void __launch_bounds__(384, 1)
k_jacM(const float* __restrict__ w1, const float* __restrict__ w3,
       float* __restrict__ out, int ncell)
{
    extern __shared__ char raw[];
    SmemJ3* s = reinterpret_cast<SmemJ3*>(raw);
    const u32 sWb = smem_u32(&s->W[0][0][0][0]);

    const int tid  = threadIdx.x;
    const int lane = tid & 31;
    const int wid  = tid >> 5;      // 0..11
    const int g    = lane >> 2;     // 0..7
    const int tg   = lane & 3;
    const int n0   = blockIdx.x * CPBJ;

    int cellA[2], iiA[2], cellB[2], iiB[2];
    #pragma unroll
    for (int mt = 0; mt < 2; mt++) {
        int r1 = (wid + 12 * mt) * 16 + g, r2 = r1 + 8;
        cellA[mt] = r1 / 6; iiA[mt] = r1 - 6 * cellA[mt];
        cellB[mt] = r2 / 6; iiB[mt] = r2 - 6 * cellB[mt];
    }

    // copy chunk (np quarter, kc) into buffer b
    auto copyW = [&](int np, int kc, int b) {
        for (int i = tid; i < 1024; i += 384) {
            int sp = i >> 9;
            int rem = i & 511;
            int nl = rem >> 3, q = rem & 7;
            const void* src = (const void*)(g_wB +
                ((size_t)(sp * 256 + np * 64 + nl) * 128 + kc * 32 + q * 4));
            int colb = (q * 4) ^ ((nl & 3) << 3);
            u32 dst = sWb + (u32)(((((b * 2 + sp) * 64 + nl) * 32) + colb) * 4);
            cp16(dst, src);
        }
        CP_COMMIT();
    };

    // ---------------- stage tables ----------------
    if (tid < 256) {
        int j = tid;
        const float* wr = w1 + (size_t)j * 8;
        float4 a = *reinterpret_cast<const float4*>(wr);
        float4 b = *reinterpret_cast<const float4*>(wr + 4);
        s->w1p[0][j] = pk2(a.x, a.y);
        s->w1p[1][j] = pk2(a.z, a.w);
        s->w1p[2][j] = pk2(b.x, b.y);
        s->w1p[3][j] = pk2(b.z, b.w);
    }
    for (int idx = tid; idx < 2 * 6 * 128; idx += 384) {
        int sp = idx / 768;
        int r = idx - sp * 768;
        int ii = r >> 7, p = r & 127;
        float va = w3[ii * H + 2 * p], vb = w3[ii * H + 2 * p + 1];
        s->w3p[sp][ii][p] = (u32)bfs(va, sp) | ((u32)bfs(vb, sp) << 16);
    }
    if (tid < CPBJ) {
        const uint4* mp = (const uint4*)(g_m2w + (size_t)(n0 + tid) * 8);
        uint4 a = mp[0], b = mp[1];
        s->m2s[tid][0] = a.x; s->m2s[tid][1] = a.y;
        s->m2s[tid][2] = a.z; s->m2s[tid][3] = a.w;
        s->m2s[tid][4] = b.x; s->m2s[tid][5] = b.y;
        s->m2s[tid][6] = b.z; s->m2s[tid][7] = b.w;
        const uint4* mq = (const uint4*)(g_m1w + (size_t)(n0 + tid) * 8);
        uint4 c = mq[0], e = mq[1];
        s->m1s[tid][0] = c.x; s->m1s[tid][1] = c.y;
        s->m1s[tid][2] = c.z; s->m1s[tid][3] = c.w;
        s->m1s[tid][4] = e.x; s->m1s[tid][5] = e.y;
        s->m1s[tid][6] = e.z; s->m1s[tid][7] = e.w;
    }
    copyW(0, 0, 0);

    u64 JA2[2][4], JB2[2][4];
    #pragma unroll
    for (int mt = 0; mt < 2; mt++)
        #pragma unroll
        for (int q2 = 0; q2 < 4; q2++) { JA2[mt][q2] = 0ull; JB2[mt][q2] = 0ull; }

    #pragma unroll 1
    for (int np = 0; np < 4; np++) {
        float d[2][8][4];
        #pragma unroll
        for (int mt = 0; mt < 2; mt++)
            #pragma unroll
            for (int t = 0; t < 8; t++)
                #pragma unroll
                for (int c = 0; c < 4; c++) d[mt][t][c] = 0.0f;

        #pragma unroll 1
        for (int kc = 0; kc < 4; kc++) {
            const int idx = np * 4 + kc;
            const int buf = idx & 1;
            CP_WAIT0();
            __syncthreads();
            if (idx < 15) {
                int nidx = idx + 1;
                copyW(nidx >> 2, nidx & 3, nidx & 1);
            }

            #pragma unroll 1
            for (int kss = 0; kss < 4; kss++) {
                int ksg = kc * 4 + kss;
                int p0g = ksg * 8 + tg;
                int sh0 = ((ksg & 1) << 4) + tg * 2;

                u32 a0[2][4], a1[2][4];
                #pragma unroll
                for (int mt = 0; mt < 2; mt++) {
                    u32 wmA = s->m2s[cellA[mt]][ksg >> 1];
                    u32 wmB = s->m2s[cellB[mt]][ksg >> 1];
                    u32 mkA0 = mask2((wmA >> sh0) & 3u);
                    u32 mkB0 = mask2((wmB >> sh0) & 3u);
                    u32 mkA1 = mask2((wmA >> (sh0 + 8)) & 3u);
                    u32 mkB1 = mask2((wmB >> (sh0 + 8)) & 3u);
                    a0[mt][0] = s->w3p[0][iiA[mt]][p0g]     & mkA0;
                    a0[mt][1] = s->w3p[0][iiB[mt]][p0g]     & mkB0;
                    a0[mt][2] = s->w3p[0][iiA[mt]][p0g + 4] & mkA1;
                    a0[mt][3] = s->w3p[0][iiB[mt]][p0g + 4] & mkB1;
                    a1[mt][0] = s->w3p[1][iiA[mt]][p0g]     & mkA0;
                    a1[mt][1] = s->w3p[1][iiB[mt]][p0g]     & mkB0;
                    a1[mt][2] = s->w3p[1][iiA[mt]][p0g + 4] & mkA1;
                    a1[mt][3] = s->w3p[1][iiB[mt]][p0g + 4] & mkB1;
                }

                const int col = (kss * 8 + 2 * tg) ^ ((g & 3) << 3);
                u64 Br[8];
                // split 0
                #pragma unroll
                for (int t = 0; t < 8; t++)
                    Br[t] = *reinterpret_cast<const u64*>(
                                &s->W[buf][0][t * 8 + g][col]);
                #pragma unroll
                for (int t = 0; t < 8; t++) {
                    mma16816(d[0][t], a0[0], (u32)Br[t], (u32)(Br[t] >> 32));
                    mma16816(d[1][t], a0[1], (u32)Br[t], (u32)(Br[t] >> 32));
                }
                #pragma unroll
                for (int t = 0; t < 8; t++) {
                    mma16816(d[0][t], a1[0], (u32)Br[t], (u32)(Br[t] >> 32));
                    mma16816(d[1][t], a1[1], (u32)Br[t], (u32)(Br[t] >> 32));
                }
                // split 1
                #pragma unroll
                for (int t = 0; t < 8; t++)
                    Br[t] = *reinterpret_cast<const u64*>(
                                &s->W[buf][1][t * 8 + g][col]);
                #pragma unroll
                for (int t = 0; t < 8; t++) {
                    mma16816(d[0][t], a0[0], (u32)Br[t], (u32)(Br[t] >> 32));
                    mma16816(d[1][t], a0[1], (u32)Br[t], (u32)(Br[t] >> 32));
                }
            }
        }

        // ---------------- fold quarter np into J ----------------
        #pragma unroll
        for (int mt = 0; mt < 2; mt++)
            #pragma unroll
            for (int t = 0; t < 8; t++) {
                int j0 = np * 64 + t * 8 + tg * 2;
                int widx = j0 >> 5, sh = j0 & 31;
                u32 wa = s->m1s[cellA[mt]][widx] >> sh;
                u32 wb = s->m1s[cellB[mt]][widx] >> sh;
                float vA0 = (wa & 1u) ? d[mt][t][0] : 0.0f;
                float vA1 = (wa & 2u) ? d[mt][t][1] : 0.0f;
                float vB0 = (wb & 1u) ? d[mt][t][2] : 0.0f;
                float vB1 = (wb & 2u) ? d[mt][t][3] : 0.0f;
                u64 pA0 = pk2(vA0, vA0), pA1 = pk2(vA1, vA1);
                u64 pB0 = pk2(vB0, vB0), pB1 = pk2(vB1, vB1);
                #pragma unroll
                for (int q2 = 0; q2 < 4; q2++) {
                    u64 wp0 = s->w1p[q2][j0];
                    u64 wp1 = s->w1p[q2][j0 + 1];
                    fma2(JA2[mt][q2], pA0, wp0);
                    fma2(JA2[mt][q2], pA1, wp1);
                    fma2(JB2[mt][q2], pB0, wp0);
                    fma2(JB2[mt][q2], pB1, wp1);
                }
            }
    }

    // ---------------- reduce across tg lanes and store ----------------
    const size_t N = (size_t)ncell;
    float* outDY = out + 6 * N;
    float* outDE = out + 42 * N;
    float* outDT = out + 48 * N;

    #pragma unroll
    for (int mt = 0; mt < 2; mt++) {
        float JA[8], JB[8];
        #pragma unroll
        for (int q2 = 0; q2 < 4; q2++) {
            upk2(JA2[mt][q2], JA[2 * q2], JA[2 * q2 + 1]);
            upk2(JB2[mt][q2], JB[2 * q2], JB[2 * q2 + 1]);
        }
        #pragma unroll
        for (int o = 1; o <= 2; o <<= 1) {
            #pragma unroll
            for (int q = 0; q < 8; q++) {
                JA[q] += __shfl_xor_sync(0xffffffffu, JA[q], o);
                JB[q] += __shfl_xor_sync(0xffffffffu, JB[q], o);
            }
        }
        if (tg == 0) {
            int nA = n0 + cellA[mt], nB = n0 + cellB[mt];
            #pragma unroll
            for (int q = 0; q < 6; q++) {
                outDY[(size_t)nA * 36 + iiA[mt] * 6 + q] = JA[q];
                outDY[(size_t)nB * 36 + iiB[mt] * 6 + q] = JB[q];
            }
            outDE[(size_t)nA * 6 + iiA[mt]] = JA[6];
            outDT[(size_t)nA * 6 + iiA[mt]] = JA[7];
            outDE[(size_t)nB * 6 + iiB[mt]] = JB[6];
            outDT[(size_t)nB * 6 + iiB[mt]] = JB[7];
        }
    }
}

extern "C" void kernel_launch(void* const* d_in, const int* in_sizes, int n_in,
                              void* d_out, int out_size) {
    // metadata order: t, y, erate, T, w1, w2, w3, b1, b2, b3
    const float* y  = (const float*)d_in[1];
    const float* er = (const float*)d_in[2];
    const float* Tg = (const float*)d_in[3];
    const float* w1 = (const float*)d_in[4];
    const float* w2 = (const float*)d_in[5];
    const float* w3 = (const float*)d_in[6];
    const float* b1 = (const float*)d_in[7];
    const float* b2 = (const float*)d_in[8];
    const float* b3 = (const float*)d_in[9];
    float* out = (float*)d_out;
    int ncell = in_sizes[2];             // NT*NB = 65536

    cudaFuncSetAttribute(k_fwdM, cudaFuncAttributeMaxDynamicSharedMemorySize,
                         (int)sizeof(SmemF));
    cudaFuncSetAttribute(k_jacM, cudaFuncAttributeMaxDynamicSharedMemorySize,
                         (int)sizeof(SmemJ3));

    k_prepW<<<64, 256>>>(w2);
    k_prepA<<<64, 256>>>(w2);
    k_fwdM<<<ncell / G, 256, sizeof(SmemF)>>>(y, er, Tg, w1, w2, w3,
                                              b1, b2, b3, out, ncell);
    k_jacM<<<ncell / CPBJ, 384, sizeof(SmemJ3)>>>(w1, w3, out, ncell);
}